// round 1
// baseline (speedup 1.0000x reference)
#include <cuda_runtime.h>
#include <cuda_bf16.h>
#include <math.h>

#define BB 2
#define SS 2048
#define DMODEL 4096
#define NH 32
#define NKV 8
#define HD 128
#define MROWS (BB*SS)   // 4096

// Scratch (device globals — no allocation allowed)
__device__ float g_q[(size_t)MROWS * NH * HD];     // 64 MB
__device__ float g_k[(size_t)MROWS * NKV * HD];    // 16 MB
__device__ float g_v[(size_t)MROWS * NKV * HD];    // 16 MB
__device__ float g_attn[(size_t)MROWS * NH * HD];  // 64 MB
__device__ float g_cos[MROWS * (HD/2)];
__device__ float g_sin[MROWS * (HD/2)];

// ---------------------------------------------------------------------------
// SGEMM (NT): C[M,N] = A[M,K] @ W[N,K]^T, all row-major, K contiguous.
// 128x128 tile, BK=16, 256 threads, 8x8 register microtile.
// M,N multiples of 128; K multiple of 16.
// ---------------------------------------------------------------------------
__global__ __launch_bounds__(256) void sgemm_nt(const float* __restrict__ A,
                                                const float* __restrict__ W,
                                                float* __restrict__ C,
                                                int M, int N, int K) {
    __shared__ float As[16][128];
    __shared__ float Bs[16][128];
    int t = threadIdx.x;
    int bm = blockIdx.y * 128;
    int bn = blockIdx.x * 128;
    int tr = (t >> 4) * 8;
    int tc = (t & 15) * 8;

    float acc[8][8];
#pragma unroll
    for (int i = 0; i < 8; i++)
#pragma unroll
        for (int j = 0; j < 8; j++) acc[i][j] = 0.f;

    for (int k0 = 0; k0 < K; k0 += 16) {
#pragma unroll
        for (int i = 0; i < 2; i++) {
            int idx = t + i * 256;          // 0..511
            int row = idx >> 2;             // 0..127
            int k4  = (idx & 3) * 4;        // 0,4,8,12
            float4 av = *(const float4*)(A + (size_t)(bm + row) * K + k0 + k4);
            As[k4+0][row] = av.x; As[k4+1][row] = av.y;
            As[k4+2][row] = av.z; As[k4+3][row] = av.w;
            float4 bv = *(const float4*)(W + (size_t)(bn + row) * K + k0 + k4);
            Bs[k4+0][row] = bv.x; Bs[k4+1][row] = bv.y;
            Bs[k4+2][row] = bv.z; Bs[k4+3][row] = bv.w;
        }
        __syncthreads();
#pragma unroll
        for (int kk = 0; kk < 16; kk++) {
            float a[8], b[8];
            *(float4*)&a[0] = *(const float4*)&As[kk][tr];
            *(float4*)&a[4] = *(const float4*)&As[kk][tr + 4];
            *(float4*)&b[0] = *(const float4*)&Bs[kk][tc];
            *(float4*)&b[4] = *(const float4*)&Bs[kk][tc + 4];
#pragma unroll
            for (int i = 0; i < 8; i++)
#pragma unroll
                for (int j = 0; j < 8; j++)
                    acc[i][j] += a[i] * b[j];
        }
        __syncthreads();
    }

#pragma unroll
    for (int i = 0; i < 8; i++) {
        float4 v0 = make_float4(acc[i][0], acc[i][1], acc[i][2], acc[i][3]);
        float4 v1 = make_float4(acc[i][4], acc[i][5], acc[i][6], acc[i][7]);
        float* cp = C + (size_t)(bm + tr + i) * N + bn + tc;
        *(float4*)cp       = v0;
        *(float4*)(cp + 4) = v1;
    }
}

// ---------------------------------------------------------------------------
// RoPE table: cos/sin per (row, freq-index), fp64 internally for accuracy.
// ---------------------------------------------------------------------------
__global__ void rope_table(const int* __restrict__ pos) {
    int idx = blockIdx.x * blockDim.x + threadIdx.x;
    if (idx >= MROWS * 64) return;
    int i   = idx & 63;
    int row = idx >> 6;
    double inv = exp(-(double)(2 * i) / 128.0 * log(10000.0));
    double ang = (double)pos[row] * inv;
    g_cos[idx] = (float)cos(ang);
    g_sin[idx] = (float)sin(ang);
}

// ---------------------------------------------------------------------------
// Apply RoPE in-place to q (32 heads) and k (8 heads).
// ---------------------------------------------------------------------------
__global__ void rope_apply() {
    int idx = blockIdx.x * blockDim.x + threadIdx.x;
    const int total = MROWS * (NH + NKV) * 64;
    if (idx >= total) return;
    int i    = idx & 63;
    int head = (idx >> 6) % (NH + NKV);
    int row  = idx / (64 * (NH + NKV));
    float c = g_cos[row * 64 + i];
    float s = g_sin[row * 64 + i];
    float* base = (head < NH)
        ? (g_q + (size_t)row * NH * HD + head * HD)
        : (g_k + (size_t)row * NKV * HD + (head - NH) * HD);
    float x1 = base[i];
    float x2 = base[i + 64];
    base[i]      = x1 * c - x2 * s;
    base[i + 64] = x2 * c + x1 * s;
}

// ---------------------------------------------------------------------------
// Flash attention, fp32, causal, GQA (4 q-heads per kv-head).
// Block: 256 threads = 8 warps; Br=64 q rows, Bc=64 k cols, D=128.
// Lane layout: lane = r_local*4 + dgrp; warp owns 8 rows; lane owns
// dims [dgrp*32, dgrp*32+32) of its row. Q frag (scaled) lives in registers.
// ---------------------------------------------------------------------------
__global__ __launch_bounds__(256) void flash_kernel(const float* __restrict__ q,
                                                    const float* __restrict__ k,
                                                    const float* __restrict__ v,
                                                    float* __restrict__ o) {
    extern __shared__ float sm[];
    float* Ks = sm;                 // 64*128
    float* Vs = sm + 64 * 128;      // 64*128
    float* Sc = sm + 2 * 64 * 128;  // 64*65 (padded stride)

    int qt = blockIdx.x;   // q tile (0..31)
    int h  = blockIdx.y;   // head
    int b  = blockIdx.z;   // batch
    int kvh = h >> 2;      // NH/NKV = 4

    int t    = threadIdx.x;
    int warp = t >> 5;
    int lane = t & 31;
    int rl   = lane >> 2;
    int dg   = lane & 3;
    int row  = warp * 8 + rl;   // 0..63
    int qg   = qt * 64 + row;   // global q position

    const float scale = 0.08838834764831845f;  // 1/sqrt(128)

    // Q fragment: 32 dims, pre-scaled
    float qf[32];
    {
        const float* qp = q + ((size_t)(b * SS + qg)) * (NH * HD) + h * HD + dg * 32;
#pragma unroll
        for (int i = 0; i < 8; i++) {
            float4 t4 = *(const float4*)(qp + i * 4);
            qf[4*i+0] = t4.x * scale; qf[4*i+1] = t4.y * scale;
            qf[4*i+2] = t4.z * scale; qf[4*i+3] = t4.w * scale;
        }
    }

    float acc[32];
#pragma unroll
    for (int i = 0; i < 32; i++) acc[i] = 0.f;
    float m = -1e30f, l = 0.f;

    for (int kt = 0; kt <= qt; kt++) {
        // cooperative load of K,V tiles (coalesced, float4)
#pragma unroll
        for (int i = 0; i < 8; i++) {
            int idx = i * 256 + t;          // 0..2047
            int r   = idx >> 5;             // 0..63
            int c4  = (idx & 31) * 4;       // 0..124
            size_t g = ((size_t)(b * SS + kt * 64 + r)) * (NKV * HD) + kvh * HD + c4;
            *(float4*)&Ks[r * 128 + c4] = *(const float4*)(k + g);
            *(float4*)&Vs[r * 128 + c4] = *(const float4*)(v + g);
        }
        __syncthreads();

        // Pass 1: scores + row max
        float rowmax = -1e30f;
#pragma unroll 4
        for (int c = 0; c < 64; c++) {
            const float4* kp = (const float4*)&Ks[c * 128 + dg * 32];
            float part = 0.f;
#pragma unroll
            for (int i = 0; i < 8; i++) {
                float4 kv4 = kp[i];
                part += qf[4*i+0]*kv4.x + qf[4*i+1]*kv4.y
                      + qf[4*i+2]*kv4.z + qf[4*i+3]*kv4.w;
            }
            part += __shfl_xor_sync(0xffffffffu, part, 1);
            part += __shfl_xor_sync(0xffffffffu, part, 2);
            float sc = ((kt * 64 + c) <= qg) ? part : -1e30f;
            if (dg == 0) Sc[row * 65 + c] = sc;
            rowmax = fmaxf(rowmax, sc);
        }
        __syncwarp();

        float mn = fmaxf(m, rowmax);
        float alpha = __expf(m - mn);
        l *= alpha;
#pragma unroll
        for (int i = 0; i < 32; i++) acc[i] *= alpha;

        // Pass 2: P = exp(S - m), l += P, acc += P @ V
#pragma unroll 2
        for (int c = 0; c < 64; c++) {
            float p = __expf(Sc[row * 65 + c] - mn);
            l += p;
            const float4* vp = (const float4*)&Vs[c * 128 + dg * 32];
#pragma unroll
            for (int i = 0; i < 8; i++) {
                float4 vv = vp[i];
                acc[4*i+0] += p * vv.x; acc[4*i+1] += p * vv.y;
                acc[4*i+2] += p * vv.z; acc[4*i+3] += p * vv.w;
            }
        }
        m = mn;
        __syncthreads();
    }

    float inv_l = 1.f / l;
    float* op = o + ((size_t)(b * SS + qg)) * (NH * HD) + h * HD + dg * 32;
#pragma unroll
    for (int i = 0; i < 8; i++) {
        float4 ov = make_float4(acc[4*i+0]*inv_l, acc[4*i+1]*inv_l,
                                acc[4*i+2]*inv_l, acc[4*i+3]*inv_l);
        *(float4*)(op + 4 * i) = ov;
    }
}

// ---------------------------------------------------------------------------
extern "C" void kernel_launch(void* const* d_in, const int* in_sizes, int n_in,
                              void* d_out, int out_size) {
    const float* hid = (const float*)d_in[0];
    const int*   pos = (const int*)d_in[1];
    const float* Wq  = (const float*)d_in[2];
    const float* Wk  = (const float*)d_in[3];
    const float* Wv  = (const float*)d_in[4];
    const float* Wo  = (const float*)d_in[5];
    float* out = (float*)d_out;

    float *pq, *pk, *pv, *pattn;
    cudaGetSymbolAddress((void**)&pq,    g_q);
    cudaGetSymbolAddress((void**)&pk,    g_k);
    cudaGetSymbolAddress((void**)&pv,    g_v);
    cudaGetSymbolAddress((void**)&pattn, g_attn);

    // QKV projections
    sgemm_nt<<<dim3(NH*HD/128,  MROWS/128), 256>>>(hid, Wq, pq, MROWS, NH*HD,  DMODEL);
    sgemm_nt<<<dim3(NKV*HD/128, MROWS/128), 256>>>(hid, Wk, pk, MROWS, NKV*HD, DMODEL);
    sgemm_nt<<<dim3(NKV*HD/128, MROWS/128), 256>>>(hid, Wv, pv, MROWS, NKV*HD, DMODEL);

    // RoPE
    rope_table<<<(MROWS*64 + 255)/256, 256>>>(pos);
    rope_apply<<<(MROWS*(NH+NKV)*64 + 255)/256, 256>>>();

    // Attention
    int smem = (2 * 64 * 128 + 64 * 65) * (int)sizeof(float);  // 82176 B
    cudaFuncSetAttribute(flash_kernel, cudaFuncAttributeMaxDynamicSharedMemorySize, smem);
    flash_kernel<<<dim3(SS/64, NH, BB), 256, smem>>>(pq, pk, pv, pattn);

    // Output projection
    sgemm_nt<<<dim3(NH*HD/128, MROWS/128), 256>>>(pattn, Wo, out, MROWS, NH*HD, NH*HD);
}

// round 4
// speedup vs baseline: 1.2122x; 1.2122x over previous
#include <cuda_runtime.h>
#include <cuda_bf16.h>
#include <math.h>
#include <stdint.h>

#define BB 2
#define SS 2048
#define DMODEL 4096
#define NH 32
#define NKV 8
#define HD 128
#define MROWS (BB*SS)   // 4096

// ---------------- scratch (device globals; no allocation allowed) ----------
__device__ float g_q[(size_t)MROWS * NH * HD];
__device__ float g_k[(size_t)MROWS * NKV * HD];
__device__ float g_v[(size_t)MROWS * NKV * HD];
__device__ float g_attn[(size_t)MROWS * NH * HD];
__device__ float g_cos[MROWS * (HD/2)];
__device__ float g_sin[MROWS * (HD/2)];

// bf16 hi/lo decompositions
__device__ __nv_bfloat16 g_hid_h[(size_t)MROWS * DMODEL];
__device__ __nv_bfloat16 g_hid_l[(size_t)MROWS * DMODEL];
__device__ __nv_bfloat16 g_wq_h[(size_t)NH*HD * DMODEL];
__device__ __nv_bfloat16 g_wq_l[(size_t)NH*HD * DMODEL];
__device__ __nv_bfloat16 g_wk_h[(size_t)NKV*HD * DMODEL];
__device__ __nv_bfloat16 g_wk_l[(size_t)NKV*HD * DMODEL];
__device__ __nv_bfloat16 g_wv_h[(size_t)NKV*HD * DMODEL];
__device__ __nv_bfloat16 g_wv_l[(size_t)NKV*HD * DMODEL];
__device__ __nv_bfloat16 g_wo_h[(size_t)NH*HD * NH*HD];
__device__ __nv_bfloat16 g_wo_l[(size_t)NH*HD * NH*HD];
__device__ __nv_bfloat16 g_at_h[(size_t)MROWS * NH*HD];
__device__ __nv_bfloat16 g_at_l[(size_t)MROWS * NH*HD];

// ---------------- PTX helpers (sm_80+ base-target safe) ---------------------
__device__ __forceinline__ uint32_t smem_u32(const void* p) {
    uint32_t a;
    asm("{ .reg .u64 t; cvta.to.shared.u64 t, %1; cvt.u32.u64 %0, t; }" : "=r"(a) : "l"(p));
    return a;
}
__device__ __forceinline__ void cp16(uint32_t dst, const void* src) {
    asm volatile("cp.async.cg.shared.global [%0], [%1], 16;\n" :: "r"(dst), "l"(src));
}
__device__ __forceinline__ void cp_commit() { asm volatile("cp.async.commit_group;\n" ::: "memory"); }

__device__ __forceinline__ void ldm_x4(uint32_t* r, uint32_t addr) {
    asm volatile("ldmatrix.sync.aligned.m8n8.x4.shared.b16 {%0,%1,%2,%3}, [%4];"
        : "=r"(r[0]), "=r"(r[1]), "=r"(r[2]), "=r"(r[3]) : "r"(addr));
}
__device__ __forceinline__ void ldm_x2(uint32_t* r, uint32_t addr) {
    asm volatile("ldmatrix.sync.aligned.m8n8.x2.shared.b16 {%0,%1}, [%2];"
        : "=r"(r[0]), "=r"(r[1]) : "r"(addr));
}
__device__ __forceinline__ void mma16816(float* d, const uint32_t* a, const uint32_t* b) {
    asm volatile("mma.sync.aligned.m16n8k16.row.col.f32.bf16.bf16.f32 "
        "{%0,%1,%2,%3}, {%4,%5,%6,%7}, {%8,%9}, {%0,%1,%2,%3};"
        : "+f"(d[0]), "+f"(d[1]), "+f"(d[2]), "+f"(d[3])
        : "r"(a[0]), "r"(a[1]), "r"(a[2]), "r"(a[3]), "r"(b[0]), "r"(b[1]));
}

// ---------------- fp32 -> bf16 hi/lo decomposition --------------------------
__global__ void decompose(const float* __restrict__ s,
                          __nv_bfloat16* __restrict__ h,
                          __nv_bfloat16* __restrict__ l, int n) {
    int i = blockIdx.x * blockDim.x + threadIdx.x;
    if (i >= n) return;
    float f = s[i];
    __nv_bfloat16 hh = __float2bfloat16(f);
    h[i] = hh;
    l[i] = __float2bfloat16(f - __bfloat162float(hh));
}

// ---------------------------------------------------------------------------
// HMMA bf16-split GEMM (NT): C[M,N] = A[M,K] @ W[N,K]^T, fp32 result.
// C ≈ Ah·Bh + Ah·Bl + Al·Bh (fp32 accumulate).
// CTA 128x128, BK=32, 256 thr (8 warps in 2x4 grid, warp tile 64x32),
// double-buffered cp.async, ldmatrix from padded smem (stride 40 bf16).
// ---------------------------------------------------------------------------
#define SA   40                 // smem row stride in bf16 elements (80 B)
#define MAT  (128*SA)           // elements per matrix per stage
#define GSTAGE (4*MAT)          // Ah,Al,Bh,Bl
#define GK_SMEM (2*GSTAGE*2)    // bytes (2 stages, bf16)

__global__ __launch_bounds__(256, 1)
void gemm_mma(const __nv_bfloat16* __restrict__ Ah, const __nv_bfloat16* __restrict__ Al,
              const __nv_bfloat16* __restrict__ Bh, const __nv_bfloat16* __restrict__ Bl,
              float* __restrict__ C, int M, int N, int K) {
    extern __shared__ __nv_bfloat16 smbuf[];
    int t = threadIdx.x;
    int wid = t >> 5, lane = t & 31;
    int bm = blockIdx.y * 128, bn = blockIdx.x * 128;
    int wm = (wid >> 2) * 64;   // 0 or 64
    int wn = (wid & 3) * 32;    // 0,32,64,96

    float acc[4][4][4];
#pragma unroll
    for (int a = 0; a < 4; a++)
#pragma unroll
        for (int b = 0; b < 4; b++)
#pragma unroll
            for (int c = 0; c < 4; c++) acc[a][b][c] = 0.f;

    auto load_stage = [&](int s, int k0) {
        __nv_bfloat16* st = smbuf + s * GSTAGE;
        const __nv_bfloat16* srcs[4] = { Ah + k0, Al + k0, Bh + k0, Bl + k0 };
        const int r0s[4] = { bm, bm, bn, bn };
#pragma unroll
        for (int mtx = 0; mtx < 4; mtx++) {
            const __nv_bfloat16* g = srcs[mtx];
            int r0 = r0s[mtx];
#pragma unroll
            for (int i = 0; i < 2; i++) {
                int idx = i * 256 + t;          // 0..511
                int r = idx >> 2;               // 0..127
                int c = (idx & 3) * 8;          // bf16 elements: 0,8,16,24
                cp16(smem_u32(st + mtx * MAT + r * SA + c),
                     g + (size_t)(r0 + r) * K + c);
            }
        }
        cp_commit();
    };

    const int NCH = K >> 5;      // K/32
    load_stage(0, 0);

    for (int ch = 0; ch < NCH; ch++) {
        if (ch + 1 < NCH) {
            load_stage((ch + 1) & 1, (ch + 1) << 5);
            asm volatile("cp.async.wait_group 1;\n" ::: "memory");
        } else {
            asm volatile("cp.async.wait_group 0;\n" ::: "memory");
        }
        __syncthreads();

        __nv_bfloat16* st = smbuf + (ch & 1) * GSTAGE;
        uint32_t oAh = smem_u32(st);
        uint32_t oAl = smem_u32(st + MAT);
        uint32_t oBh = smem_u32(st + 2 * MAT);
        uint32_t oBl = smem_u32(st + 3 * MAT);

#pragma unroll
        for (int kk = 0; kk < 2; kk++) {
            int koff = kk * 16;
            uint32_t ah[4][4], al[4][4], bh[4][2], bl[4][2];
#pragma unroll
            for (int mi = 0; mi < 4; mi++) {
                uint32_t ra = ((wm + mi * 16 + (lane & 15)) * SA + koff + ((lane >> 4) << 3)) * 2;
                ldm_x4(ah[mi], oAh + ra);
                ldm_x4(al[mi], oAl + ra);
            }
#pragma unroll
            for (int ni = 0; ni < 4; ni++) {
                uint32_t rb = ((wn + ni * 8 + (lane & 7)) * SA + koff + (((lane >> 3) & 1) << 3)) * 2;
                ldm_x2(bh[ni], oBh + rb);
                ldm_x2(bl[ni], oBl + rb);
            }
#pragma unroll
            for (int mi = 0; mi < 4; mi++)
#pragma unroll
                for (int ni = 0; ni < 4; ni++) {
                    mma16816(acc[mi][ni], ah[mi], bh[ni]);
                    mma16816(acc[mi][ni], ah[mi], bl[ni]);
                    mma16816(acc[mi][ni], al[mi], bh[ni]);
                }
        }
        __syncthreads();
    }

    // epilogue: c0,c1 -> (row, col), c2,c3 -> (row+8, col)
    int row = lane >> 2;
    int col = (lane & 3) * 2;
#pragma unroll
    for (int mi = 0; mi < 4; mi++)
#pragma unroll
        for (int ni = 0; ni < 4; ni++) {
            float* c0 = C + (size_t)(bm + wm + mi * 16 + row) * N + bn + wn + ni * 8 + col;
            c0[0] = acc[mi][ni][0];
            c0[1] = acc[mi][ni][1];
            float* c1 = c0 + 8 * (size_t)N;
            c1[0] = acc[mi][ni][2];
            c1[1] = acc[mi][ni][3];
        }
}

// ---------------- RoPE -------------------------------------------------------
__global__ void rope_table(const int* __restrict__ pos) {
    int idx = blockIdx.x * blockDim.x + threadIdx.x;
    if (idx >= MROWS * 64) return;
    int i   = idx & 63;
    int row = idx >> 6;
    double inv = exp(-(double)(2 * i) / 128.0 * log(10000.0));
    double ang = (double)pos[row] * inv;
    g_cos[idx] = (float)cos(ang);
    g_sin[idx] = (float)sin(ang);
}
__global__ void rope_apply() {
    int idx = blockIdx.x * blockDim.x + threadIdx.x;
    const int total = MROWS * (NH + NKV) * 64;
    if (idx >= total) return;
    int i    = idx & 63;
    int head = (idx >> 6) % (NH + NKV);
    int row  = idx / (64 * (NH + NKV));
    float c = g_cos[row * 64 + i];
    float s = g_sin[row * 64 + i];
    float* base = (head < NH)
        ? (g_q + (size_t)row * NH * HD + head * HD)
        : (g_k + (size_t)row * NKV * HD + (head - NH) * HD);
    float x1 = base[i];
    float x2 = base[i + 64];
    base[i]      = x1 * c - x2 * s;
    base[i + 64] = x2 * c + x1 * s;
}

// ---------------- flash attention (fp32, causal, GQA) -----------------------
__global__ __launch_bounds__(256) void flash_kernel(const float* __restrict__ q,
                                                    const float* __restrict__ k,
                                                    const float* __restrict__ v,
                                                    float* __restrict__ o) {
    extern __shared__ float sm[];
    float* Ks = sm;
    float* Vs = sm + 64 * 128;
    float* Sc = sm + 2 * 64 * 128;

    int qt = blockIdx.x;
    int h  = blockIdx.y;
    int b  = blockIdx.z;
    int kvh = h >> 2;

    int t    = threadIdx.x;
    int warp = t >> 5;
    int lane = t & 31;
    int rl   = lane >> 2;
    int dg   = lane & 3;
    int row  = warp * 8 + rl;
    int qg   = qt * 64 + row;

    const float scale = 0.08838834764831845f;

    float qf[32];
    {
        const float* qp = q + ((size_t)(b * SS + qg)) * (NH * HD) + h * HD + dg * 32;
#pragma unroll
        for (int i = 0; i < 8; i++) {
            float4 t4 = *(const float4*)(qp + i * 4);
            qf[4*i+0] = t4.x * scale; qf[4*i+1] = t4.y * scale;
            qf[4*i+2] = t4.z * scale; qf[4*i+3] = t4.w * scale;
        }
    }

    float acc[32];
#pragma unroll
    for (int i = 0; i < 32; i++) acc[i] = 0.f;
    float m = -1e30f, l = 0.f;

    for (int kt = 0; kt <= qt; kt++) {
#pragma unroll
        for (int i = 0; i < 8; i++) {
            int idx = i * 256 + t;
            int r   = idx >> 5;
            int c4  = (idx & 31) * 4;
            size_t g = ((size_t)(b * SS + kt * 64 + r)) * (NKV * HD) + kvh * HD + c4;
            *(float4*)&Ks[r * 128 + c4] = *(const float4*)(k + g);
            *(float4*)&Vs[r * 128 + c4] = *(const float4*)(v + g);
        }
        __syncthreads();

        float rowmax = -1e30f;
#pragma unroll 4
        for (int c = 0; c < 64; c++) {
            const float4* kp = (const float4*)&Ks[c * 128 + dg * 32];
            float part = 0.f;
#pragma unroll
            for (int i = 0; i < 8; i++) {
                float4 kv4 = kp[i];
                part += qf[4*i+0]*kv4.x + qf[4*i+1]*kv4.y
                      + qf[4*i+2]*kv4.z + qf[4*i+3]*kv4.w;
            }
            part += __shfl_xor_sync(0xffffffffu, part, 1);
            part += __shfl_xor_sync(0xffffffffu, part, 2);
            float sc = ((kt * 64 + c) <= qg) ? part : -1e30f;
            if (dg == 0) Sc[row * 65 + c] = sc;
            rowmax = fmaxf(rowmax, sc);
        }
        __syncwarp();

        float mn = fmaxf(m, rowmax);
        float alpha = __expf(m - mn);
        l *= alpha;
#pragma unroll
        for (int i = 0; i < 32; i++) acc[i] *= alpha;

#pragma unroll 2
        for (int c = 0; c < 64; c++) {
            float p = __expf(Sc[row * 65 + c] - mn);
            l += p;
            const float4* vp = (const float4*)&Vs[c * 128 + dg * 32];
#pragma unroll
            for (int i = 0; i < 8; i++) {
                float4 vv = vp[i];
                acc[4*i+0] += p * vv.x; acc[4*i+1] += p * vv.y;
                acc[4*i+2] += p * vv.z; acc[4*i+3] += p * vv.w;
            }
        }
        m = mn;
        __syncthreads();
    }

    float inv_l = 1.f / l;
    float* op = o + ((size_t)(b * SS + qg)) * (NH * HD) + h * HD + dg * 32;
#pragma unroll
    for (int i = 0; i < 8; i++) {
        float4 ov = make_float4(acc[4*i+0]*inv_l, acc[4*i+1]*inv_l,
                                acc[4*i+2]*inv_l, acc[4*i+3]*inv_l);
        *(float4*)(op + 4 * i) = ov;
    }
}

// ---------------------------------------------------------------------------
extern "C" void kernel_launch(void* const* d_in, const int* in_sizes, int n_in,
                              void* d_out, int out_size) {
    const float* hid = (const float*)d_in[0];
    const int*   pos = (const int*)d_in[1];
    const float* Wq  = (const float*)d_in[2];
    const float* Wk  = (const float*)d_in[3];
    const float* Wv  = (const float*)d_in[4];
    const float* Wo  = (const float*)d_in[5];
    float* out = (float*)d_out;

    float *pq, *pk, *pv, *pattn;
    cudaGetSymbolAddress((void**)&pq,    g_q);
    cudaGetSymbolAddress((void**)&pk,    g_k);
    cudaGetSymbolAddress((void**)&pv,    g_v);
    cudaGetSymbolAddress((void**)&pattn, g_attn);
    __nv_bfloat16 *hh, *hl, *qh, *ql, *kh, *kl, *vh, *vl, *oh, *ol, *ah, *al;
    cudaGetSymbolAddress((void**)&hh, g_hid_h); cudaGetSymbolAddress((void**)&hl, g_hid_l);
    cudaGetSymbolAddress((void**)&qh, g_wq_h);  cudaGetSymbolAddress((void**)&ql, g_wq_l);
    cudaGetSymbolAddress((void**)&kh, g_wk_h);  cudaGetSymbolAddress((void**)&kl, g_wk_l);
    cudaGetSymbolAddress((void**)&vh, g_wv_h);  cudaGetSymbolAddress((void**)&vl, g_wv_l);
    cudaGetSymbolAddress((void**)&oh, g_wo_h);  cudaGetSymbolAddress((void**)&ol, g_wo_l);
    cudaGetSymbolAddress((void**)&ah, g_at_h);  cudaGetSymbolAddress((void**)&al, g_at_l);

    const int nHid = MROWS * DMODEL;
    const int nWq  = NH * HD * DMODEL;
    const int nWk  = NKV * HD * DMODEL;
    decompose<<<(nHid + 255) / 256, 256>>>(hid, hh, hl, nHid);
    decompose<<<(nWq  + 255) / 256, 256>>>(Wq,  qh, ql, nWq);
    decompose<<<(nWk  + 255) / 256, 256>>>(Wk,  kh, kl, nWk);
    decompose<<<(nWk  + 255) / 256, 256>>>(Wv,  vh, vl, nWk);
    decompose<<<(nWq  + 255) / 256, 256>>>(Wo,  oh, ol, nWq);

    cudaFuncSetAttribute(gemm_mma, cudaFuncAttributeMaxDynamicSharedMemorySize, GK_SMEM);

    gemm_mma<<<dim3(NH*HD/128,  MROWS/128), 256, GK_SMEM>>>(hh, hl, qh, ql, pq, MROWS, NH*HD,  DMODEL);
    gemm_mma<<<dim3(NKV*HD/128, MROWS/128), 256, GK_SMEM>>>(hh, hl, kh, kl, pk, MROWS, NKV*HD, DMODEL);
    gemm_mma<<<dim3(NKV*HD/128, MROWS/128), 256, GK_SMEM>>>(hh, hl, vh, vl, pv, MROWS, NKV*HD, DMODEL);

    rope_table<<<(MROWS*64 + 255)/256, 256>>>(pos);
    rope_apply<<<(MROWS*(NH+NKV)*64 + 255)/256, 256>>>();

    int smem = (2 * 64 * 128 + 64 * 65) * (int)sizeof(float);
    cudaFuncSetAttribute(flash_kernel, cudaFuncAttributeMaxDynamicSharedMemorySize, smem);
    flash_kernel<<<dim3(SS/64, NH, BB), 256, smem>>>(pq, pk, pv, pattn);

    const int nAt = MROWS * NH * HD;
    decompose<<<(nAt + 255) / 256, 256>>>(pattn, ah, al, nAt);
    gemm_mma<<<dim3(NH*HD/128, MROWS/128), 256, GK_SMEM>>>(ah, al, oh, ol, out, MROWS, NH*HD, NH*HD);
}

// round 5
// speedup vs baseline: 1.2256x; 1.0111x over previous
#include <cuda_runtime.h>
#include <cuda_bf16.h>
#include <math.h>
#include <stdint.h>

#define BB 2
#define SS 2048
#define DMODEL 4096
#define NH 32
#define NKV 8
#define HD 128
#define MROWS (BB*SS)   // 4096

// ---------------- scratch (device globals; no allocation allowed) ----------
__device__ float g_q[(size_t)MROWS * NH * HD];
__device__ float g_k[(size_t)MROWS * NKV * HD];
__device__ float g_v[(size_t)MROWS * NKV * HD];
__device__ float g_attn[(size_t)MROWS * NH * HD];
__device__ float g_cos[MROWS * (HD/2)];
__device__ float g_sin[MROWS * (HD/2)];

// bf16 hi/lo decompositions
__device__ __nv_bfloat16 g_hid_h[(size_t)MROWS * DMODEL];
__device__ __nv_bfloat16 g_hid_l[(size_t)MROWS * DMODEL];
__device__ __nv_bfloat16 g_wq_h[(size_t)NH*HD * DMODEL];
__device__ __nv_bfloat16 g_wq_l[(size_t)NH*HD * DMODEL];
__device__ __nv_bfloat16 g_wk_h[(size_t)NKV*HD * DMODEL];
__device__ __nv_bfloat16 g_wk_l[(size_t)NKV*HD * DMODEL];
__device__ __nv_bfloat16 g_wv_h[(size_t)NKV*HD * DMODEL];
__device__ __nv_bfloat16 g_wv_l[(size_t)NKV*HD * DMODEL];
__device__ __nv_bfloat16 g_wo_h[(size_t)NH*HD * NH*HD];
__device__ __nv_bfloat16 g_wo_l[(size_t)NH*HD * NH*HD];
__device__ __nv_bfloat16 g_at_h[(size_t)MROWS * NH*HD];
__device__ __nv_bfloat16 g_at_l[(size_t)MROWS * NH*HD];

// ---------------- PTX helpers (sm_80+ base-target safe) ---------------------
__device__ __forceinline__ uint32_t smem_u32(const void* p) {
    uint32_t a;
    asm("{ .reg .u64 t; cvta.to.shared.u64 t, %1; cvt.u32.u64 %0, t; }" : "=r"(a) : "l"(p));
    return a;
}
__device__ __forceinline__ void cp16(uint32_t dst, const void* src) {
    asm volatile("cp.async.cg.shared.global [%0], [%1], 16;\n" :: "r"(dst), "l"(src));
}
__device__ __forceinline__ void cp_commit() { asm volatile("cp.async.commit_group;\n" ::: "memory"); }

__device__ __forceinline__ void ldm_x4(uint32_t* r, uint32_t addr) {
    asm volatile("ldmatrix.sync.aligned.m8n8.x4.shared.b16 {%0,%1,%2,%3}, [%4];"
        : "=r"(r[0]), "=r"(r[1]), "=r"(r[2]), "=r"(r[3]) : "r"(addr));
}
__device__ __forceinline__ void mma16816(float* d, const uint32_t* a, const uint32_t* b) {
    asm volatile("mma.sync.aligned.m16n8k16.row.col.f32.bf16.bf16.f32 "
        "{%0,%1,%2,%3}, {%4,%5,%6,%7}, {%8,%9}, {%0,%1,%2,%3};"
        : "+f"(d[0]), "+f"(d[1]), "+f"(d[2]), "+f"(d[3])
        : "r"(a[0]), "r"(a[1]), "r"(a[2]), "r"(a[3]), "r"(b[0]), "r"(b[1]));
}

// ---------------- fp32 -> bf16 hi/lo decomposition --------------------------
__global__ void decompose(const float* __restrict__ s,
                          __nv_bfloat16* __restrict__ h,
                          __nv_bfloat16* __restrict__ l, int n) {
    int i = blockIdx.x * blockDim.x + threadIdx.x;
    if (i >= n) return;
    float f = s[i];
    __nv_bfloat16 hh = __float2bfloat16(f);
    h[i] = hh;
    l[i] = __float2bfloat16(f - __bfloat162float(hh));
}

// ---------------------------------------------------------------------------
// HMMA bf16-split GEMM (NT): C[M,N] = A[M,K] @ W[N,K]^T, fp32 result.
// C ≈ Ah·Bh + Ah·Bl + Al·Bh. CTA 128x256, BK=32, 8 warps (2x4, warp tile
// 64x64). Smem rows pack hi|lo (64 bf16 = 128B) with XOR swizzle
// (chunk ^ (row&7)) — conflict-free fill + ldmatrix, and kk/lo address
// variants are single XORs. 3-stage cp.async pipeline.
// ---------------------------------------------------------------------------
#define BM 128
#define BN 256
#define STG_A (128*64)                 // elements
#define STG_B (256*64)
#define STG_ELE (STG_A + STG_B)        // 24576
#define STG_BYTES (STG_ELE*2)          // 49152
#define GK_SMEM (3*STG_BYTES + 128)    // 147584 B

__global__ __launch_bounds__(256, 1)
void gemm_mma(const __nv_bfloat16* __restrict__ Ah, const __nv_bfloat16* __restrict__ Al,
              const __nv_bfloat16* __restrict__ Bh, const __nv_bfloat16* __restrict__ Bl,
              float* __restrict__ C, int M, int N, int K) {
    extern __shared__ __nv_bfloat16 smraw[];
    uint32_t sm0 = (smem_u32(smraw) + 127) & ~127u;

    int t = threadIdx.x;
    int wid = t >> 5, lane = t & 31;
    int bm = blockIdx.y * BM, bn = blockIdx.x * BN;
    int wm = (wid >> 2) * 64;   // 0 or 64
    int wn = (wid & 3) * 64;    // 0,64,128,192

    float acc[4][8][4];
#pragma unroll
    for (int a = 0; a < 4; a++)
#pragma unroll
        for (int b = 0; b < 8; b++)
#pragma unroll
            for (int c = 0; c < 4; c++) acc[a][b][c] = 0.f;

    auto load_stage = [&](int s, int ck) {
        int k0 = ck * 32;
        uint32_t sb = sm0 + s * STG_BYTES;
#pragma unroll
        for (int i = 0; i < 4; i++) {           // A: 128 rows x 8 chunks
            int idx = i * 256 + t;
            int r = idx >> 3, c = idx & 7;
            const __nv_bfloat16* src = ((c < 4) ? Ah : Al)
                + (size_t)(bm + r) * K + k0 + (c & 3) * 8;
            cp16(sb + r * 128 + ((c ^ (r & 7)) * 16), src);
        }
        uint32_t sbB = sb + STG_A * 2;
#pragma unroll
        for (int i = 0; i < 8; i++) {           // B: 256 rows x 8 chunks
            int idx = i * 256 + t;
            int r = idx >> 3, c = idx & 7;
            const __nv_bfloat16* src = ((c < 4) ? Bh : Bl)
                + (size_t)(bn + r) * K + k0 + (c & 3) * 8;
            cp16(sbB + r * 128 + ((c ^ (r & 7)) * 16), src);
        }
        cp_commit();
    };

    const int NCH = K >> 5;
    load_stage(0, 0);
    load_stage(1, 1);

    // per-warp ldmatrix base addresses (stage 0 offset, kk=0, hi)
    int laneR = lane & 15, laneH = lane >> 4;
    uint32_t aBase[4], bBase[4];
#pragma unroll
    for (int mi = 0; mi < 4; mi++) {
        int r = wm + mi * 16 + laneR;
        aBase[mi] = sm0 + r * 128 + ((laneH ^ (r & 7)) * 16);
    }
#pragma unroll
    for (int nb = 0; nb < 4; nb++) {
        int r = wn + nb * 16 + laneR;
        bBase[nb] = sm0 + STG_A * 2 + r * 128 + ((laneH ^ (r & 7)) * 16);
    }

    for (int ch = 0; ch < NCH; ch++) {
        if (ch + 2 < NCH) {
            int s = (ch + 2) % 3;
            load_stage(s, ch + 2);
            asm volatile("cp.async.wait_group 2;\n" ::: "memory");
        } else if (ch + 1 < NCH) {
            asm volatile("cp.async.wait_group 1;\n" ::: "memory");
        } else {
            asm volatile("cp.async.wait_group 0;\n" ::: "memory");
        }
        __syncthreads();

        uint32_t soff = (uint32_t)(ch % 3) * STG_BYTES;
#pragma unroll
        for (int kk = 0; kk < 2; kk++) {
            uint32_t kx = kk * 32;     // chunk^2 == addr^32
            uint32_t ah[4][4], al[4][4];
#pragma unroll
            for (int mi = 0; mi < 4; mi++) {
                uint32_t a0 = (aBase[mi] + soff) ^ kx;
                ldm_x4(ah[mi], a0);
                ldm_x4(al[mi], a0 ^ 64);      // lo half: chunk^4
            }
#pragma unroll
            for (int half = 0; half < 2; half++) {
                uint32_t bh[2][4], bl[2][4];
#pragma unroll
                for (int j = 0; j < 2; j++) {
                    int nb = half * 2 + j;
                    uint32_t b0 = (bBase[nb] + soff) ^ kx;
                    ldm_x4(bh[j], b0);
                    ldm_x4(bl[j], b0 ^ 64);
                }
#pragma unroll
                for (int mi = 0; mi < 4; mi++)
#pragma unroll
                    for (int j = 0; j < 2; j++)
#pragma unroll
                        for (int sub = 0; sub < 2; sub++) {
                            int ni = half * 4 + j * 2 + sub;
                            uint32_t fh[2] = { bh[j][sub], bh[j][2 + sub] };
                            uint32_t fl[2] = { bl[j][sub], bl[j][2 + sub] };
                            mma16816(acc[mi][ni], ah[mi], fh);
                            mma16816(acc[mi][ni], ah[mi], fl);
                            mma16816(acc[mi][ni], al[mi], fh);
                        }
            }
        }
        __syncthreads();
    }

    // epilogue
    int row = lane >> 2;
    int col = (lane & 3) * 2;
#pragma unroll
    for (int mi = 0; mi < 4; mi++)
#pragma unroll
        for (int ni = 0; ni < 8; ni++) {
            float* c0 = C + (size_t)(bm + wm + mi * 16 + row) * N + bn + wn + ni * 8 + col;
            c0[0] = acc[mi][ni][0];
            c0[1] = acc[mi][ni][1];
            float* c1 = c0 + 8 * (size_t)N;
            c1[0] = acc[mi][ni][2];
            c1[1] = acc[mi][ni][3];
        }
}

// ---------------- RoPE -------------------------------------------------------
__global__ void rope_table(const int* __restrict__ pos) {
    int idx = blockIdx.x * blockDim.x + threadIdx.x;
    if (idx >= MROWS * 64) return;
    int i   = idx & 63;
    int row = idx >> 6;
    double inv = exp(-(double)(2 * i) / 128.0 * log(10000.0));
    double ang = (double)pos[row] * inv;
    g_cos[idx] = (float)cos(ang);
    g_sin[idx] = (float)sin(ang);
}
__global__ void rope_apply() {
    int idx = blockIdx.x * blockDim.x + threadIdx.x;
    const int total = MROWS * (NH + NKV) * 64;
    if (idx >= total) return;
    int i    = idx & 63;
    int head = (idx >> 6) % (NH + NKV);
    int row  = idx / (64 * (NH + NKV));
    float c = g_cos[row * 64 + i];
    float s = g_sin[row * 64 + i];
    float* base = (head < NH)
        ? (g_q + (size_t)row * NH * HD + head * HD)
        : (g_k + (size_t)row * NKV * HD + (head - NH) * HD);
    float x1 = base[i];
    float x2 = base[i + 64];
    base[i]      = x1 * c - x2 * s;
    base[i + 64] = x2 * c + x1 * s;
}

// ---------------- flash attention (fp32, causal, GQA) -----------------------
__global__ __launch_bounds__(256) void flash_kernel(const float* __restrict__ q,
                                                    const float* __restrict__ k,
                                                    const float* __restrict__ v,
                                                    float* __restrict__ o) {
    extern __shared__ float sm[];
    float* Ks = sm;
    float* Vs = sm + 64 * 128;
    float* Sc = sm + 2 * 64 * 128;

    int qt = blockIdx.x;
    int h  = blockIdx.y;
    int b  = blockIdx.z;
    int kvh = h >> 2;

    int t    = threadIdx.x;
    int warp = t >> 5;
    int lane = t & 31;
    int rl   = lane >> 2;
    int dg   = lane & 3;
    int row  = warp * 8 + rl;
    int qg   = qt * 64 + row;

    const float scale = 0.08838834764831845f;

    float qf[32];
    {
        const float* qp = q + ((size_t)(b * SS + qg)) * (NH * HD) + h * HD + dg * 32;
#pragma unroll
        for (int i = 0; i < 8; i++) {
            float4 t4 = *(const float4*)(qp + i * 4);
            qf[4*i+0] = t4.x * scale; qf[4*i+1] = t4.y * scale;
            qf[4*i+2] = t4.z * scale; qf[4*i+3] = t4.w * scale;
        }
    }

    float acc[32];
#pragma unroll
    for (int i = 0; i < 32; i++) acc[i] = 0.f;
    float m = -1e30f, l = 0.f;

    for (int kt = 0; kt <= qt; kt++) {
#pragma unroll
        for (int i = 0; i < 8; i++) {
            int idx = i * 256 + t;
            int r   = idx >> 5;
            int c4  = (idx & 31) * 4;
            size_t g = ((size_t)(b * SS + kt * 64 + r)) * (NKV * HD) + kvh * HD + c4;
            *(float4*)&Ks[r * 128 + c4] = *(const float4*)(k + g);
            *(float4*)&Vs[r * 128 + c4] = *(const float4*)(v + g);
        }
        __syncthreads();

        float rowmax = -1e30f;
#pragma unroll 4
        for (int c = 0; c < 64; c++) {
            const float4* kp = (const float4*)&Ks[c * 128 + dg * 32];
            float part = 0.f;
#pragma unroll
            for (int i = 0; i < 8; i++) {
                float4 kv4 = kp[i];
                part += qf[4*i+0]*kv4.x + qf[4*i+1]*kv4.y
                      + qf[4*i+2]*kv4.z + qf[4*i+3]*kv4.w;
            }
            part += __shfl_xor_sync(0xffffffffu, part, 1);
            part += __shfl_xor_sync(0xffffffffu, part, 2);
            float sc = ((kt * 64 + c) <= qg) ? part : -1e30f;
            if (dg == 0) Sc[row * 65 + c] = sc;
            rowmax = fmaxf(rowmax, sc);
        }
        __syncwarp();

        float mn = fmaxf(m, rowmax);
        float alpha = __expf(m - mn);
        l *= alpha;
#pragma unroll
        for (int i = 0; i < 32; i++) acc[i] *= alpha;

#pragma unroll 2
        for (int c = 0; c < 64; c++) {
            float p = __expf(Sc[row * 65 + c] - mn);
            l += p;
            const float4* vp = (const float4*)&Vs[c * 128 + dg * 32];
#pragma unroll
            for (int i = 0; i < 8; i++) {
                float4 vv = vp[i];
                acc[4*i+0] += p * vv.x; acc[4*i+1] += p * vv.y;
                acc[4*i+2] += p * vv.z; acc[4*i+3] += p * vv.w;
            }
        }
        m = mn;
        __syncthreads();
    }

    float inv_l = 1.f / l;
    float* op = o + ((size_t)(b * SS + qg)) * (NH * HD) + h * HD + dg * 32;
#pragma unroll
    for (int i = 0; i < 8; i++) {
        float4 ov = make_float4(acc[4*i+0]*inv_l, acc[4*i+1]*inv_l,
                                acc[4*i+2]*inv_l, acc[4*i+3]*inv_l);
        *(float4*)(op + 4 * i) = ov;
    }
}

// ---------------------------------------------------------------------------
extern "C" void kernel_launch(void* const* d_in, const int* in_sizes, int n_in,
                              void* d_out, int out_size) {
    const float* hid = (const float*)d_in[0];
    const int*   pos = (const int*)d_in[1];
    const float* Wq  = (const float*)d_in[2];
    const float* Wk  = (const float*)d_in[3];
    const float* Wv  = (const float*)d_in[4];
    const float* Wo  = (const float*)d_in[5];
    float* out = (float*)d_out;

    float *pq, *pk, *pv, *pattn;
    cudaGetSymbolAddress((void**)&pq,    g_q);
    cudaGetSymbolAddress((void**)&pk,    g_k);
    cudaGetSymbolAddress((void**)&pv,    g_v);
    cudaGetSymbolAddress((void**)&pattn, g_attn);
    __nv_bfloat16 *hh, *hl, *qh, *ql, *kh, *kl, *vh, *vl, *oh, *ol, *ah, *al;
    cudaGetSymbolAddress((void**)&hh, g_hid_h); cudaGetSymbolAddress((void**)&hl, g_hid_l);
    cudaGetSymbolAddress((void**)&qh, g_wq_h);  cudaGetSymbolAddress((void**)&ql, g_wq_l);
    cudaGetSymbolAddress((void**)&kh, g_wk_h);  cudaGetSymbolAddress((void**)&kl, g_wk_l);
    cudaGetSymbolAddress((void**)&vh, g_wv_h);  cudaGetSymbolAddress((void**)&vl, g_wv_l);
    cudaGetSymbolAddress((void**)&oh, g_wo_h);  cudaGetSymbolAddress((void**)&ol, g_wo_l);
    cudaGetSymbolAddress((void**)&ah, g_at_h);  cudaGetSymbolAddress((void**)&al, g_at_l);

    const int nHid = MROWS * DMODEL;
    const int nWq  = NH * HD * DMODEL;
    const int nWk  = NKV * HD * DMODEL;
    decompose<<<(nHid + 255) / 256, 256>>>(hid, hh, hl, nHid);
    decompose<<<(nWq  + 255) / 256, 256>>>(Wq,  qh, ql, nWq);
    decompose<<<(nWk  + 255) / 256, 256>>>(Wk,  kh, kl, nWk);
    decompose<<<(nWk  + 255) / 256, 256>>>(Wv,  vh, vl, nWk);
    decompose<<<(nWq  + 255) / 256, 256>>>(Wo,  oh, ol, nWq);

    cudaFuncSetAttribute(gemm_mma, cudaFuncAttributeMaxDynamicSharedMemorySize, GK_SMEM);

    gemm_mma<<<dim3(NH*HD/BN,  MROWS/BM), 256, GK_SMEM>>>(hh, hl, qh, ql, pq, MROWS, NH*HD,  DMODEL);
    gemm_mma<<<dim3(NKV*HD/BN, MROWS/BM), 256, GK_SMEM>>>(hh, hl, kh, kl, pk, MROWS, NKV*HD, DMODEL);
    gemm_mma<<<dim3(NKV*HD/BN, MROWS/BM), 256, GK_SMEM>>>(hh, hl, vh, vl, pv, MROWS, NKV*HD, DMODEL);

    rope_table<<<(MROWS*64 + 255)/256, 256>>>(pos);
    rope_apply<<<(MROWS*(NH+NKV)*64 + 255)/256, 256>>>();

    int smem = (2 * 64 * 128 + 64 * 65) * (int)sizeof(float);
    cudaFuncSetAttribute(flash_kernel, cudaFuncAttributeMaxDynamicSharedMemorySize, smem);
    flash_kernel<<<dim3(SS/64, NH, BB), 256, smem>>>(pq, pk, pv, pattn);

    const int nAt = MROWS * NH * HD;
    decompose<<<(nAt + 255) / 256, 256>>>(pattn, ah, al, nAt);
    gemm_mma<<<dim3(NH*HD/BN, MROWS/BM), 256, GK_SMEM>>>(ah, al, oh, ol, out, MROWS, NH*HD, NH*HD);
}

// round 6
// speedup vs baseline: 3.5193x; 2.8715x over previous
#include <cuda_runtime.h>
#include <cuda_fp16.h>
#include <math.h>
#include <stdint.h>

#define BB 2
#define SS 2048
#define DMODEL 4096
#define NH 32
#define NKV 8
#define HD 128
#define MROWS (BB*SS)   // 4096

// ---------------- scratch (device globals; no allocation allowed) ----------
__device__ float g_q[(size_t)MROWS * NH * HD];
__device__ float g_k[(size_t)MROWS * NKV * HD];
__device__ float g_v[(size_t)MROWS * NKV * HD];
__device__ float g_attn[(size_t)MROWS * NH * HD];
__device__ float g_cos[MROWS * (HD/2)];
__device__ float g_sin[MROWS * (HD/2)];

// fp16 operands
__device__ __half g_hid_f16[(size_t)MROWS * DMODEL];
__device__ __half g_at_f16[(size_t)MROWS * NH*HD];
__device__ __half g_wq_h[(size_t)NH*HD * DMODEL];
__device__ __half g_wq_l[(size_t)NH*HD * DMODEL];
__device__ __half g_wk_h[(size_t)NKV*HD * DMODEL];
__device__ __half g_wk_l[(size_t)NKV*HD * DMODEL];
__device__ __half g_wv_h[(size_t)NKV*HD * DMODEL];
__device__ __half g_wv_l[(size_t)NKV*HD * DMODEL];
__device__ __half g_wo_h[(size_t)NH*HD * NH*HD];
__device__ __half g_wo_l[(size_t)NH*HD * NH*HD];

// ---------------- PTX helpers (sm_80+ base-target safe) ---------------------
__device__ __forceinline__ uint32_t smem_u32(const void* p) {
    uint32_t a;
    asm("{ .reg .u64 t; cvta.to.shared.u64 t, %1; cvt.u32.u64 %0, t; }" : "=r"(a) : "l"(p));
    return a;
}
__device__ __forceinline__ void cp16(uint32_t dst, const void* src) {
    asm volatile("cp.async.cg.shared.global [%0], [%1], 16;\n" :: "r"(dst), "l"(src));
}
__device__ __forceinline__ void cp_commit() { asm volatile("cp.async.commit_group;\n" ::: "memory"); }

__device__ __forceinline__ void ldm_x4(uint32_t* r, uint32_t addr) {
    asm volatile("ldmatrix.sync.aligned.m8n8.x4.shared.b16 {%0,%1,%2,%3}, [%4];"
        : "=r"(r[0]), "=r"(r[1]), "=r"(r[2]), "=r"(r[3]) : "r"(addr));
}
__device__ __forceinline__ void mma16816(float* d, const uint32_t* a, const uint32_t* b) {
    asm volatile("mma.sync.aligned.m16n8k16.row.col.f32.f16.f16.f32 "
        "{%0,%1,%2,%3}, {%4,%5,%6,%7}, {%8,%9}, {%0,%1,%2,%3};"
        : "+f"(d[0]), "+f"(d[1]), "+f"(d[2]), "+f"(d[3])
        : "r"(a[0]), "r"(a[1]), "r"(a[2]), "r"(a[3]), "r"(b[0]), "r"(b[1]));
}

// ---------------- conversion kernels ----------------------------------------
__global__ void tofp16(const float* __restrict__ s, __half* __restrict__ d, int n) {
    int i = blockIdx.x * blockDim.x + threadIdx.x;
    if (i < n) d[i] = __float2half(s[i]);
}
__global__ void decompose_h(const float* __restrict__ s,
                            __half* __restrict__ h, __half* __restrict__ l, int n) {
    int i = blockIdx.x * blockDim.x + threadIdx.x;
    if (i >= n) return;
    float f = s[i];
    __half hh = __float2half(f);
    h[i] = hh;
    l[i] = __float2half(f - __half2float(hh));
}

// ---------------------------------------------------------------------------
// HMMA fp16 2-term split GEMM (NT): C[M,N] = A[M,K] @ W[N,K]^T, fp32 result.
// C ≈ Ah·Bh + Ah·Bl   (A = plain fp16 cast; B = fp16 hi/lo).
// CTA 128x256, BK=32, 8 warps (2x4, warp tile 64x64). 3-stage cp.async.
// A smem rows 64B (4 chunks, rotation swizzle (c + r/2)&3);
// B smem rows 128B packed hi|lo (8 chunks, XOR swizzle c^(r&7)).
// ---------------------------------------------------------------------------
#define BM 128
#define BN 256
#define STG_A_BYTES (128*64)                   // 8192
#define STG_B_BYTES (256*128)                  // 32768
#define STG_BYTES (STG_A_BYTES + STG_B_BYTES)  // 40960
#define GK_SMEM (3*STG_BYTES + 128)            // 123008

__global__ __launch_bounds__(256, 1)
void gemm_mma(const __half* __restrict__ A,
              const __half* __restrict__ Bh, const __half* __restrict__ Bl,
              float* __restrict__ C, int M, int N, int K) {
    extern __shared__ __half smraw[];
    uint32_t sm0 = (smem_u32(smraw) + 127) & ~127u;

    int t = threadIdx.x;
    int wid = t >> 5, lane = t & 31;
    int bm = blockIdx.y * BM, bn = blockIdx.x * BN;
    int wm = (wid >> 2) * 64;   // 0 or 64
    int wn = (wid & 3) * 64;    // 0,64,128,192

    float acc[4][8][4];
#pragma unroll
    for (int a = 0; a < 4; a++)
#pragma unroll
        for (int b = 0; b < 8; b++)
#pragma unroll
            for (int c = 0; c < 4; c++) acc[a][b][c] = 0.f;

    auto load_stage = [&](int s, int ck) {
        int k0 = ck * 32;
        uint32_t sb = sm0 + s * STG_BYTES;
#pragma unroll
        for (int i = 0; i < 2; i++) {           // A: 128 rows x 4 chunks
            int idx = i * 256 + t;
            int r = idx >> 2, c = idx & 3;
            cp16(sb + r * 64 + (((c + (r >> 1)) & 3) * 16),
                 A + (size_t)(bm + r) * K + k0 + c * 8);
        }
        uint32_t sbB = sb + STG_A_BYTES;
#pragma unroll
        for (int i = 0; i < 8; i++) {           // B: 256 rows x 8 chunks (hi|lo)
            int idx = i * 256 + t;
            int r = idx >> 3, c = idx & 7;
            const __half* src = ((c < 4) ? Bh : Bl)
                + (size_t)(bn + r) * K + k0 + (c & 3) * 8;
            cp16(sbB + r * 128 + ((c ^ (r & 7)) * 16), src);
        }
        cp_commit();
    };

    const int NCH = K >> 5;
    load_stage(0, 0);
    load_stage(1, 1);

    int laneR = lane & 15, laneH = lane >> 4;
    uint32_t aOff[4]; int aRot[4];
    uint32_t bBase[4];
#pragma unroll
    for (int mi = 0; mi < 4; mi++) {
        int r = wm + mi * 16 + laneR;
        aOff[mi] = sm0 + r * 64;
        aRot[mi] = r >> 1;
    }
#pragma unroll
    for (int nb = 0; nb < 4; nb++) {
        int r = wn + nb * 16 + laneR;
        bBase[nb] = sm0 + STG_A_BYTES + r * 128 + ((laneH ^ (r & 7)) * 16);
    }

    for (int ch = 0; ch < NCH; ch++) {
        if (ch + 2 < NCH) {
            load_stage((ch + 2) % 3, ch + 2);
            asm volatile("cp.async.wait_group 2;\n" ::: "memory");
        } else if (ch + 1 < NCH) {
            asm volatile("cp.async.wait_group 1;\n" ::: "memory");
        } else {
            asm volatile("cp.async.wait_group 0;\n" ::: "memory");
        }
        __syncthreads();

        uint32_t soff = (uint32_t)(ch % 3) * STG_BYTES;
#pragma unroll
        for (int kk = 0; kk < 2; kk++) {
            uint32_t kx = kk * 32;        // B: chunk^2 == addr^32
            int kc = kk * 2 + laneH;      // A logical chunk
            uint32_t ah[4][4];
#pragma unroll
            for (int mi = 0; mi < 4; mi++) {
                uint32_t a0 = aOff[mi] + soff + (((kc + aRot[mi]) & 3) * 16);
                ldm_x4(ah[mi], a0);
            }
#pragma unroll
            for (int half = 0; half < 2; half++) {
                uint32_t bh[2][4], bl[2][4];
#pragma unroll
                for (int j = 0; j < 2; j++) {
                    int nb = half * 2 + j;
                    uint32_t b0 = (bBase[nb] + soff) ^ kx;
                    ldm_x4(bh[j], b0);
                    ldm_x4(bl[j], b0 ^ 64);       // lo half: chunk^4
                }
#pragma unroll
                for (int mi = 0; mi < 4; mi++)
#pragma unroll
                    for (int j = 0; j < 2; j++)
#pragma unroll
                        for (int sub = 0; sub < 2; sub++) {
                            int ni = half * 4 + j * 2 + sub;
                            uint32_t fh[2] = { bh[j][sub], bh[j][2 + sub] };
                            uint32_t fl[2] = { bl[j][sub], bl[j][2 + sub] };
                            mma16816(acc[mi][ni], ah[mi], fh);
                            mma16816(acc[mi][ni], ah[mi], fl);
                        }
            }
        }
        __syncthreads();
    }

    // epilogue
    int row = lane >> 2;
    int col = (lane & 3) * 2;
#pragma unroll
    for (int mi = 0; mi < 4; mi++)
#pragma unroll
        for (int ni = 0; ni < 8; ni++) {
            float* c0 = C + (size_t)(bm + wm + mi * 16 + row) * N + bn + wn + ni * 8 + col;
            c0[0] = acc[mi][ni][0];
            c0[1] = acc[mi][ni][1];
            float* c1 = c0 + 8 * (size_t)N;
            c1[0] = acc[mi][ni][2];
            c1[1] = acc[mi][ni][3];
        }
}

// ---------------- RoPE -------------------------------------------------------
__global__ void rope_table(const int* __restrict__ pos) {
    int idx = blockIdx.x * blockDim.x + threadIdx.x;
    if (idx >= MROWS * 64) return;
    int i   = idx & 63;
    int row = idx >> 6;
    double inv = exp(-(double)(2 * i) / 128.0 * log(10000.0));
    double ang = (double)pos[row] * inv;
    g_cos[idx] = (float)cos(ang);
    g_sin[idx] = (float)sin(ang);
}
__global__ void rope_apply() {
    int idx = blockIdx.x * blockDim.x + threadIdx.x;
    const int total = MROWS * (NH + NKV) * 64;
    if (idx >= total) return;
    int i    = idx & 63;
    int head = (idx >> 6) % (NH + NKV);
    int row  = idx / (64 * (NH + NKV));
    float c = g_cos[row * 64 + i];
    float s = g_sin[row * 64 + i];
    float* base = (head < NH)
        ? (g_q + (size_t)row * NH * HD + head * HD)
        : (g_k + (size_t)row * NKV * HD + (head - NH) * HD);
    float x1 = base[i];
    float x2 = base[i + 64];
    base[i]      = x1 * c - x2 * s;
    base[i + 64] = x2 * c + x1 * s;
}

// ---------------- flash attention (fp32, causal, GQA) -----------------------
// Lane layout: lane = rl*4 + dg; warp owns 8 rows; lane owns INTERLEAVED dims
// d = dg*4 + i*16 + j (i=0..7, j=0..3) -> bank-conflict-free smem reads.
__global__ __launch_bounds__(256) void flash_kernel(const float* __restrict__ q,
                                                    const float* __restrict__ k,
                                                    const float* __restrict__ v,
                                                    float* __restrict__ o) {
    extern __shared__ float sm[];
    float* Ks = sm;
    float* Vs = sm + 64 * 128;
    float* Sc = sm + 2 * 64 * 128;

    int qt = blockIdx.x;
    int h  = blockIdx.y;
    int b  = blockIdx.z;
    int kvh = h >> 2;

    int t    = threadIdx.x;
    int warp = t >> 5;
    int lane = t & 31;
    int rl   = lane >> 2;
    int dg   = lane & 3;
    int row  = warp * 8 + rl;
    int qg   = qt * 64 + row;

    const float scale = 0.08838834764831845f;

    float qf[32];
    {
        const float* qp = q + ((size_t)(b * SS + qg)) * (NH * HD) + h * HD + dg * 4;
#pragma unroll
        for (int i = 0; i < 8; i++) {
            float4 t4 = *(const float4*)(qp + i * 16);
            qf[4*i+0] = t4.x * scale; qf[4*i+1] = t4.y * scale;
            qf[4*i+2] = t4.z * scale; qf[4*i+3] = t4.w * scale;
        }
    }

    float acc[32];
#pragma unroll
    for (int i = 0; i < 32; i++) acc[i] = 0.f;
    float m = -1e30f, l = 0.f;

    for (int kt = 0; kt <= qt; kt++) {
#pragma unroll
        for (int i = 0; i < 8; i++) {
            int idx = i * 256 + t;
            int r   = idx >> 5;
            int c4  = (idx & 31) * 4;
            size_t g = ((size_t)(b * SS + kt * 64 + r)) * (NKV * HD) + kvh * HD + c4;
            *(float4*)&Ks[r * 128 + c4] = *(const float4*)(k + g);
            *(float4*)&Vs[r * 128 + c4] = *(const float4*)(v + g);
        }
        __syncthreads();

        float rowmax = -1e30f;
#pragma unroll 4
        for (int c = 0; c < 64; c++) {
            const float* kp = &Ks[c * 128 + dg * 4];
            float part = 0.f;
#pragma unroll
            for (int i = 0; i < 8; i++) {
                float4 kv4 = *(const float4*)(kp + i * 16);
                part += qf[4*i+0]*kv4.x + qf[4*i+1]*kv4.y
                      + qf[4*i+2]*kv4.z + qf[4*i+3]*kv4.w;
            }
            part += __shfl_xor_sync(0xffffffffu, part, 1);
            part += __shfl_xor_sync(0xffffffffu, part, 2);
            float sc = ((kt * 64 + c) <= qg) ? part : -1e30f;
            if (dg == 0) Sc[row * 65 + c] = sc;
            rowmax = fmaxf(rowmax, sc);
        }
        __syncwarp();

        float mn = fmaxf(m, rowmax);
        float alpha = __expf(m - mn);
        l *= alpha;
#pragma unroll
        for (int i = 0; i < 32; i++) acc[i] *= alpha;

#pragma unroll 2
        for (int c = 0; c < 64; c++) {
            float p = __expf(Sc[row * 65 + c] - mn);
            l += p;
            const float* vp = &Vs[c * 128 + dg * 4];
#pragma unroll
            for (int i = 0; i < 8; i++) {
                float4 vv = *(const float4*)(vp + i * 16);
                acc[4*i+0] += p * vv.x; acc[4*i+1] += p * vv.y;
                acc[4*i+2] += p * vv.z; acc[4*i+3] += p * vv.w;
            }
        }
        m = mn;
        __syncthreads();
    }

    float inv_l = 1.f / l;
    float* op = o + ((size_t)(b * SS + qg)) * (NH * HD) + h * HD + dg * 4;
#pragma unroll
    for (int i = 0; i < 8; i++) {
        float4 ov = make_float4(acc[4*i+0]*inv_l, acc[4*i+1]*inv_l,
                                acc[4*i+2]*inv_l, acc[4*i+3]*inv_l);
        *(float4*)(op + i * 16) = ov;
    }
}

// ---------------------------------------------------------------------------
extern "C" void kernel_launch(void* const* d_in, const int* in_sizes, int n_in,
                              void* d_out, int out_size) {
    const float* hid = (const float*)d_in[0];
    const int*   pos = (const int*)d_in[1];
    const float* Wq  = (const float*)d_in[2];
    const float* Wk  = (const float*)d_in[3];
    const float* Wv  = (const float*)d_in[4];
    const float* Wo  = (const float*)d_in[5];
    float* out = (float*)d_out;

    float *pq, *pk, *pv, *pattn;
    cudaGetSymbolAddress((void**)&pq,    g_q);
    cudaGetSymbolAddress((void**)&pk,    g_k);
    cudaGetSymbolAddress((void**)&pv,    g_v);
    cudaGetSymbolAddress((void**)&pattn, g_attn);
    __half *hf, *af, *qh, *ql, *kh, *kl, *vh, *vl, *oh, *ol;
    cudaGetSymbolAddress((void**)&hf, g_hid_f16);
    cudaGetSymbolAddress((void**)&af, g_at_f16);
    cudaGetSymbolAddress((void**)&qh, g_wq_h);  cudaGetSymbolAddress((void**)&ql, g_wq_l);
    cudaGetSymbolAddress((void**)&kh, g_wk_h);  cudaGetSymbolAddress((void**)&kl, g_wk_l);
    cudaGetSymbolAddress((void**)&vh, g_wv_h);  cudaGetSymbolAddress((void**)&vl, g_wv_l);
    cudaGetSymbolAddress((void**)&oh, g_wo_h);  cudaGetSymbolAddress((void**)&ol, g_wo_l);

    const int nHid = MROWS * DMODEL;
    const int nWq  = NH * HD * DMODEL;
    const int nWk  = NKV * HD * DMODEL;
    tofp16<<<(nHid + 255) / 256, 256>>>(hid, hf, nHid);
    decompose_h<<<(nWq + 255) / 256, 256>>>(Wq, qh, ql, nWq);
    decompose_h<<<(nWk + 255) / 256, 256>>>(Wk, kh, kl, nWk);
    decompose_h<<<(nWk + 255) / 256, 256>>>(Wv, vh, vl, nWk);
    decompose_h<<<(nWq + 255) / 256, 256>>>(Wo, oh, ol, nWq);

    cudaFuncSetAttribute(gemm_mma, cudaFuncAttributeMaxDynamicSharedMemorySize, GK_SMEM);

    gemm_mma<<<dim3(NH*HD/BN,  MROWS/BM), 256, GK_SMEM>>>(hf, qh, ql, pq, MROWS, NH*HD,  DMODEL);
    gemm_mma<<<dim3(NKV*HD/BN, MROWS/BM), 256, GK_SMEM>>>(hf, kh, kl, pk, MROWS, NKV*HD, DMODEL);
    gemm_mma<<<dim3(NKV*HD/BN, MROWS/BM), 256, GK_SMEM>>>(hf, vh, vl, pv, MROWS, NKV*HD, DMODEL);

    rope_table<<<(MROWS*64 + 255)/256, 256>>>(pos);
    rope_apply<<<(MROWS*(NH+NKV)*64 + 255)/256, 256>>>();

    int smem = (2 * 64 * 128 + 64 * 65) * (int)sizeof(float);
    cudaFuncSetAttribute(flash_kernel, cudaFuncAttributeMaxDynamicSharedMemorySize, smem);
    flash_kernel<<<dim3(SS/64, NH, BB), 256, smem>>>(pq, pk, pv, pattn);

    const int nAt = MROWS * NH * HD;
    tofp16<<<(nAt + 255) / 256, 256>>>(pattn, af, nAt);
    gemm_mma<<<dim3(NH*HD/BN, MROWS/BM), 256, GK_SMEM>>>(af, oh, ol, out, MROWS, NH*HD, NH*HD);
}

// round 8
// speedup vs baseline: 7.7986x; 2.2160x over previous
#include <cuda_runtime.h>
#include <cuda_fp16.h>
#include <math.h>
#include <stdint.h>

#define BB 2
#define SS 2048
#define DMODEL 4096
#define NH 32
#define NKV 8
#define HD 128
#define MROWS (BB*SS)   // 4096
#define QSCALE 0.08838834764831845f

extern __shared__ char dyn_smem[];

// ---------------- scratch (device globals; no allocation allowed) ----------
__device__ float g_q[(size_t)MROWS * NH * HD];
__device__ float g_k[(size_t)MROWS * NKV * HD];
__device__ float g_v[(size_t)MROWS * NKV * HD];
__device__ float g_attn[(size_t)MROWS * NH * HD];
__device__ float g_cos[MROWS * (HD/2)];
__device__ float g_sin[MROWS * (HD/2)];

// fp16 operands
__device__ __half g_hid_f16[(size_t)MROWS * DMODEL];
__device__ __half g_at_f16[(size_t)MROWS * NH*HD];
__device__ __half g_wq_h[(size_t)NH*HD * DMODEL];
__device__ __half g_wq_l[(size_t)NH*HD * DMODEL];
__device__ __half g_wk_h[(size_t)NKV*HD * DMODEL];
__device__ __half g_wk_l[(size_t)NKV*HD * DMODEL];
__device__ __half g_wv_h[(size_t)NKV*HD * DMODEL];
__device__ __half g_wv_l[(size_t)NKV*HD * DMODEL];
__device__ __half g_wo_h[(size_t)NH*HD * NH*HD];
__device__ __half g_wo_l[(size_t)NH*HD * NH*HD];

// fp16 attention operands (post-rope, split)
__device__ __half g_qh[(size_t)MROWS * NH * HD];
__device__ __half g_ql[(size_t)MROWS * NH * HD];
__device__ __half g_kh[(size_t)MROWS * NKV * HD];
__device__ __half g_kl[(size_t)MROWS * NKV * HD];
__device__ __half g_vth[(size_t)BB * NKV * HD * SS];  // [b][kvh][d][s]
__device__ __half g_vtl[(size_t)BB * NKV * HD * SS];

// ---------------- PTX helpers (sm_80+ base-target safe) ---------------------
__device__ __forceinline__ uint32_t smem_u32(const void* p) {
    uint32_t a;
    asm("{ .reg .u64 t; cvta.to.shared.u64 t, %1; cvt.u32.u64 %0, t; }" : "=r"(a) : "l"(p));
    return a;
}
__device__ __forceinline__ void cp16(uint32_t dst, const void* src) {
    asm volatile("cp.async.cg.shared.global [%0], [%1], 16;\n" :: "r"(dst), "l"(src));
}
__device__ __forceinline__ void cp_commit() { asm volatile("cp.async.commit_group;\n" ::: "memory"); }

__device__ __forceinline__ void ldm_x4(uint32_t* r, uint32_t addr) {
    asm volatile("ldmatrix.sync.aligned.m8n8.x4.shared.b16 {%0,%1,%2,%3}, [%4];"
        : "=r"(r[0]), "=r"(r[1]), "=r"(r[2]), "=r"(r[3]) : "r"(addr));
}
__device__ __forceinline__ void mma16816(float* d, const uint32_t* a, const uint32_t* b) {
    asm volatile("mma.sync.aligned.m16n8k16.row.col.f32.f16.f16.f32 "
        "{%0,%1,%2,%3}, {%4,%5,%6,%7}, {%8,%9}, {%0,%1,%2,%3};"
        : "+f"(d[0]), "+f"(d[1]), "+f"(d[2]), "+f"(d[3])
        : "r"(a[0]), "r"(a[1]), "r"(a[2]), "r"(a[3]), "r"(b[0]), "r"(b[1]));
}

// ---------------- conversion kernels ----------------------------------------
__global__ void tofp16(const float* __restrict__ s, __half* __restrict__ d, int n) {
    int i = blockIdx.x * blockDim.x + threadIdx.x;
    if (i < n) d[i] = __float2half(s[i]);
}
__global__ void decompose_h(const float* __restrict__ s,
                            __half* __restrict__ h, __half* __restrict__ l, int n) {
    int i = blockIdx.x * blockDim.x + threadIdx.x;
    if (i >= n) return;
    float f = s[i];
    __half hh = __float2half(f);
    h[i] = hh;
    l[i] = __float2half(f - __half2float(hh));
}

// ---------------------------------------------------------------------------
// HMMA fp16 2-term split GEMM (NT): C[M,N] = A[M,K] @ W[N,K]^T, fp32 result.
// ---------------------------------------------------------------------------
#define BM 128
#define BN 256
#define STG_A_BYTES (128*64)
#define STG_B_BYTES (256*128)
#define STG_BYTES (STG_A_BYTES + STG_B_BYTES)
#define GK_SMEM (3*STG_BYTES + 128)

__global__ __launch_bounds__(256, 1)
void gemm_mma(const __half* __restrict__ A,
              const __half* __restrict__ Bh, const __half* __restrict__ Bl,
              float* __restrict__ C, int M, int N, int K) {
    uint32_t sm0 = (smem_u32(dyn_smem) + 127) & ~127u;

    int t = threadIdx.x;
    int wid = t >> 5, lane = t & 31;
    int bm = blockIdx.y * BM, bn = blockIdx.x * BN;
    int wm = (wid >> 2) * 64;
    int wn = (wid & 3) * 64;

    float acc[4][8][4];
#pragma unroll
    for (int a = 0; a < 4; a++)
#pragma unroll
        for (int b = 0; b < 8; b++)
#pragma unroll
            for (int c = 0; c < 4; c++) acc[a][b][c] = 0.f;

    auto load_stage = [&](int s, int ck) {
        int k0 = ck * 32;
        uint32_t sb = sm0 + s * STG_BYTES;
#pragma unroll
        for (int i = 0; i < 2; i++) {
            int idx = i * 256 + t;
            int r = idx >> 2, c = idx & 3;
            cp16(sb + r * 64 + (((c + (r >> 1)) & 3) * 16),
                 A + (size_t)(bm + r) * K + k0 + c * 8);
        }
        uint32_t sbB = sb + STG_A_BYTES;
#pragma unroll
        for (int i = 0; i < 8; i++) {
            int idx = i * 256 + t;
            int r = idx >> 3, c = idx & 7;
            const __half* src = ((c < 4) ? Bh : Bl)
                + (size_t)(bn + r) * K + k0 + (c & 3) * 8;
            cp16(sbB + r * 128 + ((c ^ (r & 7)) * 16), src);
        }
        cp_commit();
    };

    const int NCH = K >> 5;
    load_stage(0, 0);
    load_stage(1, 1);

    int laneR = lane & 15, laneH = lane >> 4;
    uint32_t aOff[4]; int aRot[4];
    uint32_t bBase[4];
#pragma unroll
    for (int mi = 0; mi < 4; mi++) {
        int r = wm + mi * 16 + laneR;
        aOff[mi] = sm0 + r * 64;
        aRot[mi] = r >> 1;
    }
#pragma unroll
    for (int nb = 0; nb < 4; nb++) {
        int r = wn + nb * 16 + laneR;
        bBase[nb] = sm0 + STG_A_BYTES + r * 128 + ((laneH ^ (r & 7)) * 16);
    }

    for (int ch = 0; ch < NCH; ch++) {
        if (ch + 2 < NCH) {
            load_stage((ch + 2) % 3, ch + 2);
            asm volatile("cp.async.wait_group 2;\n" ::: "memory");
        } else if (ch + 1 < NCH) {
            asm volatile("cp.async.wait_group 1;\n" ::: "memory");
        } else {
            asm volatile("cp.async.wait_group 0;\n" ::: "memory");
        }
        __syncthreads();

        uint32_t soff = (uint32_t)(ch % 3) * STG_BYTES;
#pragma unroll
        for (int kk = 0; kk < 2; kk++) {
            uint32_t kx = kk * 32;
            int kc = kk * 2 + laneH;
            uint32_t ah[4][4];
#pragma unroll
            for (int mi = 0; mi < 4; mi++) {
                uint32_t a0 = aOff[mi] + soff + (((kc + aRot[mi]) & 3) * 16);
                ldm_x4(ah[mi], a0);
            }
#pragma unroll
            for (int half = 0; half < 2; half++) {
                uint32_t bh[2][4], bl[2][4];
#pragma unroll
                for (int j = 0; j < 2; j++) {
                    int nb = half * 2 + j;
                    uint32_t b0 = (bBase[nb] + soff) ^ kx;
                    ldm_x4(bh[j], b0);
                    ldm_x4(bl[j], b0 ^ 64);
                }
#pragma unroll
                for (int mi = 0; mi < 4; mi++)
#pragma unroll
                    for (int j = 0; j < 2; j++)
#pragma unroll
                        for (int sub = 0; sub < 2; sub++) {
                            int ni = half * 4 + j * 2 + sub;
                            uint32_t fh[2] = { bh[j][sub], bh[j][2 + sub] };
                            uint32_t fl[2] = { bl[j][sub], bl[j][2 + sub] };
                            mma16816(acc[mi][ni], ah[mi], fh);
                            mma16816(acc[mi][ni], ah[mi], fl);
                        }
            }
        }
        __syncthreads();
    }

    int row = lane >> 2;
    int col = (lane & 3) * 2;
#pragma unroll
    for (int mi = 0; mi < 4; mi++)
#pragma unroll
        for (int ni = 0; ni < 8; ni++) {
            float* c0 = C + (size_t)(bm + wm + mi * 16 + row) * N + bn + wn + ni * 8 + col;
            c0[0] = acc[mi][ni][0];
            c0[1] = acc[mi][ni][1];
            float* c1 = c0 + 8 * (size_t)N;
            c1[0] = acc[mi][ni][2];
            c1[1] = acc[mi][ni][3];
        }
}

// ---------------- RoPE table ------------------------------------------------
__global__ void rope_table(const int* __restrict__ pos) {
    int idx = blockIdx.x * blockDim.x + threadIdx.x;
    if (idx >= MROWS * 64) return;
    int i   = idx & 63;
    int row = idx >> 6;
    double inv = exp(-(double)(2 * i) / 128.0 * log(10000.0));
    double ang = (double)pos[row] * inv;
    g_cos[idx] = (float)cos(ang);
    g_sin[idx] = (float)sin(ang);
}

// ---------------- fused RoPE + fp16 hi/lo split ------------------------------
__global__ void rope_split_q() {
    int idx = blockIdx.x * blockDim.x + threadIdx.x;
    if (idx >= MROWS * NH * 64) return;
    int i   = idx & 63;
    int h   = (idx >> 6) & (NH - 1);
    int row = idx >> 11;
    float c = g_cos[row * 64 + i];
    float s = g_sin[row * 64 + i];
    size_t o = (size_t)row * NH * HD + h * HD;
    float x1 = g_q[o + i], x2 = g_q[o + i + 64];
    float y1 = (x1 * c - x2 * s) * QSCALE;
    float y2 = (x2 * c + x1 * s) * QSCALE;
    __half h1 = __float2half(y1), h2 = __float2half(y2);
    g_qh[o + i] = h1;      g_ql[o + i]      = __float2half(y1 - __half2float(h1));
    g_qh[o + i + 64] = h2; g_ql[o + i + 64] = __float2half(y2 - __half2float(h2));
}
__global__ void rope_split_k() {
    int idx = blockIdx.x * blockDim.x + threadIdx.x;
    if (idx >= MROWS * NKV * 64) return;
    int i   = idx & 63;
    int h   = (idx >> 6) & (NKV - 1);
    int row = idx >> 9;
    float c = g_cos[row * 64 + i];
    float s = g_sin[row * 64 + i];
    size_t o = (size_t)row * NKV * HD + h * HD;
    float x1 = g_k[o + i], x2 = g_k[o + i + 64];
    float y1 = x1 * c - x2 * s;
    float y2 = x2 * c + x1 * s;
    __half h1 = __float2half(y1), h2 = __float2half(y2);
    g_kh[o + i] = h1;      g_kl[o + i]      = __float2half(y1 - __half2float(h1));
    g_kh[o + i + 64] = h2; g_kl[o + i + 64] = __float2half(y2 - __half2float(h2));
}

// ---------------- V transpose + split: g_v -> Vt[b][kvh][d][s] ---------------
__global__ __launch_bounds__(256) void split_vt() {
    __shared__ float sv[64][129];
    int blk = blockIdx.x;                 // (b*8+kvh)*32 + st
    int st  = blk & 31;
    int kvh = (blk >> 5) & 7;
    int b   = blk >> 8;
    int tid = threadIdx.x;
#pragma unroll
    for (int it = 0; it < 32; it++) {
        int idx = it * 256 + tid;
        int r = idx >> 7, c = idx & 127;
        sv[r][c] = g_v[(size_t)(b * SS + st * 64 + r) * (NKV * HD) + kvh * HD + c];
    }
    __syncthreads();
    int d = tid >> 1, j = tid & 1;
    __half hbuf[32], lbuf[32];
#pragma unroll
    for (int q = 0; q < 32; q++) {
        float f = sv[j * 32 + q][d];
        __half hh = __float2half(f);
        hbuf[q] = hh;
        lbuf[q] = __float2half(f - __half2float(hh));
    }
    size_t base = ((size_t)(b * NKV + kvh) * HD + d) * SS + st * 64 + j * 32;
    uint4* dh = (uint4*)(g_vth + base);
    uint4* dl = (uint4*)(g_vtl + base);
#pragma unroll
    for (int q = 0; q < 4; q++) {
        dh[q] = ((uint4*)hbuf)[q];
        dl[q] = ((uint4*)lbuf)[q];
    }
}

// ---------------------------------------------------------------------------
// HMMA flash attention: fp16 split QK (3-term) and PV (3-term), fp32 softmax.
// Block 128 thr (4 warps), Br=64 q rows, Bc=64 kv cols, D=128.
// ---------------------------------------------------------------------------
#define SQH 0
#define SQL 16384
#define SKH 32768
#define SKL 49152
#define SVH 65536
#define SVL 81920
#define FL_SMEM 98304

__global__ __launch_bounds__(128) void flash_mma(
    const __half* __restrict__ Qh_g, const __half* __restrict__ Ql_g,
    const __half* __restrict__ Kh_g, const __half* __restrict__ Kl_g,
    const __half* __restrict__ Vth_g, const __half* __restrict__ Vtl_g,
    float* __restrict__ out) {
    uint32_t s0 = smem_u32(dyn_smem);

    int qt = blockIdx.x, h = blockIdx.y, b = blockIdx.z;
    int kvh = h >> 2;
    int t = threadIdx.x, wid = t >> 5, lane = t & 31;
    int laneR = lane & 15, laneH = lane >> 4;
    int wm = wid * 16;

    // Q tile (once per CTA)
#pragma unroll
    for (int i = 0; i < 8; i++) {
        int idx = i * 128 + t;
        int r = idx >> 4, c = idx & 15;
        uint32_t d = r * 256 + ((c ^ (r & 7)) * 16);
        size_t g = ((size_t)(b * SS + qt * 64 + r)) * (NH * HD) + h * HD + c * 8;
        cp16(s0 + SQH + d, Qh_g + g);
        cp16(s0 + SQL + d, Ql_g + g);
    }
    auto loadKV = [&](int kt) {
#pragma unroll
        for (int i = 0; i < 8; i++) {
            int idx = i * 128 + t;
            int r = idx >> 4, c = idx & 15;
            uint32_t d = r * 256 + ((c ^ (r & 7)) * 16);
            size_t g = ((size_t)(b * SS + kt * 64 + r)) * (NKV * HD) + kvh * HD + c * 8;
            cp16(s0 + SKH + d, Kh_g + g);
            cp16(s0 + SKL + d, Kl_g + g);
        }
#pragma unroll
        for (int i = 0; i < 8; i++) {
            int idx = i * 128 + t;
            int r = idx >> 3, c = idx & 7;
            uint32_t d = r * 128 + ((c ^ (r & 7)) * 16);
            size_t g = ((size_t)((b * NKV + kvh) * HD + r)) * SS + kt * 64 + c * 8;
            cp16(s0 + SVH + d, Vth_g + g);
            cp16(s0 + SVL + d, Vtl_g + g);
        }
    };
    loadKV(0);
    cp_commit();

    float o_[16][4];
#pragma unroll
    for (int n = 0; n < 16; n++)
#pragma unroll
        for (int c = 0; c < 4; c++) o_[n][c] = 0.f;
    float m0 = -1e30f, m1 = -1e30f, l0 = 0.f, l1 = 0.f;
    int r0 = lane >> 2;
    int qrow0 = qt * 64 + wm + r0;
    int qrow1 = qrow0 + 8;

    for (int kt = 0; kt <= qt; kt++) {
        asm volatile("cp.async.wait_group 0;\n" ::: "memory");
        __syncthreads();

        // --- S = Q K^T (3-term split) ---
        float s[8][4];
#pragma unroll
        for (int j = 0; j < 8; j++)
#pragma unroll
            for (int c = 0; c < 4; c++) s[j][c] = 0.f;

#pragma unroll
        for (int kk = 0; kk < 8; kk++) {
            uint32_t qa[4], qb[4];
            {
                int r = wm + laneR;
                uint32_t ph = (uint32_t)(((kk * 2 + laneH) ^ (r & 7)) * 16);
                ldm_x4(qa, s0 + SQH + r * 256 + ph);
                ldm_x4(qb, s0 + SQL + r * 256 + ph);
            }
#pragma unroll
            for (int jj = 0; jj < 4; jj++) {
                uint32_t kh_[4], kl_[4];
                int r = jj * 16 + laneR;
                uint32_t ph = (uint32_t)(((kk * 2 + laneH) ^ (r & 7)) * 16);
                ldm_x4(kh_, s0 + SKH + r * 256 + ph);
                ldm_x4(kl_, s0 + SKL + r * 256 + ph);
#pragma unroll
                for (int sub = 0; sub < 2; sub++) {
                    int j = jj * 2 + sub;
                    uint32_t fh[2] = { kh_[sub], kh_[2 + sub] };
                    uint32_t fl[2] = { kl_[sub], kl_[2 + sub] };
                    mma16816(s[j], qa, fh);
                    mma16816(s[j], qa, fl);
                    mma16816(s[j], qb, fh);
                }
            }
        }

        // --- causal mask (diagonal tile only) ---
        if (kt == qt) {
#pragma unroll
            for (int j = 0; j < 8; j++) {
                int cb = kt * 64 + j * 8 + (lane & 3) * 2;
                if (cb     > qrow0) s[j][0] = -1e30f;
                if (cb + 1 > qrow0) s[j][1] = -1e30f;
                if (cb     > qrow1) s[j][2] = -1e30f;
                if (cb + 1 > qrow1) s[j][3] = -1e30f;
            }
        }

        // --- online softmax ---
        float rm0 = -1e30f, rm1 = -1e30f;
#pragma unroll
        for (int j = 0; j < 8; j++) {
            rm0 = fmaxf(rm0, fmaxf(s[j][0], s[j][1]));
            rm1 = fmaxf(rm1, fmaxf(s[j][2], s[j][3]));
        }
        rm0 = fmaxf(rm0, __shfl_xor_sync(0xffffffffu, rm0, 1));
        rm0 = fmaxf(rm0, __shfl_xor_sync(0xffffffffu, rm0, 2));
        rm1 = fmaxf(rm1, __shfl_xor_sync(0xffffffffu, rm1, 1));
        rm1 = fmaxf(rm1, __shfl_xor_sync(0xffffffffu, rm1, 2));
        float mn0 = fmaxf(m0, rm0), mn1 = fmaxf(m1, rm1);
        float a0 = __expf(m0 - mn0), a1 = __expf(m1 - mn1);
        l0 *= a0; l1 *= a1;
#pragma unroll
        for (int n = 0; n < 16; n++) {
            o_[n][0] *= a0; o_[n][1] *= a0;
            o_[n][2] *= a1; o_[n][3] *= a1;
        }
        m0 = mn0; m1 = mn1;

        uint32_t ph0[8], ph1[8], pl0[8], pl1[8];
        float sum0 = 0.f, sum1 = 0.f;
#pragma unroll
        for (int j = 0; j < 8; j++) {
            float e0 = __expf(s[j][0] - mn0), e1 = __expf(s[j][1] - mn0);
            float e2 = __expf(s[j][2] - mn1), e3 = __expf(s[j][3] - mn1);
            sum0 += e0 + e1; sum1 += e2 + e3;
            __half2 hh0 = __floats2half2_rn(e0, e1);
            __half2 hh1 = __floats2half2_rn(e2, e3);
            ph0[j] = *(uint32_t*)&hh0;
            ph1[j] = *(uint32_t*)&hh1;
            __half2 dd0 = __floats2half2_rn(e0 - __low2float(hh0), e1 - __high2float(hh0));
            __half2 dd1 = __floats2half2_rn(e2 - __low2float(hh1), e3 - __high2float(hh1));
            pl0[j] = *(uint32_t*)&dd0;
            pl1[j] = *(uint32_t*)&dd1;
        }
        sum0 += __shfl_xor_sync(0xffffffffu, sum0, 1);
        sum0 += __shfl_xor_sync(0xffffffffu, sum0, 2);
        sum1 += __shfl_xor_sync(0xffffffffu, sum1, 1);
        sum1 += __shfl_xor_sync(0xffffffffu, sum1, 2);
        l0 += sum0; l1 += sum1;

        // --- O += P V (3-term split) ---
#pragma unroll
        for (int tt = 0; tt < 4; tt++) {
            uint32_t pa[4] = { ph0[2*tt], ph1[2*tt], ph0[2*tt+1], ph1[2*tt+1] };
            uint32_t pb[4] = { pl0[2*tt], pl1[2*tt], pl0[2*tt+1], pl1[2*tt+1] };
#pragma unroll
            for (int dg = 0; dg < 8; dg++) {
                uint32_t vh_[4], vl_[4];
                int r = dg * 16 + laneR;
                uint32_t ph = (uint32_t)(((tt * 2 + laneH) ^ (r & 7)) * 16);
                ldm_x4(vh_, s0 + SVH + r * 128 + ph);
                ldm_x4(vl_, s0 + SVL + r * 128 + ph);
#pragma unroll
                for (int sub = 0; sub < 2; sub++) {
                    int n = dg * 2 + sub;
                    uint32_t fh[2] = { vh_[sub], vh_[2 + sub] };
                    uint32_t fl[2] = { vl_[sub], vl_[2 + sub] };
                    mma16816(o_[n], pa, fh);
                    mma16816(o_[n], pa, fl);
                    mma16816(o_[n], pb, fh);
                }
            }
        }

        __syncthreads();
        if (kt + 1 <= qt) {
            loadKV(kt + 1);
            cp_commit();
        }
    }

    float il0 = 1.f / l0, il1 = 1.f / l1;
    size_t ob0 = (size_t)(b * SS + qrow0) * (NH * HD) + h * HD + (lane & 3) * 2;
    size_t ob1 = (size_t)(b * SS + qrow1) * (NH * HD) + h * HD + (lane & 3) * 2;
#pragma unroll
    for (int n = 0; n < 16; n++) {
        float2 w0 = make_float2(o_[n][0] * il0, o_[n][1] * il0);
        float2 w1 = make_float2(o_[n][2] * il1, o_[n][3] * il1);
        *(float2*)(out + ob0 + n * 8) = w0;
        *(float2*)(out + ob1 + n * 8) = w1;
    }
}

// ---------------------------------------------------------------------------
extern "C" void kernel_launch(void* const* d_in, const int* in_sizes, int n_in,
                              void* d_out, int out_size) {
    const float* hid = (const float*)d_in[0];
    const int*   pos = (const int*)d_in[1];
    const float* Wq  = (const float*)d_in[2];
    const float* Wk  = (const float*)d_in[3];
    const float* Wv  = (const float*)d_in[4];
    const float* Wo  = (const float*)d_in[5];
    float* out = (float*)d_out;

    float *pq, *pk, *pv, *pattn;
    cudaGetSymbolAddress((void**)&pq,    g_q);
    cudaGetSymbolAddress((void**)&pk,    g_k);
    cudaGetSymbolAddress((void**)&pv,    g_v);
    cudaGetSymbolAddress((void**)&pattn, g_attn);
    __half *hf, *af, *qh, *ql, *kh, *kl, *vh, *vl, *oh, *ol;
    __half *fqh, *fql, *fkh, *fkl, *fvh, *fvl;
    cudaGetSymbolAddress((void**)&hf, g_hid_f16);
    cudaGetSymbolAddress((void**)&af, g_at_f16);
    cudaGetSymbolAddress((void**)&qh, g_wq_h);  cudaGetSymbolAddress((void**)&ql, g_wq_l);
    cudaGetSymbolAddress((void**)&kh, g_wk_h);  cudaGetSymbolAddress((void**)&kl, g_wk_l);
    cudaGetSymbolAddress((void**)&vh, g_wv_h);  cudaGetSymbolAddress((void**)&vl, g_wv_l);
    cudaGetSymbolAddress((void**)&oh, g_wo_h);  cudaGetSymbolAddress((void**)&ol, g_wo_l);
    cudaGetSymbolAddress((void**)&fqh, g_qh);   cudaGetSymbolAddress((void**)&fql, g_ql);
    cudaGetSymbolAddress((void**)&fkh, g_kh);   cudaGetSymbolAddress((void**)&fkl, g_kl);
    cudaGetSymbolAddress((void**)&fvh, g_vth);  cudaGetSymbolAddress((void**)&fvl, g_vtl);

    const int nHid = MROWS * DMODEL;
    const int nWq  = NH * HD * DMODEL;
    const int nWk  = NKV * HD * DMODEL;
    tofp16<<<(nHid + 255) / 256, 256>>>(hid, hf, nHid);
    decompose_h<<<(nWq + 255) / 256, 256>>>(Wq, qh, ql, nWq);
    decompose_h<<<(nWk + 255) / 256, 256>>>(Wk, kh, kl, nWk);
    decompose_h<<<(nWk + 255) / 256, 256>>>(Wv, vh, vl, nWk);
    decompose_h<<<(nWq + 255) / 256, 256>>>(Wo, oh, ol, nWq);

    cudaFuncSetAttribute(gemm_mma, cudaFuncAttributeMaxDynamicSharedMemorySize, GK_SMEM);

    gemm_mma<<<dim3(NH*HD/BN,  MROWS/BM), 256, GK_SMEM>>>(hf, qh, ql, pq, MROWS, NH*HD,  DMODEL);
    gemm_mma<<<dim3(NKV*HD/BN, MROWS/BM), 256, GK_SMEM>>>(hf, kh, kl, pk, MROWS, NKV*HD, DMODEL);
    gemm_mma<<<dim3(NKV*HD/BN, MROWS/BM), 256, GK_SMEM>>>(hf, vh, vl, pv, MROWS, NKV*HD, DMODEL);

    rope_table<<<(MROWS*64 + 255)/256, 256>>>(pos);
    rope_split_q<<<(MROWS*NH*64 + 255)/256, 256>>>();
    rope_split_k<<<(MROWS*NKV*64 + 255)/256, 256>>>();
    split_vt<<<BB*NKV*32, 256>>>();

    cudaFuncSetAttribute(flash_mma, cudaFuncAttributeMaxDynamicSharedMemorySize, FL_SMEM);
    flash_mma<<<dim3(SS/64, NH, BB), 128, FL_SMEM>>>(fqh, fql, fkh, fkl, fvh, fvl, pattn);

    const int nAt = MROWS * NH * HD;
    tofp16<<<(nAt + 255) / 256, 256>>>(pattn, af, nAt);
    gemm_mma<<<dim3(NH*HD/BN, MROWS/BM), 256, GK_SMEM>>>(af, oh, ol, out, MROWS, NH*HD, NH*HD);
}

// round 9
// speedup vs baseline: 7.9943x; 1.0251x over previous
#include <cuda_runtime.h>
#include <cuda_fp16.h>
#include <math.h>
#include <stdint.h>

#define BB 2
#define SS 2048
#define DMODEL 4096
#define NH 32
#define NKV 8
#define HD 128
#define MROWS (BB*SS)   // 4096
#define QSCALE 0.08838834764831845f

extern __shared__ char dyn_smem[];

// ---------------- scratch (device globals; no allocation allowed) ----------
__device__ float g_q[(size_t)MROWS * NH * HD];
__device__ float g_k[(size_t)MROWS * NKV * HD];
__device__ float g_v[(size_t)MROWS * NKV * HD];
__device__ float g_cos[MROWS * (HD/2)];
__device__ float g_sin[MROWS * (HD/2)];

// fp16 operands
__device__ __half g_hid_f16[(size_t)MROWS * DMODEL];
__device__ __half g_at_f16[(size_t)MROWS * NH*HD];
__device__ __half g_wq_h[(size_t)NH*HD * DMODEL];
__device__ __half g_wq_l[(size_t)NH*HD * DMODEL];
__device__ __half g_wk_h[(size_t)NKV*HD * DMODEL];
__device__ __half g_wk_l[(size_t)NKV*HD * DMODEL];
__device__ __half g_wv_h[(size_t)NKV*HD * DMODEL];
__device__ __half g_wv_l[(size_t)NKV*HD * DMODEL];
__device__ __half g_wo_h[(size_t)NH*HD * NH*HD];
__device__ __half g_wo_l[(size_t)NH*HD * NH*HD];

// fp16 attention operands (post-rope, split)
__device__ __half g_qh[(size_t)MROWS * NH * HD];
__device__ __half g_ql[(size_t)MROWS * NH * HD];
__device__ __half g_kh[(size_t)MROWS * NKV * HD];
__device__ __half g_kl[(size_t)MROWS * NKV * HD];
__device__ __half g_vth[(size_t)BB * NKV * HD * SS];  // [b][kvh][d][s]
__device__ __half g_vtl[(size_t)BB * NKV * HD * SS];

// ---------------- PTX helpers (sm_80+ base-target safe) ---------------------
__device__ __forceinline__ uint32_t smem_u32(const void* p) {
    uint32_t a;
    asm("{ .reg .u64 t; cvta.to.shared.u64 t, %1; cvt.u32.u64 %0, t; }" : "=r"(a) : "l"(p));
    return a;
}
__device__ __forceinline__ void cp16(uint32_t dst, const void* src) {
    asm volatile("cp.async.cg.shared.global [%0], [%1], 16;\n" :: "r"(dst), "l"(src));
}
__device__ __forceinline__ void cp_commit() { asm volatile("cp.async.commit_group;\n" ::: "memory"); }

__device__ __forceinline__ void ldm_x4(uint32_t* r, uint32_t addr) {
    asm volatile("ldmatrix.sync.aligned.m8n8.x4.shared.b16 {%0,%1,%2,%3}, [%4];"
        : "=r"(r[0]), "=r"(r[1]), "=r"(r[2]), "=r"(r[3]) : "r"(addr));
}
__device__ __forceinline__ void mma16816(float* d, const uint32_t* a, const uint32_t* b) {
    asm volatile("mma.sync.aligned.m16n8k16.row.col.f32.f16.f16.f32 "
        "{%0,%1,%2,%3}, {%4,%5,%6,%7}, {%8,%9}, {%0,%1,%2,%3};"
        : "+f"(d[0]), "+f"(d[1]), "+f"(d[2]), "+f"(d[3])
        : "r"(a[0]), "r"(a[1]), "r"(a[2]), "r"(a[3]), "r"(b[0]), "r"(b[1]));
}

// ---------------- conversion kernels ----------------------------------------
__global__ void tofp16(const float* __restrict__ s, __half* __restrict__ d, int n) {
    int i = blockIdx.x * blockDim.x + threadIdx.x;
    if (i < n) d[i] = __float2half(s[i]);
}
__global__ void decompose_h(const float* __restrict__ s,
                            __half* __restrict__ h, __half* __restrict__ l, int n) {
    int i = blockIdx.x * blockDim.x + threadIdx.x;
    if (i >= n) return;
    float f = s[i];
    __half hh = __float2half(f);
    h[i] = hh;
    l[i] = __float2half(f - __half2float(hh));
}

// ---------------------------------------------------------------------------
// HMMA fp16 2-term split GEMM core (NT), CTA 128x256, BK=32, 3-stage.
// ---------------------------------------------------------------------------
#define BM 128
#define BN 256
#define STG_A_BYTES (128*64)
#define STG_B_BYTES (256*128)
#define STG_BYTES (STG_A_BYTES + STG_B_BYTES)
#define GK_SMEM (3*STG_BYTES + 128)

__device__ __forceinline__ void gemm_core(
    const __half* __restrict__ A,
    const __half* __restrict__ Bh, const __half* __restrict__ Bl,
    float* __restrict__ C, int bm, int bn, int N, int K) {
    uint32_t sm0 = (smem_u32(dyn_smem) + 127) & ~127u;

    int t = threadIdx.x;
    int wid = t >> 5, lane = t & 31;
    int wm = (wid >> 2) * 64;
    int wn = (wid & 3) * 64;

    float acc[4][8][4];
#pragma unroll
    for (int a = 0; a < 4; a++)
#pragma unroll
        for (int b = 0; b < 8; b++)
#pragma unroll
            for (int c = 0; c < 4; c++) acc[a][b][c] = 0.f;

    auto load_stage = [&](int s, int ck) {
        int k0 = ck * 32;
        uint32_t sb = sm0 + s * STG_BYTES;
#pragma unroll
        for (int i = 0; i < 2; i++) {
            int idx = i * 256 + t;
            int r = idx >> 2, c = idx & 3;
            cp16(sb + r * 64 + (((c + (r >> 1)) & 3) * 16),
                 A + (size_t)(bm + r) * K + k0 + c * 8);
        }
        uint32_t sbB = sb + STG_A_BYTES;
#pragma unroll
        for (int i = 0; i < 8; i++) {
            int idx = i * 256 + t;
            int r = idx >> 3, c = idx & 7;
            const __half* src = ((c < 4) ? Bh : Bl)
                + (size_t)(bn + r) * K + k0 + (c & 3) * 8;
            cp16(sbB + r * 128 + ((c ^ (r & 7)) * 16), src);
        }
        cp_commit();
    };

    const int NCH = K >> 5;
    load_stage(0, 0);
    load_stage(1, 1);

    int laneR = lane & 15, laneH = lane >> 4;
    uint32_t aOff[4]; int aRot[4];
    uint32_t bBase[4];
#pragma unroll
    for (int mi = 0; mi < 4; mi++) {
        int r = wm + mi * 16 + laneR;
        aOff[mi] = sm0 + r * 64;
        aRot[mi] = r >> 1;
    }
#pragma unroll
    for (int nb = 0; nb < 4; nb++) {
        int r = wn + nb * 16 + laneR;
        bBase[nb] = sm0 + STG_A_BYTES + r * 128 + ((laneH ^ (r & 7)) * 16);
    }

    for (int ch = 0; ch < NCH; ch++) {
        if (ch + 2 < NCH) {
            load_stage((ch + 2) % 3, ch + 2);
            asm volatile("cp.async.wait_group 2;\n" ::: "memory");
        } else if (ch + 1 < NCH) {
            asm volatile("cp.async.wait_group 1;\n" ::: "memory");
        } else {
            asm volatile("cp.async.wait_group 0;\n" ::: "memory");
        }
        __syncthreads();

        uint32_t soff = (uint32_t)(ch % 3) * STG_BYTES;
#pragma unroll
        for (int kk = 0; kk < 2; kk++) {
            uint32_t kx = kk * 32;
            int kc = kk * 2 + laneH;
            uint32_t ah[4][4];
#pragma unroll
            for (int mi = 0; mi < 4; mi++) {
                uint32_t a0 = aOff[mi] + soff + (((kc + aRot[mi]) & 3) * 16);
                ldm_x4(ah[mi], a0);
            }
#pragma unroll
            for (int half = 0; half < 2; half++) {
                uint32_t bh[2][4], bl[2][4];
#pragma unroll
                for (int j = 0; j < 2; j++) {
                    int nb = half * 2 + j;
                    uint32_t b0 = (bBase[nb] + soff) ^ kx;
                    ldm_x4(bh[j], b0);
                    ldm_x4(bl[j], b0 ^ 64);
                }
#pragma unroll
                for (int mi = 0; mi < 4; mi++)
#pragma unroll
                    for (int j = 0; j < 2; j++)
#pragma unroll
                        for (int sub = 0; sub < 2; sub++) {
                            int ni = half * 4 + j * 2 + sub;
                            uint32_t fh[2] = { bh[j][sub], bh[j][2 + sub] };
                            uint32_t fl[2] = { bl[j][sub], bl[j][2 + sub] };
                            mma16816(acc[mi][ni], ah[mi], fh);
                            mma16816(acc[mi][ni], ah[mi], fl);
                        }
            }
        }
        __syncthreads();
    }

    int row = lane >> 2;
    int col = (lane & 3) * 2;
#pragma unroll
    for (int mi = 0; mi < 4; mi++)
#pragma unroll
        for (int ni = 0; ni < 8; ni++) {
            float* c0 = C + (size_t)(bm + wm + mi * 16 + row) * N + bn + wn + ni * 8 + col;
            c0[0] = acc[mi][ni][0];
            c0[1] = acc[mi][ni][1];
            float* c1 = c0 + 8 * (size_t)N;
            c1[0] = acc[mi][ni][2];
            c1[1] = acc[mi][ni][3];
        }
}

// fused QKV: 24 N-tiles (16 Q, 4 K, 4 V), one launch
__global__ __launch_bounds__(256, 1)
void gemm_qkv(const __half* __restrict__ A,
              const __half* __restrict__ Wqh, const __half* __restrict__ Wql,
              const __half* __restrict__ Wkh, const __half* __restrict__ Wkl,
              const __half* __restrict__ Wvh, const __half* __restrict__ Wvl,
              float* __restrict__ pq, float* __restrict__ pk, float* __restrict__ pv) {
    int tx = blockIdx.x;
    const __half *Bh, *Bl; float* C; int N, bn;
    if (tx < 16)      { Bh = Wqh; Bl = Wql; C = pq; N = NH*HD;  bn = tx * 256; }
    else if (tx < 20) { Bh = Wkh; Bl = Wkl; C = pk; N = NKV*HD; bn = (tx - 16) * 256; }
    else              { Bh = Wvh; Bl = Wvl; C = pv; N = NKV*HD; bn = (tx - 20) * 256; }
    gemm_core(A, Bh, Bl, C, blockIdx.y * BM, bn, N, DMODEL);
}

__global__ __launch_bounds__(256, 1)
void gemm_mma(const __half* __restrict__ A,
              const __half* __restrict__ Bh, const __half* __restrict__ Bl,
              float* __restrict__ C, int M, int N, int K) {
    gemm_core(A, Bh, Bl, C, blockIdx.y * BM, blockIdx.x * BN, N, K);
}

// ---------------- RoPE table ------------------------------------------------
__global__ void rope_table(const int* __restrict__ pos) {
    int idx = blockIdx.x * blockDim.x + threadIdx.x;
    if (idx >= MROWS * 64) return;
    int i   = idx & 63;
    int row = idx >> 6;
    double inv = exp(-(double)(2 * i) / 128.0 * log(10000.0));
    double ang = (double)pos[row] * inv;
    g_cos[idx] = (float)cos(ang);
    g_sin[idx] = (float)sin(ang);
}

// ---------------- fused RoPE + fp16 hi/lo split (q and k in one pass) --------
__global__ void rope_split_qk() {
    int idx = blockIdx.x * blockDim.x + threadIdx.x;
    const int total = MROWS * (NH + NKV) * 64;
    if (idx >= total) return;
    int i    = idx & 63;
    int head = (idx >> 6) % (NH + NKV);
    int row  = idx / (64 * (NH + NKV));
    float c = g_cos[row * 64 + i];
    float s = g_sin[row * 64 + i];
    if (head < NH) {
        size_t o = (size_t)row * NH * HD + head * HD;
        float x1 = g_q[o + i], x2 = g_q[o + i + 64];
        float y1 = (x1 * c - x2 * s) * QSCALE;
        float y2 = (x2 * c + x1 * s) * QSCALE;
        __half h1 = __float2half(y1), h2 = __float2half(y2);
        g_qh[o + i] = h1;      g_ql[o + i]      = __float2half(y1 - __half2float(h1));
        g_qh[o + i + 64] = h2; g_ql[o + i + 64] = __float2half(y2 - __half2float(h2));
    } else {
        size_t o = (size_t)row * NKV * HD + (head - NH) * HD;
        float x1 = g_k[o + i], x2 = g_k[o + i + 64];
        float y1 = x1 * c - x2 * s;
        float y2 = x2 * c + x1 * s;
        __half h1 = __float2half(y1), h2 = __float2half(y2);
        g_kh[o + i] = h1;      g_kl[o + i]      = __float2half(y1 - __half2float(h1));
        g_kh[o + i + 64] = h2; g_kl[o + i + 64] = __float2half(y2 - __half2float(h2));
    }
}

// ---------------- V transpose + split: g_v -> Vt[b][kvh][d][s] ---------------
__global__ __launch_bounds__(256) void split_vt() {
    __shared__ float sv[64][129];
    int blk = blockIdx.x;
    int st  = blk & 31;
    int kvh = (blk >> 5) & 7;
    int b   = blk >> 8;
    int tid = threadIdx.x;
#pragma unroll
    for (int it = 0; it < 32; it++) {
        int idx = it * 256 + tid;
        int r = idx >> 7, c = idx & 127;
        sv[r][c] = g_v[(size_t)(b * SS + st * 64 + r) * (NKV * HD) + kvh * HD + c];
    }
    __syncthreads();
    int d = tid >> 1, j = tid & 1;
    __half hbuf[32], lbuf[32];
#pragma unroll
    for (int q = 0; q < 32; q++) {
        float f = sv[j * 32 + q][d];
        __half hh = __float2half(f);
        hbuf[q] = hh;
        lbuf[q] = __float2half(f - __half2float(hh));
    }
    size_t base = ((size_t)(b * NKV + kvh) * HD + d) * SS + st * 64 + j * 32;
    uint4* dh = (uint4*)(g_vth + base);
    uint4* dl = (uint4*)(g_vtl + base);
#pragma unroll
    for (int q = 0; q < 4; q++) {
        dh[q] = ((uint4*)hbuf)[q];
        dl[q] = ((uint4*)lbuf)[q];
    }
}

// ---------------------------------------------------------------------------
// HMMA flash attention: fp16 split QK (3-term) and PV (3-term), fp32 softmax.
// Writes fp16 output directly (Wo GEMM A-operand precision == old tofp16 pass).
// ---------------------------------------------------------------------------
#define SQH 0
#define SQL 16384
#define SKH 32768
#define SKL 49152
#define SVH 65536
#define SVL 81920
#define FL_SMEM 98304

__global__ __launch_bounds__(128) void flash_mma(
    const __half* __restrict__ Qh_g, const __half* __restrict__ Ql_g,
    const __half* __restrict__ Kh_g, const __half* __restrict__ Kl_g,
    const __half* __restrict__ Vth_g, const __half* __restrict__ Vtl_g,
    __half* __restrict__ out) {
    uint32_t s0 = smem_u32(dyn_smem);

    int qt = blockIdx.x, h = blockIdx.y, b = blockIdx.z;
    int kvh = h >> 2;
    int t = threadIdx.x, wid = t >> 5, lane = t & 31;
    int laneR = lane & 15, laneH = lane >> 4;
    int wm = wid * 16;

#pragma unroll
    for (int i = 0; i < 8; i++) {
        int idx = i * 128 + t;
        int r = idx >> 4, c = idx & 15;
        uint32_t d = r * 256 + ((c ^ (r & 7)) * 16);
        size_t g = ((size_t)(b * SS + qt * 64 + r)) * (NH * HD) + h * HD + c * 8;
        cp16(s0 + SQH + d, Qh_g + g);
        cp16(s0 + SQL + d, Ql_g + g);
    }
    auto loadKV = [&](int kt) {
#pragma unroll
        for (int i = 0; i < 8; i++) {
            int idx = i * 128 + t;
            int r = idx >> 4, c = idx & 15;
            uint32_t d = r * 256 + ((c ^ (r & 7)) * 16);
            size_t g = ((size_t)(b * SS + kt * 64 + r)) * (NKV * HD) + kvh * HD + c * 8;
            cp16(s0 + SKH + d, Kh_g + g);
            cp16(s0 + SKL + d, Kl_g + g);
        }
#pragma unroll
        for (int i = 0; i < 8; i++) {
            int idx = i * 128 + t;
            int r = idx >> 3, c = idx & 7;
            uint32_t d = r * 128 + ((c ^ (r & 7)) * 16);
            size_t g = ((size_t)((b * NKV + kvh) * HD + r)) * SS + kt * 64 + c * 8;
            cp16(s0 + SVH + d, Vth_g + g);
            cp16(s0 + SVL + d, Vtl_g + g);
        }
    };
    loadKV(0);
    cp_commit();

    float o_[16][4];
#pragma unroll
    for (int n = 0; n < 16; n++)
#pragma unroll
        for (int c = 0; c < 4; c++) o_[n][c] = 0.f;
    float m0 = -1e30f, m1 = -1e30f, l0 = 0.f, l1 = 0.f;
    int r0 = lane >> 2;
    int qrow0 = qt * 64 + wm + r0;
    int qrow1 = qrow0 + 8;

    for (int kt = 0; kt <= qt; kt++) {
        asm volatile("cp.async.wait_group 0;\n" ::: "memory");
        __syncthreads();

        float s[8][4];
#pragma unroll
        for (int j = 0; j < 8; j++)
#pragma unroll
            for (int c = 0; c < 4; c++) s[j][c] = 0.f;

#pragma unroll
        for (int kk = 0; kk < 8; kk++) {
            uint32_t qa[4], qb[4];
            {
                int r = wm + laneR;
                uint32_t ph = (uint32_t)(((kk * 2 + laneH) ^ (r & 7)) * 16);
                ldm_x4(qa, s0 + SQH + r * 256 + ph);
                ldm_x4(qb, s0 + SQL + r * 256 + ph);
            }
#pragma unroll
            for (int jj = 0; jj < 4; jj++) {
                uint32_t kh_[4], kl_[4];
                int r = jj * 16 + laneR;
                uint32_t ph = (uint32_t)(((kk * 2 + laneH) ^ (r & 7)) * 16);
                ldm_x4(kh_, s0 + SKH + r * 256 + ph);
                ldm_x4(kl_, s0 + SKL + r * 256 + ph);
#pragma unroll
                for (int sub = 0; sub < 2; sub++) {
                    int j = jj * 2 + sub;
                    uint32_t fh[2] = { kh_[sub], kh_[2 + sub] };
                    uint32_t fl[2] = { kl_[sub], kl_[2 + sub] };
                    mma16816(s[j], qa, fh);
                    mma16816(s[j], qa, fl);
                    mma16816(s[j], qb, fh);
                }
            }
        }

        if (kt == qt) {
#pragma unroll
            for (int j = 0; j < 8; j++) {
                int cb = kt * 64 + j * 8 + (lane & 3) * 2;
                if (cb     > qrow0) s[j][0] = -1e30f;
                if (cb + 1 > qrow0) s[j][1] = -1e30f;
                if (cb     > qrow1) s[j][2] = -1e30f;
                if (cb + 1 > qrow1) s[j][3] = -1e30f;
            }
        }

        float rm0 = -1e30f, rm1 = -1e30f;
#pragma unroll
        for (int j = 0; j < 8; j++) {
            rm0 = fmaxf(rm0, fmaxf(s[j][0], s[j][1]));
            rm1 = fmaxf(rm1, fmaxf(s[j][2], s[j][3]));
        }
        rm0 = fmaxf(rm0, __shfl_xor_sync(0xffffffffu, rm0, 1));
        rm0 = fmaxf(rm0, __shfl_xor_sync(0xffffffffu, rm0, 2));
        rm1 = fmaxf(rm1, __shfl_xor_sync(0xffffffffu, rm1, 1));
        rm1 = fmaxf(rm1, __shfl_xor_sync(0xffffffffu, rm1, 2));
        float mn0 = fmaxf(m0, rm0), mn1 = fmaxf(m1, rm1);
        float a0 = __expf(m0 - mn0), a1 = __expf(m1 - mn1);
        l0 *= a0; l1 *= a1;
#pragma unroll
        for (int n = 0; n < 16; n++) {
            o_[n][0] *= a0; o_[n][1] *= a0;
            o_[n][2] *= a1; o_[n][3] *= a1;
        }
        m0 = mn0; m1 = mn1;

        uint32_t ph0[8], ph1[8], pl0[8], pl1[8];
        float sum0 = 0.f, sum1 = 0.f;
#pragma unroll
        for (int j = 0; j < 8; j++) {
            float e0 = __expf(s[j][0] - mn0), e1 = __expf(s[j][1] - mn0);
            float e2 = __expf(s[j][2] - mn1), e3 = __expf(s[j][3] - mn1);
            sum0 += e0 + e1; sum1 += e2 + e3;
            __half2 hh0 = __floats2half2_rn(e0, e1);
            __half2 hh1 = __floats2half2_rn(e2, e3);
            ph0[j] = *(uint32_t*)&hh0;
            ph1[j] = *(uint32_t*)&hh1;
            __half2 dd0 = __floats2half2_rn(e0 - __low2float(hh0), e1 - __high2float(hh0));
            __half2 dd1 = __floats2half2_rn(e2 - __low2float(hh1), e3 - __high2float(hh1));
            pl0[j] = *(uint32_t*)&dd0;
            pl1[j] = *(uint32_t*)&dd1;
        }
        sum0 += __shfl_xor_sync(0xffffffffu, sum0, 1);
        sum0 += __shfl_xor_sync(0xffffffffu, sum0, 2);
        sum1 += __shfl_xor_sync(0xffffffffu, sum1, 1);
        sum1 += __shfl_xor_sync(0xffffffffu, sum1, 2);
        l0 += sum0; l1 += sum1;

#pragma unroll
        for (int tt = 0; tt < 4; tt++) {
            uint32_t pa[4] = { ph0[2*tt], ph1[2*tt], ph0[2*tt+1], ph1[2*tt+1] };
            uint32_t pb[4] = { pl0[2*tt], pl1[2*tt], pl0[2*tt+1], pl1[2*tt+1] };
#pragma unroll
            for (int dg = 0; dg < 8; dg++) {
                uint32_t vh_[4], vl_[4];
                int r = dg * 16 + laneR;
                uint32_t ph = (uint32_t)(((tt * 2 + laneH) ^ (r & 7)) * 16);
                ldm_x4(vh_, s0 + SVH + r * 128 + ph);
                ldm_x4(vl_, s0 + SVL + r * 128 + ph);
#pragma unroll
                for (int sub = 0; sub < 2; sub++) {
                    int n = dg * 2 + sub;
                    uint32_t fh[2] = { vh_[sub], vh_[2 + sub] };
                    uint32_t fl[2] = { vl_[sub], vl_[2 + sub] };
                    mma16816(o_[n], pa, fh);
                    mma16816(o_[n], pa, fl);
                    mma16816(o_[n], pb, fh);
                }
            }
        }

        __syncthreads();
        if (kt + 1 <= qt) {
            loadKV(kt + 1);
            cp_commit();
        }
    }

    float il0 = 1.f / l0, il1 = 1.f / l1;
    size_t ob0 = (size_t)(b * SS + qrow0) * (NH * HD) + h * HD + (lane & 3) * 2;
    size_t ob1 = (size_t)(b * SS + qrow1) * (NH * HD) + h * HD + (lane & 3) * 2;
#pragma unroll
    for (int n = 0; n < 16; n++) {
        __half2 w0 = __floats2half2_rn(o_[n][0] * il0, o_[n][1] * il0);
        __half2 w1 = __floats2half2_rn(o_[n][2] * il1, o_[n][3] * il1);
        *(__half2*)(out + ob0 + n * 8) = w0;
        *(__half2*)(out + ob1 + n * 8) = w1;
    }
}

// ---------------------------------------------------------------------------
extern "C" void kernel_launch(void* const* d_in, const int* in_sizes, int n_in,
                              void* d_out, int out_size) {
    const float* hid = (const float*)d_in[0];
    const int*   pos = (const int*)d_in[1];
    const float* Wq  = (const float*)d_in[2];
    const float* Wk  = (const float*)d_in[3];
    const float* Wv  = (const float*)d_in[4];
    const float* Wo  = (const float*)d_in[5];
    float* out = (float*)d_out;

    float *pq, *pk, *pv;
    cudaGetSymbolAddress((void**)&pq, g_q);
    cudaGetSymbolAddress((void**)&pk, g_k);
    cudaGetSymbolAddress((void**)&pv, g_v);
    __half *hf, *af, *qh, *ql, *kh, *kl, *vh, *vl, *oh, *ol;
    __half *fqh, *fql, *fkh, *fkl, *fvh, *fvl;
    cudaGetSymbolAddress((void**)&hf, g_hid_f16);
    cudaGetSymbolAddress((void**)&af, g_at_f16);
    cudaGetSymbolAddress((void**)&qh, g_wq_h);  cudaGetSymbolAddress((void**)&ql, g_wq_l);
    cudaGetSymbolAddress((void**)&kh, g_wk_h);  cudaGetSymbolAddress((void**)&kl, g_wk_l);
    cudaGetSymbolAddress((void**)&vh, g_wv_h);  cudaGetSymbolAddress((void**)&vl, g_wv_l);
    cudaGetSymbolAddress((void**)&oh, g_wo_h);  cudaGetSymbolAddress((void**)&ol, g_wo_l);
    cudaGetSymbolAddress((void**)&fqh, g_qh);   cudaGetSymbolAddress((void**)&fql, g_ql);
    cudaGetSymbolAddress((void**)&fkh, g_kh);   cudaGetSymbolAddress((void**)&fkl, g_kl);
    cudaGetSymbolAddress((void**)&fvh, g_vth);  cudaGetSymbolAddress((void**)&fvl, g_vtl);

    const int nHid = MROWS * DMODEL;
    const int nWq  = NH * HD * DMODEL;
    const int nWk  = NKV * HD * DMODEL;
    tofp16<<<(nHid + 255) / 256, 256>>>(hid, hf, nHid);
    decompose_h<<<(nWq + 255) / 256, 256>>>(Wq, qh, ql, nWq);
    decompose_h<<<(nWk + 255) / 256, 256>>>(Wk, kh, kl, nWk);
    decompose_h<<<(nWk + 255) / 256, 256>>>(Wv, vh, vl, nWk);
    decompose_h<<<(nWq + 255) / 256, 256>>>(Wo, oh, ol, nWq);
    rope_table<<<(MROWS*64 + 255)/256, 256>>>(pos);

    cudaFuncSetAttribute(gemm_qkv, cudaFuncAttributeMaxDynamicSharedMemorySize, GK_SMEM);
    cudaFuncSetAttribute(gemm_mma, cudaFuncAttributeMaxDynamicSharedMemorySize, GK_SMEM);

    gemm_qkv<<<dim3(24, MROWS/BM), 256, GK_SMEM>>>(hf, qh, ql, kh, kl, vh, vl, pq, pk, pv);

    rope_split_qk<<<(MROWS*(NH+NKV)*64 + 255)/256, 256>>>();
    split_vt<<<BB*NKV*32, 256>>>();

    cudaFuncSetAttribute(flash_mma, cudaFuncAttributeMaxDynamicSharedMemorySize, FL_SMEM);
    flash_mma<<<dim3(SS/64, NH, BB), 128, FL_SMEM>>>(fqh, fql, fkh, fkl, fvh, fvl, af);

    gemm_mma<<<dim3(NH*HD/BN, MROWS/BM), 256, GK_SMEM>>>(af, oh, ol, out, MROWS, NH*HD, NH*HD);
}

// round 10
// speedup vs baseline: 8.2104x; 1.0270x over previous
#include <cuda_runtime.h>
#include <cuda_fp16.h>
#include <math.h>
#include <stdint.h>

#define BB 2
#define SS 2048
#define DMODEL 4096
#define NH 32
#define NKV 8
#define HD 128
#define MROWS (BB*SS)   // 4096
#define QSCALE 0.08838834764831845f

extern __shared__ char dyn_smem[];

// ---------------- scratch (device globals; no allocation allowed) ----------
__device__ float g_q[(size_t)MROWS * NH * HD];
__device__ float g_k[(size_t)MROWS * NKV * HD];
__device__ float g_v[(size_t)MROWS * NKV * HD];
__device__ float g_cos[MROWS * (HD/2)];
__device__ float g_sin[MROWS * (HD/2)];

// fp16 operands
__device__ __half g_hid_f16[(size_t)MROWS * DMODEL];
__device__ __half g_at_f16[(size_t)MROWS * NH*HD];
__device__ __half g_wq_h[(size_t)NH*HD * DMODEL];
__device__ __half g_wq_l[(size_t)NH*HD * DMODEL];
__device__ __half g_wk_h[(size_t)NKV*HD * DMODEL];
__device__ __half g_wk_l[(size_t)NKV*HD * DMODEL];
__device__ __half g_wv_h[(size_t)NKV*HD * DMODEL];
__device__ __half g_wv_l[(size_t)NKV*HD * DMODEL];
__device__ __half g_wo_h[(size_t)NH*HD * NH*HD];
__device__ __half g_wo_l[(size_t)NH*HD * NH*HD];

// fp16 attention operands (post-rope, split)
__device__ __half g_qh[(size_t)MROWS * NH * HD];
__device__ __half g_ql[(size_t)MROWS * NH * HD];
__device__ __half g_kh[(size_t)MROWS * NKV * HD];
__device__ __half g_kl[(size_t)MROWS * NKV * HD];
__device__ __half g_vth[(size_t)BB * NKV * HD * SS];  // [b][kvh][d][s]
__device__ __half g_vtl[(size_t)BB * NKV * HD * SS];

// ---------------- PTX helpers (sm_80+ base-target safe) ---------------------
__device__ __forceinline__ uint32_t smem_u32(const void* p) {
    uint32_t a;
    asm("{ .reg .u64 t; cvta.to.shared.u64 t, %1; cvt.u32.u64 %0, t; }" : "=r"(a) : "l"(p));
    return a;
}
__device__ __forceinline__ void cp16(uint32_t dst, const void* src) {
    asm volatile("cp.async.cg.shared.global [%0], [%1], 16;\n" :: "r"(dst), "l"(src));
}
__device__ __forceinline__ void cp_commit() { asm volatile("cp.async.commit_group;\n" ::: "memory"); }

__device__ __forceinline__ void ldm_x4(uint32_t* r, uint32_t addr) {
    asm volatile("ldmatrix.sync.aligned.m8n8.x4.shared.b16 {%0,%1,%2,%3}, [%4];"
        : "=r"(r[0]), "=r"(r[1]), "=r"(r[2]), "=r"(r[3]) : "r"(addr));
}
__device__ __forceinline__ void mma16816(float* d, const uint32_t* a, const uint32_t* b) {
    asm volatile("mma.sync.aligned.m16n8k16.row.col.f32.f16.f16.f32 "
        "{%0,%1,%2,%3}, {%4,%5,%6,%7}, {%8,%9}, {%0,%1,%2,%3};"
        : "+f"(d[0]), "+f"(d[1]), "+f"(d[2]), "+f"(d[3])
        : "r"(a[0]), "r"(a[1]), "r"(a[2]), "r"(a[3]), "r"(b[0]), "r"(b[1]));
}

// ---------------- conversion kernels ----------------------------------------
__global__ void tofp16(const float* __restrict__ s, __half* __restrict__ d, int n) {
    int i = blockIdx.x * blockDim.x + threadIdx.x;
    if (i < n) d[i] = __float2half(s[i]);
}
__global__ void decompose_h(const float* __restrict__ s,
                            __half* __restrict__ h, __half* __restrict__ l, int n) {
    int i = blockIdx.x * blockDim.x + threadIdx.x;
    if (i >= n) return;
    float f = s[i];
    __half hh = __float2half(f);
    h[i] = hh;
    l[i] = __float2half(f - __half2float(hh));
}

// ---------------------------------------------------------------------------
// HMMA fp16 2-term split GEMM core (NT). CTA 128x128, 8 warps (2x4, warp
// tile 64x32), BK=32, 3-stage cp.async, 2 CTAs/SM (16 warps = 4/SMSP).
// ---------------------------------------------------------------------------
#define BM 128
#define BN 128
#define STG_A_BYTES (128*64)                   // 8192
#define STG_B_BYTES (128*128)                  // 16384 (hi|lo packed rows)
#define STG_BYTES (STG_A_BYTES + STG_B_BYTES)  // 24576
#define GK_SMEM (3*STG_BYTES + 128)            // 73856

__device__ __forceinline__ void gemm_core(
    const __half* __restrict__ A,
    const __half* __restrict__ Bh, const __half* __restrict__ Bl,
    float* __restrict__ C, int bm, int bn, int N, int K) {
    uint32_t sm0 = (smem_u32(dyn_smem) + 127) & ~127u;

    int t = threadIdx.x;
    int wid = t >> 5, lane = t & 31;
    int wm = (wid >> 2) * 64;   // 0 or 64
    int wn = (wid & 3) * 32;    // 0,32,64,96

    float acc[4][4][4];
#pragma unroll
    for (int a = 0; a < 4; a++)
#pragma unroll
        for (int b = 0; b < 4; b++)
#pragma unroll
            for (int c = 0; c < 4; c++) acc[a][b][c] = 0.f;

    auto load_stage = [&](int s, int ck) {
        int k0 = ck * 32;
        uint32_t sb = sm0 + s * STG_BYTES;
#pragma unroll
        for (int i = 0; i < 2; i++) {           // A: 128 rows x 4 chunks
            int idx = i * 256 + t;
            int r = idx >> 2, c = idx & 3;
            cp16(sb + r * 64 + (((c + (r >> 1)) & 3) * 16),
                 A + (size_t)(bm + r) * K + k0 + c * 8);
        }
        uint32_t sbB = sb + STG_A_BYTES;
#pragma unroll
        for (int i = 0; i < 4; i++) {           // B: 128 rows x 8 chunks (hi|lo)
            int idx = i * 256 + t;
            int r = idx >> 3, c = idx & 7;
            const __half* src = ((c < 4) ? Bh : Bl)
                + (size_t)(bn + r) * K + k0 + (c & 3) * 8;
            cp16(sbB + r * 128 + ((c ^ (r & 7)) * 16), src);
        }
        cp_commit();
    };

    const int NCH = K >> 5;
    load_stage(0, 0);
    load_stage(1, 1);

    int laneR = lane & 15, laneH = lane >> 4;
    uint32_t aOff[4]; int aRot[4];
    uint32_t bBase[2];
#pragma unroll
    for (int mi = 0; mi < 4; mi++) {
        int r = wm + mi * 16 + laneR;
        aOff[mi] = sm0 + r * 64;
        aRot[mi] = r >> 1;
    }
#pragma unroll
    for (int nb = 0; nb < 2; nb++) {
        int r = wn + nb * 16 + laneR;
        bBase[nb] = sm0 + STG_A_BYTES + r * 128 + ((laneH ^ (r & 7)) * 16);
    }

    for (int ch = 0; ch < NCH; ch++) {
        if (ch + 2 < NCH) {
            load_stage((ch + 2) % 3, ch + 2);
            asm volatile("cp.async.wait_group 2;\n" ::: "memory");
        } else if (ch + 1 < NCH) {
            asm volatile("cp.async.wait_group 1;\n" ::: "memory");
        } else {
            asm volatile("cp.async.wait_group 0;\n" ::: "memory");
        }
        __syncthreads();

        uint32_t soff = (uint32_t)(ch % 3) * STG_BYTES;
#pragma unroll
        for (int kk = 0; kk < 2; kk++) {
            uint32_t kx = kk * 32;
            int kc = kk * 2 + laneH;
            uint32_t ah[4][4];
#pragma unroll
            for (int mi = 0; mi < 4; mi++) {
                uint32_t a0 = aOff[mi] + soff + (((kc + aRot[mi]) & 3) * 16);
                ldm_x4(ah[mi], a0);
            }
#pragma unroll
            for (int nb = 0; nb < 2; nb++) {
                uint32_t bh[4], bl[4];
                uint32_t b0 = (bBase[nb] + soff) ^ kx;
                ldm_x4(bh, b0);
                ldm_x4(bl, b0 ^ 64);
#pragma unroll
                for (int mi = 0; mi < 4; mi++)
#pragma unroll
                    for (int sub = 0; sub < 2; sub++) {
                        int ni = nb * 2 + sub;
                        uint32_t fh[2] = { bh[sub], bh[2 + sub] };
                        uint32_t fl[2] = { bl[sub], bl[2 + sub] };
                        mma16816(acc[mi][ni], ah[mi], fh);
                        mma16816(acc[mi][ni], ah[mi], fl);
                    }
            }
        }
        __syncthreads();
    }

    int row = lane >> 2;
    int col = (lane & 3) * 2;
#pragma unroll
    for (int mi = 0; mi < 4; mi++)
#pragma unroll
        for (int ni = 0; ni < 4; ni++) {
            float* c0 = C + (size_t)(bm + wm + mi * 16 + row) * N + bn + wn + ni * 8 + col;
            c0[0] = acc[mi][ni][0];
            c0[1] = acc[mi][ni][1];
            float* c1 = c0 + 8 * (size_t)N;
            c1[0] = acc[mi][ni][2];
            c1[1] = acc[mi][ni][3];
        }
}

// fused QKV: 48 N-tiles (32 Q, 8 K, 8 V), one launch
__global__ __launch_bounds__(256, 2)
void gemm_qkv(const __half* __restrict__ A,
              const __half* __restrict__ Wqh, const __half* __restrict__ Wql,
              const __half* __restrict__ Wkh, const __half* __restrict__ Wkl,
              const __half* __restrict__ Wvh, const __half* __restrict__ Wvl,
              float* __restrict__ pq, float* __restrict__ pk, float* __restrict__ pv) {
    int tx = blockIdx.x;
    const __half *Bh, *Bl; float* C; int N, bn;
    if (tx < 32)      { Bh = Wqh; Bl = Wql; C = pq; N = NH*HD;  bn = tx * 128; }
    else if (tx < 40) { Bh = Wkh; Bl = Wkl; C = pk; N = NKV*HD; bn = (tx - 32) * 128; }
    else              { Bh = Wvh; Bl = Wvl; C = pv; N = NKV*HD; bn = (tx - 40) * 128; }
    gemm_core(A, Bh, Bl, C, blockIdx.y * BM, bn, N, DMODEL);
}

__global__ __launch_bounds__(256, 2)
void gemm_mma(const __half* __restrict__ A,
              const __half* __restrict__ Bh, const __half* __restrict__ Bl,
              float* __restrict__ C, int M, int N, int K) {
    gemm_core(A, Bh, Bl, C, blockIdx.y * BM, blockIdx.x * BN, N, K);
}

// ---------------- RoPE table ------------------------------------------------
__global__ void rope_table(const int* __restrict__ pos) {
    int idx = blockIdx.x * blockDim.x + threadIdx.x;
    if (idx >= MROWS * 64) return;
    int i   = idx & 63;
    int row = idx >> 6;
    double inv = exp(-(double)(2 * i) / 128.0 * log(10000.0));
    double ang = (double)pos[row] * inv;
    g_cos[idx] = (float)cos(ang);
    g_sin[idx] = (float)sin(ang);
}

// ---------------- fused RoPE + fp16 hi/lo split (q and k in one pass) --------
__global__ void rope_split_qk() {
    int idx = blockIdx.x * blockDim.x + threadIdx.x;
    const int total = MROWS * (NH + NKV) * 64;
    if (idx >= total) return;
    int i    = idx & 63;
    int head = (idx >> 6) % (NH + NKV);
    int row  = idx / (64 * (NH + NKV));
    float c = g_cos[row * 64 + i];
    float s = g_sin[row * 64 + i];
    if (head < NH) {
        size_t o = (size_t)row * NH * HD + head * HD;
        float x1 = g_q[o + i], x2 = g_q[o + i + 64];
        float y1 = (x1 * c - x2 * s) * QSCALE;
        float y2 = (x2 * c + x1 * s) * QSCALE;
        __half h1 = __float2half(y1), h2 = __float2half(y2);
        g_qh[o + i] = h1;      g_ql[o + i]      = __float2half(y1 - __half2float(h1));
        g_qh[o + i + 64] = h2; g_ql[o + i + 64] = __float2half(y2 - __half2float(h2));
    } else {
        size_t o = (size_t)row * NKV * HD + (head - NH) * HD;
        float x1 = g_k[o + i], x2 = g_k[o + i + 64];
        float y1 = x1 * c - x2 * s;
        float y2 = x2 * c + x1 * s;
        __half h1 = __float2half(y1), h2 = __float2half(y2);
        g_kh[o + i] = h1;      g_kl[o + i]      = __float2half(y1 - __half2float(h1));
        g_kh[o + i + 64] = h2; g_kl[o + i + 64] = __float2half(y2 - __half2float(h2));
    }
}

// ---------------- V transpose + split: g_v -> Vt[b][kvh][d][s] ---------------
__global__ __launch_bounds__(256) void split_vt() {
    __shared__ float sv[64][129];
    int blk = blockIdx.x;
    int st  = blk & 31;
    int kvh = (blk >> 5) & 7;
    int b   = blk >> 8;
    int tid = threadIdx.x;
#pragma unroll
    for (int it = 0; it < 32; it++) {
        int idx = it * 256 + tid;
        int r = idx >> 7, c = idx & 127;
        sv[r][c] = g_v[(size_t)(b * SS + st * 64 + r) * (NKV * HD) + kvh * HD + c];
    }
    __syncthreads();
    int d = tid >> 1, j = tid & 1;
    __half hbuf[32], lbuf[32];
#pragma unroll
    for (int q = 0; q < 32; q++) {
        float f = sv[j * 32 + q][d];
        __half hh = __float2half(f);
        hbuf[q] = hh;
        lbuf[q] = __float2half(f - __half2float(hh));
    }
    size_t base = ((size_t)(b * NKV + kvh) * HD + d) * SS + st * 64 + j * 32;
    uint4* dh = (uint4*)(g_vth + base);
    uint4* dl = (uint4*)(g_vtl + base);
#pragma unroll
    for (int q = 0; q < 4; q++) {
        dh[q] = ((uint4*)hbuf)[q];
        dl[q] = ((uint4*)lbuf)[q];
    }
}

// ---------------------------------------------------------------------------
// HMMA flash attention: Br=128 (8 warps, 256 thr), Bc=64, fp16 3-term splits.
// smem: Qh/Ql 128x256B, Kh/Kl 64x256B, Vth/Vtl 128x128B -> 128 KB total.
// ---------------------------------------------------------------------------
#define SQH 0
#define SQL 32768
#define SKH 65536
#define SKL 81920
#define SVH 98304
#define SVL 114688
#define FL_SMEM 131072

__global__ __launch_bounds__(256) void flash_mma(
    const __half* __restrict__ Qh_g, const __half* __restrict__ Ql_g,
    const __half* __restrict__ Kh_g, const __half* __restrict__ Kl_g,
    const __half* __restrict__ Vth_g, const __half* __restrict__ Vtl_g,
    __half* __restrict__ out) {
    uint32_t s0 = smem_u32(dyn_smem);

    int qt = blockIdx.x, h = blockIdx.y, b = blockIdx.z;
    int kvh = h >> 2;
    int t = threadIdx.x, wid = t >> 5, lane = t & 31;
    int laneR = lane & 15, laneH = lane >> 4;
    int wm = wid * 16;

    // Q tile: 128 rows x 16 chunks, hi+lo
#pragma unroll
    for (int i = 0; i < 8; i++) {
        int idx = i * 256 + t;
        int r = idx >> 4, c = idx & 15;
        uint32_t d = r * 256 + ((c ^ (r & 7)) * 16);
        size_t g = ((size_t)(b * SS + qt * 128 + r)) * (NH * HD) + h * HD + c * 8;
        cp16(s0 + SQH + d, Qh_g + g);
        cp16(s0 + SQL + d, Ql_g + g);
    }
    auto loadKV = [&](int kt) {
#pragma unroll
        for (int i = 0; i < 4; i++) {
            int idx = i * 256 + t;
            int r = idx >> 4, c = idx & 15;
            uint32_t d = r * 256 + ((c ^ (r & 7)) * 16);
            size_t g = ((size_t)(b * SS + kt * 64 + r)) * (NKV * HD) + kvh * HD + c * 8;
            cp16(s0 + SKH + d, Kh_g + g);
            cp16(s0 + SKL + d, Kl_g + g);
        }
#pragma unroll
        for (int i = 0; i < 4; i++) {
            int idx = i * 256 + t;
            int r = idx >> 3, c = idx & 7;
            uint32_t d = r * 128 + ((c ^ (r & 7)) * 16);
            size_t g = ((size_t)((b * NKV + kvh) * HD + r)) * SS + kt * 64 + c * 8;
            cp16(s0 + SVH + d, Vth_g + g);
            cp16(s0 + SVL + d, Vtl_g + g);
        }
    };
    loadKV(0);
    cp_commit();

    float o_[16][4];
#pragma unroll
    for (int n = 0; n < 16; n++)
#pragma unroll
        for (int c = 0; c < 4; c++) o_[n][c] = 0.f;
    float m0 = -1e30f, m1 = -1e30f, l0 = 0.f, l1 = 0.f;
    int r0 = lane >> 2;
    int qrow0 = qt * 128 + wm + r0;
    int qrow1 = qrow0 + 8;
    const int KTMAX = 2 * qt + 1;

    for (int kt = 0; kt <= KTMAX; kt++) {
        asm volatile("cp.async.wait_group 0;\n" ::: "memory");
        __syncthreads();

        float s[8][4];
#pragma unroll
        for (int j = 0; j < 8; j++)
#pragma unroll
            for (int c = 0; c < 4; c++) s[j][c] = 0.f;

#pragma unroll
        for (int kk = 0; kk < 8; kk++) {
            uint32_t qa[4], qb[4];
            {
                int r = wm + laneR;
                uint32_t ph = (uint32_t)(((kk * 2 + laneH) ^ (r & 7)) * 16);
                ldm_x4(qa, s0 + SQH + r * 256 + ph);
                ldm_x4(qb, s0 + SQL + r * 256 + ph);
            }
#pragma unroll
            for (int jj = 0; jj < 4; jj++) {
                uint32_t kh_[4], kl_[4];
                int r = jj * 16 + laneR;
                uint32_t ph = (uint32_t)(((kk * 2 + laneH) ^ (r & 7)) * 16);
                ldm_x4(kh_, s0 + SKH + r * 256 + ph);
                ldm_x4(kl_, s0 + SKL + r * 256 + ph);
#pragma unroll
                for (int sub = 0; sub < 2; sub++) {
                    int j = jj * 2 + sub;
                    uint32_t fh[2] = { kh_[sub], kh_[2 + sub] };
                    uint32_t fl[2] = { kl_[sub], kl_[2 + sub] };
                    mma16816(s[j], qa, fh);
                    mma16816(s[j], qa, fl);
                    mma16816(s[j], qb, fh);
                }
            }
        }

        // causal mask for tiles crossing the diagonal of this warp's rows
        if (kt * 64 + 63 > qrow0) {
#pragma unroll
            for (int j = 0; j < 8; j++) {
                int cb = kt * 64 + j * 8 + (lane & 3) * 2;
                if (cb     > qrow0) s[j][0] = -1e30f;
                if (cb + 1 > qrow0) s[j][1] = -1e30f;
                if (cb     > qrow1) s[j][2] = -1e30f;
                if (cb + 1 > qrow1) s[j][3] = -1e30f;
            }
        }

        float rm0 = -1e30f, rm1 = -1e30f;
#pragma unroll
        for (int j = 0; j < 8; j++) {
            rm0 = fmaxf(rm0, fmaxf(s[j][0], s[j][1]));
            rm1 = fmaxf(rm1, fmaxf(s[j][2], s[j][3]));
        }
        rm0 = fmaxf(rm0, __shfl_xor_sync(0xffffffffu, rm0, 1));
        rm0 = fmaxf(rm0, __shfl_xor_sync(0xffffffffu, rm0, 2));
        rm1 = fmaxf(rm1, __shfl_xor_sync(0xffffffffu, rm1, 1));
        rm1 = fmaxf(rm1, __shfl_xor_sync(0xffffffffu, rm1, 2));
        float mn0 = fmaxf(m0, rm0), mn1 = fmaxf(m1, rm1);
        float a0 = __expf(m0 - mn0), a1 = __expf(m1 - mn1);
        l0 *= a0; l1 *= a1;
#pragma unroll
        for (int n = 0; n < 16; n++) {
            o_[n][0] *= a0; o_[n][1] *= a0;
            o_[n][2] *= a1; o_[n][3] *= a1;
        }
        m0 = mn0; m1 = mn1;

        uint32_t ph0[8], ph1[8], pl0[8], pl1[8];
        float sum0 = 0.f, sum1 = 0.f;
#pragma unroll
        for (int j = 0; j < 8; j++) {
            float e0 = __expf(s[j][0] - mn0), e1 = __expf(s[j][1] - mn0);
            float e2 = __expf(s[j][2] - mn1), e3 = __expf(s[j][3] - mn1);
            sum0 += e0 + e1; sum1 += e2 + e3;
            __half2 hh0 = __floats2half2_rn(e0, e1);
            __half2 hh1 = __floats2half2_rn(e2, e3);
            ph0[j] = *(uint32_t*)&hh0;
            ph1[j] = *(uint32_t*)&hh1;
            __half2 dd0 = __floats2half2_rn(e0 - __low2float(hh0), e1 - __high2float(hh0));
            __half2 dd1 = __floats2half2_rn(e2 - __low2float(hh1), e3 - __high2float(hh1));
            pl0[j] = *(uint32_t*)&dd0;
            pl1[j] = *(uint32_t*)&dd1;
        }
        sum0 += __shfl_xor_sync(0xffffffffu, sum0, 1);
        sum0 += __shfl_xor_sync(0xffffffffu, sum0, 2);
        sum1 += __shfl_xor_sync(0xffffffffu, sum1, 1);
        sum1 += __shfl_xor_sync(0xffffffffu, sum1, 2);
        l0 += sum0; l1 += sum1;

#pragma unroll
        for (int tt = 0; tt < 4; tt++) {
            uint32_t pa[4] = { ph0[2*tt], ph1[2*tt], ph0[2*tt+1], ph1[2*tt+1] };
            uint32_t pb[4] = { pl0[2*tt], pl1[2*tt], pl0[2*tt+1], pl1[2*tt+1] };
#pragma unroll
            for (int dg = 0; dg < 8; dg++) {
                uint32_t vh_[4], vl_[4];
                int r = dg * 16 + laneR;
                uint32_t ph = (uint32_t)(((tt * 2 + laneH) ^ (r & 7)) * 16);
                ldm_x4(vh_, s0 + SVH + r * 128 + ph);
                ldm_x4(vl_, s0 + SVL + r * 128 + ph);
#pragma unroll
                for (int sub = 0; sub < 2; sub++) {
                    int n = dg * 2 + sub;
                    uint32_t fh[2] = { vh_[sub], vh_[2 + sub] };
                    uint32_t fl[2] = { vl_[sub], vl_[2 + sub] };
                    mma16816(o_[n], pa, fh);
                    mma16816(o_[n], pa, fl);
                    mma16816(o_[n], pb, fh);
                }
            }
        }

        __syncthreads();
        if (kt + 1 <= KTMAX) {
            loadKV(kt + 1);
            cp_commit();
        }
    }

    float il0 = 1.f / l0, il1 = 1.f / l1;
    size_t ob0 = (size_t)(b * SS + qrow0) * (NH * HD) + h * HD + (lane & 3) * 2;
    size_t ob1 = (size_t)(b * SS + qrow1) * (NH * HD) + h * HD + (lane & 3) * 2;
#pragma unroll
    for (int n = 0; n < 16; n++) {
        __half2 w0 = __floats2half2_rn(o_[n][0] * il0, o_[n][1] * il0);
        __half2 w1 = __floats2half2_rn(o_[n][2] * il1, o_[n][3] * il1);
        *(__half2*)(out + ob0 + n * 8) = w0;
        *(__half2*)(out + ob1 + n * 8) = w1;
    }
}

// ---------------------------------------------------------------------------
extern "C" void kernel_launch(void* const* d_in, const int* in_sizes, int n_in,
                              void* d_out, int out_size) {
    const float* hid = (const float*)d_in[0];
    const int*   pos = (const int*)d_in[1];
    const float* Wq  = (const float*)d_in[2];
    const float* Wk  = (const float*)d_in[3];
    const float* Wv  = (const float*)d_in[4];
    const float* Wo  = (const float*)d_in[5];
    float* out = (float*)d_out;

    float *pq, *pk, *pv;
    cudaGetSymbolAddress((void**)&pq, g_q);
    cudaGetSymbolAddress((void**)&pk, g_k);
    cudaGetSymbolAddress((void**)&pv, g_v);
    __half *hf, *af, *qh, *ql, *kh, *kl, *vh, *vl, *oh, *ol;
    __half *fqh, *fql, *fkh, *fkl, *fvh, *fvl;
    cudaGetSymbolAddress((void**)&hf, g_hid_f16);
    cudaGetSymbolAddress((void**)&af, g_at_f16);
    cudaGetSymbolAddress((void**)&qh, g_wq_h);  cudaGetSymbolAddress((void**)&ql, g_wq_l);
    cudaGetSymbolAddress((void**)&kh, g_wk_h);  cudaGetSymbolAddress((void**)&kl, g_wk_l);
    cudaGetSymbolAddress((void**)&vh, g_wv_h);  cudaGetSymbolAddress((void**)&vl, g_wv_l);
    cudaGetSymbolAddress((void**)&oh, g_wo_h);  cudaGetSymbolAddress((void**)&ol, g_wo_l);
    cudaGetSymbolAddress((void**)&fqh, g_qh);   cudaGetSymbolAddress((void**)&fql, g_ql);
    cudaGetSymbolAddress((void**)&fkh, g_kh);   cudaGetSymbolAddress((void**)&fkl, g_kl);
    cudaGetSymbolAddress((void**)&fvh, g_vth);  cudaGetSymbolAddress((void**)&fvl, g_vtl);

    const int nHid = MROWS * DMODEL;
    const int nWq  = NH * HD * DMODEL;
    const int nWk  = NKV * HD * DMODEL;
    tofp16<<<(nHid + 255) / 256, 256>>>(hid, hf, nHid);
    decompose_h<<<(nWq + 255) / 256, 256>>>(Wq, qh, ql, nWq);
    decompose_h<<<(nWk + 255) / 256, 256>>>(Wk, kh, kl, nWk);
    decompose_h<<<(nWk + 255) / 256, 256>>>(Wv, vh, vl, nWk);
    decompose_h<<<(nWq + 255) / 256, 256>>>(Wo, oh, ol, nWq);
    rope_table<<<(MROWS*64 + 255)/256, 256>>>(pos);

    cudaFuncSetAttribute(gemm_qkv, cudaFuncAttributeMaxDynamicSharedMemorySize, GK_SMEM);
    cudaFuncSetAttribute(gemm_mma, cudaFuncAttributeMaxDynamicSharedMemorySize, GK_SMEM);

    gemm_qkv<<<dim3(48, MROWS/BM), 256, GK_SMEM>>>(hf, qh, ql, kh, kl, vh, vl, pq, pk, pv);

    rope_split_qk<<<(MROWS*(NH+NKV)*64 + 255)/256, 256>>>();
    split_vt<<<BB*NKV*32, 256>>>();

    cudaFuncSetAttribute(flash_mma, cudaFuncAttributeMaxDynamicSharedMemorySize, FL_SMEM);
    flash_mma<<<dim3(SS/128, NH, BB), 256, FL_SMEM>>>(fqh, fql, fkh, fkl, fvh, fvl, af);

    gemm_mma<<<dim3(NH*HD/BN, MROWS/BM), 256, GK_SMEM>>>(af, oh, ol, out, MROWS, NH*HD, NH*HD);
}

// round 11
// speedup vs baseline: 9.2452x; 1.1260x over previous
#include <cuda_runtime.h>
#include <cuda_fp16.h>
#include <math.h>
#include <stdint.h>

#define BB 2
#define SS 2048
#define DMODEL 4096
#define NH 32
#define NKV 8
#define HD 128
#define MROWS (BB*SS)   // 4096
#define QSCALE 0.08838834764831845f

extern __shared__ char dyn_smem[];

// ---------------- scratch (device globals; no allocation allowed) ----------
__device__ float g_q[(size_t)MROWS * NH * HD];
__device__ float g_k[(size_t)MROWS * NKV * HD];
__device__ float g_v[(size_t)MROWS * NKV * HD];
__device__ float g_cos[MROWS * (HD/2)];
__device__ float g_sin[MROWS * (HD/2)];

// fp16 operands
__device__ __half g_hid_f16[(size_t)MROWS * DMODEL];
__device__ __half g_at_f16[(size_t)MROWS * NH*HD];
__device__ __half g_wq_h[(size_t)NH*HD * DMODEL];
__device__ __half g_wq_l[(size_t)NH*HD * DMODEL];
__device__ __half g_wk_h[(size_t)NKV*HD * DMODEL];
__device__ __half g_wk_l[(size_t)NKV*HD * DMODEL];
__device__ __half g_wv_h[(size_t)NKV*HD * DMODEL];
__device__ __half g_wv_l[(size_t)NKV*HD * DMODEL];
__device__ __half g_wo_h[(size_t)NH*HD * NH*HD];

// fp16 attention operands (post-rope, split)
__device__ __half g_qh[(size_t)MROWS * NH * HD];
__device__ __half g_ql[(size_t)MROWS * NH * HD];
__device__ __half g_kh[(size_t)MROWS * NKV * HD];
__device__ __half g_kl[(size_t)MROWS * NKV * HD];
__device__ __half g_vth[(size_t)BB * NKV * HD * SS];  // [b][kvh][d][s]
__device__ __half g_vtl[(size_t)BB * NKV * HD * SS];

// ---------------- PTX helpers (sm_80+ base-target safe) ---------------------
__device__ __forceinline__ uint32_t smem_u32(const void* p) {
    uint32_t a;
    asm("{ .reg .u64 t; cvta.to.shared.u64 t, %1; cvt.u32.u64 %0, t; }" : "=r"(a) : "l"(p));
    return a;
}
__device__ __forceinline__ void cp16(uint32_t dst, const void* src) {
    asm volatile("cp.async.cg.shared.global [%0], [%1], 16;\n" :: "r"(dst), "l"(src));
}
__device__ __forceinline__ void cp_commit() { asm volatile("cp.async.commit_group;\n" ::: "memory"); }

__device__ __forceinline__ void ldm_x4(uint32_t* r, uint32_t addr) {
    asm volatile("ldmatrix.sync.aligned.m8n8.x4.shared.b16 {%0,%1,%2,%3}, [%4];"
        : "=r"(r[0]), "=r"(r[1]), "=r"(r[2]), "=r"(r[3]) : "r"(addr));
}
__device__ __forceinline__ void mma16816(float* d, const uint32_t* a, const uint32_t* b) {
    asm volatile("mma.sync.aligned.m16n8k16.row.col.f32.f16.f16.f32 "
        "{%0,%1,%2,%3}, {%4,%5,%6,%7}, {%8,%9}, {%0,%1,%2,%3};"
        : "+f"(d[0]), "+f"(d[1]), "+f"(d[2]), "+f"(d[3])
        : "r"(a[0]), "r"(a[1]), "r"(a[2]), "r"(a[3]), "r"(b[0]), "r"(b[1]));
}

// ---------------- conversion kernels ----------------------------------------
__global__ void tofp16(const float* __restrict__ s, __half* __restrict__ d, int n) {
    int i = blockIdx.x * blockDim.x + threadIdx.x;
    if (i < n) d[i] = __float2half(s[i]);
}

// fused weight prep: Wq/Wk/Wv hi+lo split; Wo hi only
#define NW1 (NH*HD*DMODEL)     // 16777216
#define NW2 (NKV*HD*DMODEL)    // 4194304
__global__ void prep_weights(const float* __restrict__ Wq, const float* __restrict__ Wk,
                             const float* __restrict__ Wv, const float* __restrict__ Wo) {
    int i = blockIdx.x * blockDim.x + threadIdx.x;
    if (i < NW1) {
        float f = Wq[i];
        __half hh = __float2half(f);
        g_wq_h[i] = hh;
        g_wq_l[i] = __float2half(f - __half2float(hh));
    } else if (i < NW1 + NW2) {
        int j = i - NW1;
        float f = Wk[j];
        __half hh = __float2half(f);
        g_wk_h[j] = hh;
        g_wk_l[j] = __float2half(f - __half2float(hh));
    } else if (i < NW1 + 2*NW2) {
        int j = i - NW1 - NW2;
        float f = Wv[j];
        __half hh = __float2half(f);
        g_wv_h[j] = hh;
        g_wv_l[j] = __float2half(f - __half2float(hh));
    } else if (i < 2*NW1 + 2*NW2) {
        int j = i - NW1 - 2*NW2;
        g_wo_h[j] = __float2half(Wo[j]);
    }
}

// ---------------------------------------------------------------------------
// HMMA fp16 2-term split GEMM core (NT). CTA 128x128, 8 warps (2x4, warp
// tile 64x32), BK=32, 3-stage cp.async, 2 CTAs/SM.
// ---------------------------------------------------------------------------
#define BM 128
#define BN 128
#define STG_A_BYTES (128*64)                   // 8192
#define STG_B_BYTES (128*128)                  // 16384 (hi|lo packed rows)
#define STG_BYTES (STG_A_BYTES + STG_B_BYTES)  // 24576
#define GK_SMEM (3*STG_BYTES + 128)            // 73856

__device__ __forceinline__ void gemm_core(
    const __half* __restrict__ A,
    const __half* __restrict__ Bh, const __half* __restrict__ Bl,
    float* __restrict__ C, int bm, int bn, int N, int K) {
    uint32_t sm0 = (smem_u32(dyn_smem) + 127) & ~127u;

    int t = threadIdx.x;
    int wid = t >> 5, lane = t & 31;
    int wm = (wid >> 2) * 64;
    int wn = (wid & 3) * 32;

    float acc[4][4][4];
#pragma unroll
    for (int a = 0; a < 4; a++)
#pragma unroll
        for (int b = 0; b < 4; b++)
#pragma unroll
            for (int c = 0; c < 4; c++) acc[a][b][c] = 0.f;

    auto load_stage = [&](int s, int ck) {
        int k0 = ck * 32;
        uint32_t sb = sm0 + s * STG_BYTES;
#pragma unroll
        for (int i = 0; i < 2; i++) {
            int idx = i * 256 + t;
            int r = idx >> 2, c = idx & 3;
            cp16(sb + r * 64 + (((c + (r >> 1)) & 3) * 16),
                 A + (size_t)(bm + r) * K + k0 + c * 8);
        }
        uint32_t sbB = sb + STG_A_BYTES;
#pragma unroll
        for (int i = 0; i < 4; i++) {
            int idx = i * 256 + t;
            int r = idx >> 3, c = idx & 7;
            const __half* src = ((c < 4) ? Bh : Bl)
                + (size_t)(bn + r) * K + k0 + (c & 3) * 8;
            cp16(sbB + r * 128 + ((c ^ (r & 7)) * 16), src);
        }
        cp_commit();
    };

    const int NCH = K >> 5;
    load_stage(0, 0);
    load_stage(1, 1);

    int laneR = lane & 15, laneH = lane >> 4;
    uint32_t aOff[4]; int aRot[4];
    uint32_t bBase[2];
#pragma unroll
    for (int mi = 0; mi < 4; mi++) {
        int r = wm + mi * 16 + laneR;
        aOff[mi] = sm0 + r * 64;
        aRot[mi] = r >> 1;
    }
#pragma unroll
    for (int nb = 0; nb < 2; nb++) {
        int r = wn + nb * 16 + laneR;
        bBase[nb] = sm0 + STG_A_BYTES + r * 128 + ((laneH ^ (r & 7)) * 16);
    }

    for (int ch = 0; ch < NCH; ch++) {
        if (ch + 2 < NCH) {
            load_stage((ch + 2) % 3, ch + 2);
            asm volatile("cp.async.wait_group 2;\n" ::: "memory");
        } else if (ch + 1 < NCH) {
            asm volatile("cp.async.wait_group 1;\n" ::: "memory");
        } else {
            asm volatile("cp.async.wait_group 0;\n" ::: "memory");
        }
        __syncthreads();

        uint32_t soff = (uint32_t)(ch % 3) * STG_BYTES;
#pragma unroll
        for (int kk = 0; kk < 2; kk++) {
            uint32_t kx = kk * 32;
            int kc = kk * 2 + laneH;
            uint32_t ah[4][4];
#pragma unroll
            for (int mi = 0; mi < 4; mi++) {
                uint32_t a0 = aOff[mi] + soff + (((kc + aRot[mi]) & 3) * 16);
                ldm_x4(ah[mi], a0);
            }
#pragma unroll
            for (int nb = 0; nb < 2; nb++) {
                uint32_t bh[4], bl[4];
                uint32_t b0 = (bBase[nb] + soff) ^ kx;
                ldm_x4(bh, b0);
                ldm_x4(bl, b0 ^ 64);
#pragma unroll
                for (int mi = 0; mi < 4; mi++)
#pragma unroll
                    for (int sub = 0; sub < 2; sub++) {
                        int ni = nb * 2 + sub;
                        uint32_t fh[2] = { bh[sub], bh[2 + sub] };
                        uint32_t fl[2] = { bl[sub], bl[2 + sub] };
                        mma16816(acc[mi][ni], ah[mi], fh);
                        mma16816(acc[mi][ni], ah[mi], fl);
                    }
            }
        }
        __syncthreads();
    }

    int row = lane >> 2;
    int col = (lane & 3) * 2;
#pragma unroll
    for (int mi = 0; mi < 4; mi++)
#pragma unroll
        for (int ni = 0; ni < 4; ni++) {
            float* c0 = C + (size_t)(bm + wm + mi * 16 + row) * N + bn + wn + ni * 8 + col;
            c0[0] = acc[mi][ni][0];
            c0[1] = acc[mi][ni][1];
            float* c1 = c0 + 8 * (size_t)N;
            c1[0] = acc[mi][ni][2];
            c1[1] = acc[mi][ni][3];
        }
}

// fused QKV: 48 N-tiles (32 Q, 8 K, 8 V), one launch
__global__ __launch_bounds__(256, 2)
void gemm_qkv(const __half* __restrict__ A,
              const __half* __restrict__ Wqh, const __half* __restrict__ Wql,
              const __half* __restrict__ Wkh, const __half* __restrict__ Wkl,
              const __half* __restrict__ Wvh, const __half* __restrict__ Wvl,
              float* __restrict__ pq, float* __restrict__ pk, float* __restrict__ pv) {
    int tx = blockIdx.x;
    const __half *Bh, *Bl; float* C; int N, bn;
    if (tx < 32)      { Bh = Wqh; Bl = Wql; C = pq; N = NH*HD;  bn = tx * 128; }
    else if (tx < 40) { Bh = Wkh; Bl = Wkl; C = pk; N = NKV*HD; bn = (tx - 32) * 128; }
    else              { Bh = Wvh; Bl = Wvl; C = pv; N = NKV*HD; bn = (tx - 40) * 128; }
    gemm_core(A, Bh, Bl, C, blockIdx.y * BM, bn, N, DMODEL);
}

// ---------------------------------------------------------------------------
// Single-term fp16 GEMM (for Wo): B stored like A (64B rows, rotation swizzle).
// Stage = 16 KB; 3 stages = 48 KB -> 2 CTAs/SM easily.
// ---------------------------------------------------------------------------
#define ST1_BYTES 16384
#define GK1_SMEM (3*ST1_BYTES + 128)

__global__ __launch_bounds__(256, 2)
void gemm_mma1(const __half* __restrict__ A, const __half* __restrict__ B,
               float* __restrict__ C, int M, int N, int K) {
    uint32_t sm0 = (smem_u32(dyn_smem) + 127) & ~127u;

    int t = threadIdx.x;
    int wid = t >> 5, lane = t & 31;
    int bm = blockIdx.y * BM, bn = blockIdx.x * BN;
    int wm = (wid >> 2) * 64;
    int wn = (wid & 3) * 32;

    float acc[4][4][4];
#pragma unroll
    for (int a = 0; a < 4; a++)
#pragma unroll
        for (int b = 0; b < 4; b++)
#pragma unroll
            for (int c = 0; c < 4; c++) acc[a][b][c] = 0.f;

    auto load_stage = [&](int s, int ck) {
        int k0 = ck * 32;
        uint32_t sb = sm0 + s * ST1_BYTES;
#pragma unroll
        for (int i = 0; i < 2; i++) {           // A: 128 rows x 4 chunks
            int idx = i * 256 + t;
            int r = idx >> 2, c = idx & 3;
            cp16(sb + r * 64 + (((c + (r >> 1)) & 3) * 16),
                 A + (size_t)(bm + r) * K + k0 + c * 8);
        }
        uint32_t sbB = sb + 8192;
#pragma unroll
        for (int i = 0; i < 2; i++) {           // B: 128 rows x 4 chunks
            int idx = i * 256 + t;
            int r = idx >> 2, c = idx & 3;
            cp16(sbB + r * 64 + (((c + (r >> 1)) & 3) * 16),
                 B + (size_t)(bn + r) * K + k0 + c * 8);
        }
        cp_commit();
    };

    const int NCH = K >> 5;
    load_stage(0, 0);
    load_stage(1, 1);

    int laneR = lane & 15, laneH = lane >> 4;
    uint32_t aOff[4]; int aRot[4];
    uint32_t bOff[2]; int bRot[2];
#pragma unroll
    for (int mi = 0; mi < 4; mi++) {
        int r = wm + mi * 16 + laneR;
        aOff[mi] = sm0 + r * 64;
        aRot[mi] = r >> 1;
    }
#pragma unroll
    for (int nb = 0; nb < 2; nb++) {
        int r = wn + nb * 16 + laneR;
        bOff[nb] = sm0 + 8192 + r * 64;
        bRot[nb] = r >> 1;
    }

    for (int ch = 0; ch < NCH; ch++) {
        if (ch + 2 < NCH) {
            load_stage((ch + 2) % 3, ch + 2);
            asm volatile("cp.async.wait_group 2;\n" ::: "memory");
        } else if (ch + 1 < NCH) {
            asm volatile("cp.async.wait_group 1;\n" ::: "memory");
        } else {
            asm volatile("cp.async.wait_group 0;\n" ::: "memory");
        }
        __syncthreads();

        uint32_t soff = (uint32_t)(ch % 3) * ST1_BYTES;
#pragma unroll
        for (int kk = 0; kk < 2; kk++) {
            int kc = kk * 2 + laneH;
            uint32_t ah[4][4];
#pragma unroll
            for (int mi = 0; mi < 4; mi++) {
                uint32_t a0 = aOff[mi] + soff + (((kc + aRot[mi]) & 3) * 16);
                ldm_x4(ah[mi], a0);
            }
#pragma unroll
            for (int nb = 0; nb < 2; nb++) {
                uint32_t bh[4];
                uint32_t b0 = bOff[nb] + soff + (((kc + bRot[nb]) & 3) * 16);
                ldm_x4(bh, b0);
#pragma unroll
                for (int mi = 0; mi < 4; mi++)
#pragma unroll
                    for (int sub = 0; sub < 2; sub++) {
                        int ni = nb * 2 + sub;
                        uint32_t fh[2] = { bh[sub], bh[2 + sub] };
                        mma16816(acc[mi][ni], ah[mi], fh);
                    }
            }
        }
        __syncthreads();
    }

    int row = lane >> 2;
    int col = (lane & 3) * 2;
#pragma unroll
    for (int mi = 0; mi < 4; mi++)
#pragma unroll
        for (int ni = 0; ni < 4; ni++) {
            float* c0 = C + (size_t)(bm + wm + mi * 16 + row) * N + bn + wn + ni * 8 + col;
            c0[0] = acc[mi][ni][0];
            c0[1] = acc[mi][ni][1];
            float* c1 = c0 + 8 * (size_t)N;
            c1[0] = acc[mi][ni][2];
            c1[1] = acc[mi][ni][3];
        }
}

// ---------------- RoPE table ------------------------------------------------
__global__ void rope_table(const int* __restrict__ pos) {
    int idx = blockIdx.x * blockDim.x + threadIdx.x;
    if (idx >= MROWS * 64) return;
    int i   = idx & 63;
    int row = idx >> 6;
    double inv = exp(-(double)(2 * i) / 128.0 * log(10000.0));
    double ang = (double)pos[row] * inv;
    g_cos[idx] = (float)cos(ang);
    g_sin[idx] = (float)sin(ang);
}

// ---------------- fused RoPE + fp16 hi/lo split (q and k in one pass) --------
__global__ void rope_split_qk() {
    int idx = blockIdx.x * blockDim.x + threadIdx.x;
    const int total = MROWS * (NH + NKV) * 64;
    if (idx >= total) return;
    int i    = idx & 63;
    int head = (idx >> 6) % (NH + NKV);
    int row  = idx / (64 * (NH + NKV));
    float c = g_cos[row * 64 + i];
    float s = g_sin[row * 64 + i];
    if (head < NH) {
        size_t o = (size_t)row * NH * HD + head * HD;
        float x1 = g_q[o + i], x2 = g_q[o + i + 64];
        float y1 = (x1 * c - x2 * s) * QSCALE;
        float y2 = (x2 * c + x1 * s) * QSCALE;
        __half h1 = __float2half(y1), h2 = __float2half(y2);
        g_qh[o + i] = h1;      g_ql[o + i]      = __float2half(y1 - __half2float(h1));
        g_qh[o + i + 64] = h2; g_ql[o + i + 64] = __float2half(y2 - __half2float(h2));
    } else {
        size_t o = (size_t)row * NKV * HD + (head - NH) * HD;
        float x1 = g_k[o + i], x2 = g_k[o + i + 64];
        float y1 = x1 * c - x2 * s;
        float y2 = x2 * c + x1 * s;
        __half h1 = __float2half(y1), h2 = __float2half(y2);
        g_kh[o + i] = h1;      g_kl[o + i]      = __float2half(y1 - __half2float(h1));
        g_kh[o + i + 64] = h2; g_kl[o + i + 64] = __float2half(y2 - __half2float(h2));
    }
}

// ---------------- V transpose + split: g_v -> Vt[b][kvh][d][s] ---------------
__global__ __launch_bounds__(256) void split_vt() {
    __shared__ float sv[64][129];
    int blk = blockIdx.x;
    int st  = blk & 31;
    int kvh = (blk >> 5) & 7;
    int b   = blk >> 8;
    int tid = threadIdx.x;
#pragma unroll
    for (int it = 0; it < 32; it++) {
        int idx = it * 256 + tid;
        int r = idx >> 7, c = idx & 127;
        sv[r][c] = g_v[(size_t)(b * SS + st * 64 + r) * (NKV * HD) + kvh * HD + c];
    }
    __syncthreads();
    int d = tid >> 1, j = tid & 1;
    __half hbuf[32], lbuf[32];
#pragma unroll
    for (int q = 0; q < 32; q++) {
        float f = sv[j * 32 + q][d];
        __half hh = __float2half(f);
        hbuf[q] = hh;
        lbuf[q] = __float2half(f - __half2float(hh));
    }
    size_t base = ((size_t)(b * NKV + kvh) * HD + d) * SS + st * 64 + j * 32;
    uint4* dh = (uint4*)(g_vth + base);
    uint4* dl = (uint4*)(g_vtl + base);
#pragma unroll
    for (int q = 0; q < 4; q++) {
        dh[q] = ((uint4*)hbuf)[q];
        dl[q] = ((uint4*)lbuf)[q];
    }
}

// ---------------------------------------------------------------------------
// HMMA flash attention: Br=128 (8 warps, 256 thr), Bc=64, fp16 3-term splits.
// ---------------------------------------------------------------------------
#define SQH 0
#define SQL 32768
#define SKH 65536
#define SKL 81920
#define SVH 98304
#define SVL 114688
#define FL_SMEM 131072

__global__ __launch_bounds__(256) void flash_mma(
    const __half* __restrict__ Qh_g, const __half* __restrict__ Ql_g,
    const __half* __restrict__ Kh_g, const __half* __restrict__ Kl_g,
    const __half* __restrict__ Vth_g, const __half* __restrict__ Vtl_g,
    __half* __restrict__ out) {
    uint32_t s0 = smem_u32(dyn_smem);

    int qt = blockIdx.x, h = blockIdx.y, b = blockIdx.z;
    int kvh = h >> 2;
    int t = threadIdx.x, wid = t >> 5, lane = t & 31;
    int laneR = lane & 15, laneH = lane >> 4;
    int wm = wid * 16;

#pragma unroll
    for (int i = 0; i < 8; i++) {
        int idx = i * 256 + t;
        int r = idx >> 4, c = idx & 15;
        uint32_t d = r * 256 + ((c ^ (r & 7)) * 16);
        size_t g = ((size_t)(b * SS + qt * 128 + r)) * (NH * HD) + h * HD + c * 8;
        cp16(s0 + SQH + d, Qh_g + g);
        cp16(s0 + SQL + d, Ql_g + g);
    }
    auto loadKV = [&](int kt) {
#pragma unroll
        for (int i = 0; i < 4; i++) {
            int idx = i * 256 + t;
            int r = idx >> 4, c = idx & 15;
            uint32_t d = r * 256 + ((c ^ (r & 7)) * 16);
            size_t g = ((size_t)(b * SS + kt * 64 + r)) * (NKV * HD) + kvh * HD + c * 8;
            cp16(s0 + SKH + d, Kh_g + g);
            cp16(s0 + SKL + d, Kl_g + g);
        }
#pragma unroll
        for (int i = 0; i < 4; i++) {
            int idx = i * 256 + t;
            int r = idx >> 3, c = idx & 7;
            uint32_t d = r * 128 + ((c ^ (r & 7)) * 16);
            size_t g = ((size_t)((b * NKV + kvh) * HD + r)) * SS + kt * 64 + c * 8;
            cp16(s0 + SVH + d, Vth_g + g);
            cp16(s0 + SVL + d, Vtl_g + g);
        }
    };
    loadKV(0);
    cp_commit();

    float o_[16][4];
#pragma unroll
    for (int n = 0; n < 16; n++)
#pragma unroll
        for (int c = 0; c < 4; c++) o_[n][c] = 0.f;
    float m0 = -1e30f, m1 = -1e30f, l0 = 0.f, l1 = 0.f;
    int r0 = lane >> 2;
    int qrow0 = qt * 128 + wm + r0;
    int qrow1 = qrow0 + 8;
    const int KTMAX = 2 * qt + 1;

    for (int kt = 0; kt <= KTMAX; kt++) {
        asm volatile("cp.async.wait_group 0;\n" ::: "memory");
        __syncthreads();

        float s[8][4];
#pragma unroll
        for (int j = 0; j < 8; j++)
#pragma unroll
            for (int c = 0; c < 4; c++) s[j][c] = 0.f;

#pragma unroll
        for (int kk = 0; kk < 8; kk++) {
            uint32_t qa[4], qb[4];
            {
                int r = wm + laneR;
                uint32_t ph = (uint32_t)(((kk * 2 + laneH) ^ (r & 7)) * 16);
                ldm_x4(qa, s0 + SQH + r * 256 + ph);
                ldm_x4(qb, s0 + SQL + r * 256 + ph);
            }
#pragma unroll
            for (int jj = 0; jj < 4; jj++) {
                uint32_t kh_[4], kl_[4];
                int r = jj * 16 + laneR;
                uint32_t ph = (uint32_t)(((kk * 2 + laneH) ^ (r & 7)) * 16);
                ldm_x4(kh_, s0 + SKH + r * 256 + ph);
                ldm_x4(kl_, s0 + SKL + r * 256 + ph);
#pragma unroll
                for (int sub = 0; sub < 2; sub++) {
                    int j = jj * 2 + sub;
                    uint32_t fh[2] = { kh_[sub], kh_[2 + sub] };
                    uint32_t fl[2] = { kl_[sub], kl_[2 + sub] };
                    mma16816(s[j], qa, fh);
                    mma16816(s[j], qa, fl);
                    mma16816(s[j], qb, fh);
                }
            }
        }

        if (kt * 64 + 63 > qrow0) {
#pragma unroll
            for (int j = 0; j < 8; j++) {
                int cb = kt * 64 + j * 8 + (lane & 3) * 2;
                if (cb     > qrow0) s[j][0] = -1e30f;
                if (cb + 1 > qrow0) s[j][1] = -1e30f;
                if (cb     > qrow1) s[j][2] = -1e30f;
                if (cb + 1 > qrow1) s[j][3] = -1e30f;
            }
        }

        float rm0 = -1e30f, rm1 = -1e30f;
#pragma unroll
        for (int j = 0; j < 8; j++) {
            rm0 = fmaxf(rm0, fmaxf(s[j][0], s[j][1]));
            rm1 = fmaxf(rm1, fmaxf(s[j][2], s[j][3]));
        }
        rm0 = fmaxf(rm0, __shfl_xor_sync(0xffffffffu, rm0, 1));
        rm0 = fmaxf(rm0, __shfl_xor_sync(0xffffffffu, rm0, 2));
        rm1 = fmaxf(rm1, __shfl_xor_sync(0xffffffffu, rm1, 1));
        rm1 = fmaxf(rm1, __shfl_xor_sync(0xffffffffu, rm1, 2));
        float mn0 = fmaxf(m0, rm0), mn1 = fmaxf(m1, rm1);
        float a0 = __expf(m0 - mn0), a1 = __expf(m1 - mn1);
        l0 *= a0; l1 *= a1;
#pragma unroll
        for (int n = 0; n < 16; n++) {
            o_[n][0] *= a0; o_[n][1] *= a0;
            o_[n][2] *= a1; o_[n][3] *= a1;
        }
        m0 = mn0; m1 = mn1;

        uint32_t ph0[8], ph1[8], pl0[8], pl1[8];
        float sum0 = 0.f, sum1 = 0.f;
#pragma unroll
        for (int j = 0; j < 8; j++) {
            float e0 = __expf(s[j][0] - mn0), e1 = __expf(s[j][1] - mn0);
            float e2 = __expf(s[j][2] - mn1), e3 = __expf(s[j][3] - mn1);
            sum0 += e0 + e1; sum1 += e2 + e3;
            __half2 hh0 = __floats2half2_rn(e0, e1);
            __half2 hh1 = __floats2half2_rn(e2, e3);
            ph0[j] = *(uint32_t*)&hh0;
            ph1[j] = *(uint32_t*)&hh1;
            __half2 dd0 = __floats2half2_rn(e0 - __low2float(hh0), e1 - __high2float(hh0));
            __half2 dd1 = __floats2half2_rn(e2 - __low2float(hh1), e3 - __high2float(hh1));
            pl0[j] = *(uint32_t*)&dd0;
            pl1[j] = *(uint32_t*)&dd1;
        }
        sum0 += __shfl_xor_sync(0xffffffffu, sum0, 1);
        sum0 += __shfl_xor_sync(0xffffffffu, sum0, 2);
        sum1 += __shfl_xor_sync(0xffffffffu, sum1, 1);
        sum1 += __shfl_xor_sync(0xffffffffu, sum1, 2);
        l0 += sum0; l1 += sum1;

#pragma unroll
        for (int tt = 0; tt < 4; tt++) {
            uint32_t pa[4] = { ph0[2*tt], ph1[2*tt], ph0[2*tt+1], ph1[2*tt+1] };
            uint32_t pb[4] = { pl0[2*tt], pl1[2*tt], pl0[2*tt+1], pl1[2*tt+1] };
#pragma unroll
            for (int dg = 0; dg < 8; dg++) {
                uint32_t vh_[4], vl_[4];
                int r = dg * 16 + laneR;
                uint32_t ph = (uint32_t)(((tt * 2 + laneH) ^ (r & 7)) * 16);
                ldm_x4(vh_, s0 + SVH + r * 128 + ph);
                ldm_x4(vl_, s0 + SVL + r * 128 + ph);
#pragma unroll
                for (int sub = 0; sub < 2; sub++) {
                    int n = dg * 2 + sub;
                    uint32_t fh[2] = { vh_[sub], vh_[2 + sub] };
                    uint32_t fl[2] = { vl_[sub], vl_[2 + sub] };
                    mma16816(o_[n], pa, fh);
                    mma16816(o_[n], pa, fl);
                    mma16816(o_[n], pb, fh);
                }
            }
        }

        __syncthreads();
        if (kt + 1 <= KTMAX) {
            loadKV(kt + 1);
            cp_commit();
        }
    }

    float il0 = 1.f / l0, il1 = 1.f / l1;
    size_t ob0 = (size_t)(b * SS + qrow0) * (NH * HD) + h * HD + (lane & 3) * 2;
    size_t ob1 = (size_t)(b * SS + qrow1) * (NH * HD) + h * HD + (lane & 3) * 2;
#pragma unroll
    for (int n = 0; n < 16; n++) {
        __half2 w0 = __floats2half2_rn(o_[n][0] * il0, o_[n][1] * il0);
        __half2 w1 = __floats2half2_rn(o_[n][2] * il1, o_[n][3] * il1);
        *(__half2*)(out + ob0 + n * 8) = w0;
        *(__half2*)(out + ob1 + n * 8) = w1;
    }
}

// ---------------------------------------------------------------------------
extern "C" void kernel_launch(void* const* d_in, const int* in_sizes, int n_in,
                              void* d_out, int out_size) {
    const float* hid = (const float*)d_in[0];
    const int*   pos = (const int*)d_in[1];
    const float* Wq  = (const float*)d_in[2];
    const float* Wk  = (const float*)d_in[3];
    const float* Wv  = (const float*)d_in[4];
    const float* Wo  = (const float*)d_in[5];
    float* out = (float*)d_out;

    float *pq, *pk, *pv;
    cudaGetSymbolAddress((void**)&pq, g_q);
    cudaGetSymbolAddress((void**)&pk, g_k);
    cudaGetSymbolAddress((void**)&pv, g_v);
    __half *hf, *af, *qh, *ql, *kh, *kl, *vh, *vl, *oh;
    __half *fqh, *fql, *fkh, *fkl, *fvh, *fvl;
    cudaGetSymbolAddress((void**)&hf, g_hid_f16);
    cudaGetSymbolAddress((void**)&af, g_at_f16);
    cudaGetSymbolAddress((void**)&qh, g_wq_h);  cudaGetSymbolAddress((void**)&ql, g_wq_l);
    cudaGetSymbolAddress((void**)&kh, g_wk_h);  cudaGetSymbolAddress((void**)&kl, g_wk_l);
    cudaGetSymbolAddress((void**)&vh, g_wv_h);  cudaGetSymbolAddress((void**)&vl, g_wv_l);
    cudaGetSymbolAddress((void**)&oh, g_wo_h);
    cudaGetSymbolAddress((void**)&fqh, g_qh);   cudaGetSymbolAddress((void**)&fql, g_ql);
    cudaGetSymbolAddress((void**)&fkh, g_kh);   cudaGetSymbolAddress((void**)&fkl, g_kl);
    cudaGetSymbolAddress((void**)&fvh, g_vth);  cudaGetSymbolAddress((void**)&fvl, g_vtl);

    const int nHid = MROWS * DMODEL;
    const int nPrep = 2 * NW1 + 2 * NW2;
    tofp16<<<(nHid + 255) / 256, 256>>>(hid, hf, nHid);
    prep_weights<<<(nPrep + 255) / 256, 256>>>(Wq, Wk, Wv, Wo);
    rope_table<<<(MROWS*64 + 255)/256, 256>>>(pos);

    cudaFuncSetAttribute(gemm_qkv, cudaFuncAttributeMaxDynamicSharedMemorySize, GK_SMEM);
    cudaFuncSetAttribute(gemm_mma1, cudaFuncAttributeMaxDynamicSharedMemorySize, GK1_SMEM);

    gemm_qkv<<<dim3(48, MROWS/BM), 256, GK_SMEM>>>(hf, qh, ql, kh, kl, vh, vl, pq, pk, pv);

    rope_split_qk<<<(MROWS*(NH+NKV)*64 + 255)/256, 256>>>();
    split_vt<<<BB*NKV*32, 256>>>();

    cudaFuncSetAttribute(flash_mma, cudaFuncAttributeMaxDynamicSharedMemorySize, FL_SMEM);
    flash_mma<<<dim3(SS/128, NH, BB), 256, FL_SMEM>>>(fqh, fql, fkh, fkl, fvh, fvl, af);

    gemm_mma1<<<dim3(NH*HD/BN, MROWS/BM), 256, GK1_SMEM>>>(af, oh, out, MROWS, NH*HD, NH*HD);
}

// round 12
// speedup vs baseline: 10.7424x; 1.1619x over previous
#include <cuda_runtime.h>
#include <cuda_fp16.h>
#include <math.h>
#include <stdint.h>

#define BB 2
#define SS 2048
#define DMODEL 4096
#define NH 32
#define NKV 8
#define HD 128
#define MROWS (BB*SS)   // 4096
#define QSCALE 0.08838834764831845f

extern __shared__ char dyn_smem[];

// ---------------- scratch (device globals; no allocation allowed) ----------
__device__ float g_q[(size_t)MROWS * NH * HD];
__device__ float g_k[(size_t)MROWS * NKV * HD];
__device__ float g_v[(size_t)MROWS * NKV * HD];
__device__ float g_cos[MROWS * (HD/2)];
__device__ float g_sin[MROWS * (HD/2)];

// fp16 operands
__device__ __half g_hid_f16[(size_t)MROWS * DMODEL];
__device__ __half g_at_f16[(size_t)MROWS * NH*HD];
__device__ __half g_wq_h[(size_t)NH*HD * DMODEL];
__device__ __half g_wq_l[(size_t)NH*HD * DMODEL];
__device__ __half g_wk_h[(size_t)NKV*HD * DMODEL];
__device__ __half g_wk_l[(size_t)NKV*HD * DMODEL];
__device__ __half g_wv_h[(size_t)NKV*HD * DMODEL];
__device__ __half g_wv_l[(size_t)NKV*HD * DMODEL];
__device__ __half g_wo_h[(size_t)NH*HD * NH*HD];

// fp16 attention operands (post-rope, split)
__device__ __half g_qh[(size_t)MROWS * NH * HD];
__device__ __half g_ql[(size_t)MROWS * NH * HD];
__device__ __half g_kh[(size_t)MROWS * NKV * HD];
__device__ __half g_kl[(size_t)MROWS * NKV * HD];
__device__ __half g_vth[(size_t)BB * NKV * HD * SS];  // [b][kvh][d][s]

// ---------------- PTX helpers (sm_80+ base-target safe) ---------------------
__device__ __forceinline__ uint32_t smem_u32(const void* p) {
    uint32_t a;
    asm("{ .reg .u64 t; cvta.to.shared.u64 t, %1; cvt.u32.u64 %0, t; }" : "=r"(a) : "l"(p));
    return a;
}
__device__ __forceinline__ void cp16(uint32_t dst, const void* src) {
    asm volatile("cp.async.cg.shared.global [%0], [%1], 16;\n" :: "r"(dst), "l"(src));
}
__device__ __forceinline__ void cp_commit() { asm volatile("cp.async.commit_group;\n" ::: "memory"); }

__device__ __forceinline__ void ldm_x4(uint32_t* r, uint32_t addr) {
    asm volatile("ldmatrix.sync.aligned.m8n8.x4.shared.b16 {%0,%1,%2,%3}, [%4];"
        : "=r"(r[0]), "=r"(r[1]), "=r"(r[2]), "=r"(r[3]) : "r"(addr));
}
__device__ __forceinline__ void mma16816(float* d, const uint32_t* a, const uint32_t* b) {
    asm volatile("mma.sync.aligned.m16n8k16.row.col.f32.f16.f16.f32 "
        "{%0,%1,%2,%3}, {%4,%5,%6,%7}, {%8,%9}, {%0,%1,%2,%3};"
        : "+f"(d[0]), "+f"(d[1]), "+f"(d[2]), "+f"(d[3])
        : "r"(a[0]), "r"(a[1]), "r"(a[2]), "r"(a[3]), "r"(b[0]), "r"(b[1]));
}

// ---------------- conversion kernels ----------------------------------------
__global__ void tofp16(const float* __restrict__ s, __half* __restrict__ d, int n) {
    int i = blockIdx.x * blockDim.x + threadIdx.x;
    if (i < n) d[i] = __float2half(s[i]);
}

#define NW1 (NH*HD*DMODEL)
#define NW2 (NKV*HD*DMODEL)
__global__ void prep_weights(const float* __restrict__ Wq, const float* __restrict__ Wk,
                             const float* __restrict__ Wv, const float* __restrict__ Wo) {
    int i = blockIdx.x * blockDim.x + threadIdx.x;
    if (i < NW1) {
        float f = Wq[i];
        __half hh = __float2half(f);
        g_wq_h[i] = hh;
        g_wq_l[i] = __float2half(f - __half2float(hh));
    } else if (i < NW1 + NW2) {
        int j = i - NW1;
        float f = Wk[j];
        __half hh = __float2half(f);
        g_wk_h[j] = hh;
        g_wk_l[j] = __float2half(f - __half2float(hh));
    } else if (i < NW1 + 2*NW2) {
        int j = i - NW1 - NW2;
        float f = Wv[j];
        __half hh = __float2half(f);
        g_wv_h[j] = hh;
        g_wv_l[j] = __float2half(f - __half2float(hh));
    } else if (i < 2*NW1 + 2*NW2) {
        int j = i - NW1 - 2*NW2;
        g_wo_h[j] = __float2half(Wo[j]);
    }
}

// ---------------------------------------------------------------------------
// HMMA fp16 2-term split GEMM core (NT). CTA 128x128, 8 warps (2x4, warp
// tile 64x32), BK=64, 2-stage cp.async, 2 CTAs/SM. XOR swizzle on 128B rows.
// ---------------------------------------------------------------------------
#define BM 128
#define BN 128
#define STG_A_BYTES (128*128)                  // 16384
#define STG_B_BYTES (128*256)                  // 32768 (hi|lo packed rows)
#define STG_BYTES (STG_A_BYTES + STG_B_BYTES)  // 49152
#define GK_SMEM (2*STG_BYTES + 128)            // 98432

__device__ __forceinline__ void gemm_core(
    const __half* __restrict__ A,
    const __half* __restrict__ Bh, const __half* __restrict__ Bl,
    float* __restrict__ C, int bm, int bn, int N, int K) {
    uint32_t sm0 = (smem_u32(dyn_smem) + 127) & ~127u;

    int t = threadIdx.x;
    int wid = t >> 5, lane = t & 31;
    int wm = (wid >> 2) * 64;
    int wn = (wid & 3) * 32;

    float acc[4][4][4];
#pragma unroll
    for (int a = 0; a < 4; a++)
#pragma unroll
        for (int b = 0; b < 4; b++)
#pragma unroll
            for (int c = 0; c < 4; c++) acc[a][b][c] = 0.f;

    auto load_stage = [&](int s, int ck) {
        int k0 = ck * 64;
        uint32_t sb = sm0 + s * STG_BYTES;
#pragma unroll
        for (int i = 0; i < 4; i++) {           // A: 128 rows x 8 chunks
            int idx = i * 256 + t;
            int r = idx >> 3, c = idx & 7;
            cp16(sb + r * 128 + ((c ^ (r & 7)) * 16),
                 A + (size_t)(bm + r) * K + k0 + c * 8);
        }
        uint32_t sbB = sb + STG_A_BYTES;
#pragma unroll
        for (int i = 0; i < 8; i++) {           // B: 128 rows x 16 chunks (hi|lo)
            int idx = i * 256 + t;
            int r = idx >> 4, c = idx & 15;
            const __half* src = ((c < 8) ? Bh : Bl)
                + (size_t)(bn + r) * K + k0 + (c & 7) * 8;
            cp16(sbB + r * 256 + ((c & 8) << 4) + (((c & 7) ^ (r & 7)) * 16), src);
        }
        cp_commit();
    };

    const int NCH = K >> 6;
    load_stage(0, 0);

    int laneR = lane & 15, laneH = lane >> 4;
    uint32_t aOff[4], bOff[2];
#pragma unroll
    for (int mi = 0; mi < 4; mi++) {
        int r = wm + mi * 16 + laneR;
        aOff[mi] = sm0 + r * 128 + ((laneH ^ (r & 7)) * 16);
    }
#pragma unroll
    for (int nb = 0; nb < 2; nb++) {
        int r = wn + nb * 16 + laneR;
        bOff[nb] = sm0 + STG_A_BYTES + r * 256 + ((laneH ^ (r & 7)) * 16);
    }

    for (int ch = 0; ch < NCH; ch++) {
        if (ch + 1 < NCH) {
            load_stage((ch + 1) & 1, ch + 1);
            asm volatile("cp.async.wait_group 1;\n" ::: "memory");
        } else {
            asm volatile("cp.async.wait_group 0;\n" ::: "memory");
        }
        __syncthreads();

        uint32_t soff = (uint32_t)(ch & 1) * STG_BYTES;
#pragma unroll
        for (int kk = 0; kk < 4; kk++) {
            uint32_t kx = kk * 32;
            uint32_t ah[4][4];
#pragma unroll
            for (int mi = 0; mi < 4; mi++)
                ldm_x4(ah[mi], (aOff[mi] + soff) ^ kx);
#pragma unroll
            for (int nb = 0; nb < 2; nb++) {
                uint32_t bh[4], bl[4];
                uint32_t b0 = (bOff[nb] + soff) ^ kx;
                ldm_x4(bh, b0);
                ldm_x4(bl, b0 + 128);
#pragma unroll
                for (int mi = 0; mi < 4; mi++)
#pragma unroll
                    for (int sub = 0; sub < 2; sub++) {
                        int ni = nb * 2 + sub;
                        uint32_t fh[2] = { bh[sub], bh[2 + sub] };
                        uint32_t fl[2] = { bl[sub], bl[2 + sub] };
                        mma16816(acc[mi][ni], ah[mi], fh);
                        mma16816(acc[mi][ni], ah[mi], fl);
                    }
            }
        }
        __syncthreads();
    }

    int row = lane >> 2;
    int col = (lane & 3) * 2;
#pragma unroll
    for (int mi = 0; mi < 4; mi++)
#pragma unroll
        for (int ni = 0; ni < 4; ni++) {
            float* c0 = C + (size_t)(bm + wm + mi * 16 + row) * N + bn + wn + ni * 8 + col;
            c0[0] = acc[mi][ni][0];
            c0[1] = acc[mi][ni][1];
            float* c1 = c0 + 8 * (size_t)N;
            c1[0] = acc[mi][ni][2];
            c1[1] = acc[mi][ni][3];
        }
}

// fused QKV: 48 N-tiles (32 Q, 8 K, 8 V), one launch
__global__ __launch_bounds__(256, 2)
void gemm_qkv(const __half* __restrict__ A,
              const __half* __restrict__ Wqh, const __half* __restrict__ Wql,
              const __half* __restrict__ Wkh, const __half* __restrict__ Wkl,
              const __half* __restrict__ Wvh, const __half* __restrict__ Wvl,
              float* __restrict__ pq, float* __restrict__ pk, float* __restrict__ pv) {
    int tx = blockIdx.x;
    const __half *Bh, *Bl; float* C; int N, bn;
    if (tx < 32)      { Bh = Wqh; Bl = Wql; C = pq; N = NH*HD;  bn = tx * 128; }
    else if (tx < 40) { Bh = Wkh; Bl = Wkl; C = pk; N = NKV*HD; bn = (tx - 32) * 128; }
    else              { Bh = Wvh; Bl = Wvl; C = pv; N = NKV*HD; bn = (tx - 40) * 128; }
    gemm_core(A, Bh, Bl, C, blockIdx.y * BM, bn, N, DMODEL);
}

// ---------------------------------------------------------------------------
// Single-term fp16 GEMM (Wo): BK=64, 2-stage, both mats 128B-row XOR layout.
// ---------------------------------------------------------------------------
#define ST1_BYTES 32768
#define GK1_SMEM (2*ST1_BYTES + 128)

__global__ __launch_bounds__(256, 2)
void gemm_mma1(const __half* __restrict__ A, const __half* __restrict__ B,
               float* __restrict__ C, int M, int N, int K) {
    uint32_t sm0 = (smem_u32(dyn_smem) + 127) & ~127u;

    int t = threadIdx.x;
    int wid = t >> 5, lane = t & 31;
    int bm = blockIdx.y * BM, bn = blockIdx.x * BN;
    int wm = (wid >> 2) * 64;
    int wn = (wid & 3) * 32;

    float acc[4][4][4];
#pragma unroll
    for (int a = 0; a < 4; a++)
#pragma unroll
        for (int b = 0; b < 4; b++)
#pragma unroll
            for (int c = 0; c < 4; c++) acc[a][b][c] = 0.f;

    auto load_stage = [&](int s, int ck) {
        int k0 = ck * 64;
        uint32_t sb = sm0 + s * ST1_BYTES;
#pragma unroll
        for (int i = 0; i < 4; i++) {
            int idx = i * 256 + t;
            int r = idx >> 3, c = idx & 7;
            cp16(sb + r * 128 + ((c ^ (r & 7)) * 16),
                 A + (size_t)(bm + r) * K + k0 + c * 8);
        }
        uint32_t sbB = sb + 16384;
#pragma unroll
        for (int i = 0; i < 4; i++) {
            int idx = i * 256 + t;
            int r = idx >> 3, c = idx & 7;
            cp16(sbB + r * 128 + ((c ^ (r & 7)) * 16),
                 B + (size_t)(bn + r) * K + k0 + c * 8);
        }
        cp_commit();
    };

    const int NCH = K >> 6;
    load_stage(0, 0);

    int laneR = lane & 15, laneH = lane >> 4;
    uint32_t aOff[4], bOff[2];
#pragma unroll
    for (int mi = 0; mi < 4; mi++) {
        int r = wm + mi * 16 + laneR;
        aOff[mi] = sm0 + r * 128 + ((laneH ^ (r & 7)) * 16);
    }
#pragma unroll
    for (int nb = 0; nb < 2; nb++) {
        int r = wn + nb * 16 + laneR;
        bOff[nb] = sm0 + 16384 + r * 128 + ((laneH ^ (r & 7)) * 16);
    }

    for (int ch = 0; ch < NCH; ch++) {
        if (ch + 1 < NCH) {
            load_stage((ch + 1) & 1, ch + 1);
            asm volatile("cp.async.wait_group 1;\n" ::: "memory");
        } else {
            asm volatile("cp.async.wait_group 0;\n" ::: "memory");
        }
        __syncthreads();

        uint32_t soff = (uint32_t)(ch & 1) * ST1_BYTES;
#pragma unroll
        for (int kk = 0; kk < 4; kk++) {
            uint32_t kx = kk * 32;
            uint32_t ah[4][4];
#pragma unroll
            for (int mi = 0; mi < 4; mi++)
                ldm_x4(ah[mi], (aOff[mi] + soff) ^ kx);
#pragma unroll
            for (int nb = 0; nb < 2; nb++) {
                uint32_t bh[4];
                ldm_x4(bh, (bOff[nb] + soff) ^ kx);
#pragma unroll
                for (int mi = 0; mi < 4; mi++)
#pragma unroll
                    for (int sub = 0; sub < 2; sub++) {
                        int ni = nb * 2 + sub;
                        uint32_t fh[2] = { bh[sub], bh[2 + sub] };
                        mma16816(acc[mi][ni], ah[mi], fh);
                    }
            }
        }
        __syncthreads();
    }

    int row = lane >> 2;
    int col = (lane & 3) * 2;
#pragma unroll
    for (int mi = 0; mi < 4; mi++)
#pragma unroll
        for (int ni = 0; ni < 4; ni++) {
            float* c0 = C + (size_t)(bm + wm + mi * 16 + row) * N + bn + wn + ni * 8 + col;
            c0[0] = acc[mi][ni][0];
            c0[1] = acc[mi][ni][1];
            float* c1 = c0 + 8 * (size_t)N;
            c1[0] = acc[mi][ni][2];
            c1[1] = acc[mi][ni][3];
        }
}

// ---------------- RoPE table: fp64 reduce, fp32 sincos -----------------------
__global__ void rope_table(const int* __restrict__ pos) {
    int idx = blockIdx.x * blockDim.x + threadIdx.x;
    if (idx >= MROWS * 64) return;
    int i   = idx & 63;
    int row = idx >> 6;
    double inv = exp(-(double)(2 * i) / 128.0 * log(10000.0));
    double ang = (double)pos[row] * inv;
    float a = (float)fmod(ang, 6.283185307179586476925287);
    g_cos[idx] = __cosf(a);
    g_sin[idx] = __sinf(a);
}

// ---------------- fused RoPE + fp16 hi/lo split (q and k in one pass) --------
__global__ void rope_split_qk() {
    int idx = blockIdx.x * blockDim.x + threadIdx.x;
    const int total = MROWS * (NH + NKV) * 64;
    if (idx >= total) return;
    int i    = idx & 63;
    int head = (idx >> 6) % (NH + NKV);
    int row  = idx / (64 * (NH + NKV));
    float c = g_cos[row * 64 + i];
    float s = g_sin[row * 64 + i];
    if (head < NH) {
        size_t o = (size_t)row * NH * HD + head * HD;
        float x1 = g_q[o + i], x2 = g_q[o + i + 64];
        float y1 = (x1 * c - x2 * s) * QSCALE;
        float y2 = (x2 * c + x1 * s) * QSCALE;
        __half h1 = __float2half(y1), h2 = __float2half(y2);
        g_qh[o + i] = h1;      g_ql[o + i]      = __float2half(y1 - __half2float(h1));
        g_qh[o + i + 64] = h2; g_ql[o + i + 64] = __float2half(y2 - __half2float(h2));
    } else {
        size_t o = (size_t)row * NKV * HD + (head - NH) * HD;
        float x1 = g_k[o + i], x2 = g_k[o + i + 64];
        float y1 = x1 * c - x2 * s;
        float y2 = x2 * c + x1 * s;
        __half h1 = __float2half(y1), h2 = __float2half(y2);
        g_kh[o + i] = h1;      g_kl[o + i]      = __float2half(y1 - __half2float(h1));
        g_kh[o + i + 64] = h2; g_kl[o + i + 64] = __float2half(y2 - __half2float(h2));
    }
}

// ---------------- V transpose: g_v -> Vt[b][kvh][d][s] fp16 (hi only) --------
__global__ __launch_bounds__(256) void split_vt() {
    __shared__ float sv[64][129];
    int blk = blockIdx.x;
    int st  = blk & 31;
    int kvh = (blk >> 5) & 7;
    int b   = blk >> 8;
    int tid = threadIdx.x;
#pragma unroll
    for (int it = 0; it < 32; it++) {
        int idx = it * 256 + tid;
        int r = idx >> 7, c = idx & 127;
        sv[r][c] = g_v[(size_t)(b * SS + st * 64 + r) * (NKV * HD) + kvh * HD + c];
    }
    __syncthreads();
    int d = tid >> 1, j = tid & 1;
    __half hbuf[32];
#pragma unroll
    for (int q = 0; q < 32; q++)
        hbuf[q] = __float2half(sv[j * 32 + q][d]);
    size_t base = ((size_t)(b * NKV + kvh) * HD + d) * SS + st * 64 + j * 32;
    uint4* dh = (uint4*)(g_vth + base);
#pragma unroll
    for (int q = 0; q < 4; q++)
        dh[q] = ((uint4*)hbuf)[q];
}

// ---------------------------------------------------------------------------
// HMMA flash attention: Br=128 (8 warps), Bc=64; QK 3-term, PV 2-term (P split).
// smem: Qh/Ql 32KB each, Kh/Kl 16KB each, Vh 16KB -> 112KB.
// ---------------------------------------------------------------------------
#define SQH 0
#define SQL 32768
#define SKH 65536
#define SKL 81920
#define SVH 98304
#define FL_SMEM 114688

__global__ __launch_bounds__(256) void flash_mma(
    const __half* __restrict__ Qh_g, const __half* __restrict__ Ql_g,
    const __half* __restrict__ Kh_g, const __half* __restrict__ Kl_g,
    const __half* __restrict__ Vth_g,
    __half* __restrict__ out) {
    uint32_t s0 = smem_u32(dyn_smem);

    int qt = blockIdx.x, h = blockIdx.y, b = blockIdx.z;
    int kvh = h >> 2;
    int t = threadIdx.x, wid = t >> 5, lane = t & 31;
    int laneR = lane & 15, laneH = lane >> 4;
    int wm = wid * 16;

#pragma unroll
    for (int i = 0; i < 8; i++) {
        int idx = i * 256 + t;
        int r = idx >> 4, c = idx & 15;
        uint32_t d = r * 256 + ((c ^ (r & 7)) * 16);
        size_t g = ((size_t)(b * SS + qt * 128 + r)) * (NH * HD) + h * HD + c * 8;
        cp16(s0 + SQH + d, Qh_g + g);
        cp16(s0 + SQL + d, Ql_g + g);
    }
    auto loadKV = [&](int kt) {
#pragma unroll
        for (int i = 0; i < 4; i++) {
            int idx = i * 256 + t;
            int r = idx >> 4, c = idx & 15;
            uint32_t d = r * 256 + ((c ^ (r & 7)) * 16);
            size_t g = ((size_t)(b * SS + kt * 64 + r)) * (NKV * HD) + kvh * HD + c * 8;
            cp16(s0 + SKH + d, Kh_g + g);
            cp16(s0 + SKL + d, Kl_g + g);
        }
#pragma unroll
        for (int i = 0; i < 4; i++) {
            int idx = i * 256 + t;
            int r = idx >> 3, c = idx & 7;
            uint32_t d = r * 128 + ((c ^ (r & 7)) * 16);
            size_t g = ((size_t)((b * NKV + kvh) * HD + r)) * SS + kt * 64 + c * 8;
            cp16(s0 + SVH + d, Vth_g + g);
        }
    };
    loadKV(0);
    cp_commit();

    float o_[16][4];
#pragma unroll
    for (int n = 0; n < 16; n++)
#pragma unroll
        for (int c = 0; c < 4; c++) o_[n][c] = 0.f;
    float m0 = -1e30f, m1 = -1e30f, l0 = 0.f, l1 = 0.f;
    int r0 = lane >> 2;
    int qrow0 = qt * 128 + wm + r0;
    int qrow1 = qrow0 + 8;
    const int KTMAX = 2 * qt + 1;

    for (int kt = 0; kt <= KTMAX; kt++) {
        asm volatile("cp.async.wait_group 0;\n" ::: "memory");
        __syncthreads();

        float s[8][4];
#pragma unroll
        for (int j = 0; j < 8; j++)
#pragma unroll
            for (int c = 0; c < 4; c++) s[j][c] = 0.f;

#pragma unroll
        for (int kk = 0; kk < 8; kk++) {
            uint32_t qa[4], qb[4];
            {
                int r = wm + laneR;
                uint32_t ph = (uint32_t)(((kk * 2 + laneH) ^ (r & 7)) * 16);
                ldm_x4(qa, s0 + SQH + r * 256 + ph);
                ldm_x4(qb, s0 + SQL + r * 256 + ph);
            }
#pragma unroll
            for (int jj = 0; jj < 4; jj++) {
                uint32_t kh_[4], kl_[4];
                int r = jj * 16 + laneR;
                uint32_t ph = (uint32_t)(((kk * 2 + laneH) ^ (r & 7)) * 16);
                ldm_x4(kh_, s0 + SKH + r * 256 + ph);
                ldm_x4(kl_, s0 + SKL + r * 256 + ph);
#pragma unroll
                for (int sub = 0; sub < 2; sub++) {
                    int j = jj * 2 + sub;
                    uint32_t fh[2] = { kh_[sub], kh_[2 + sub] };
                    uint32_t fl[2] = { kl_[sub], kl_[2 + sub] };
                    mma16816(s[j], qa, fh);
                    mma16816(s[j], qa, fl);
                    mma16816(s[j], qb, fh);
                }
            }
        }

        if (kt * 64 + 63 > qrow0) {
#pragma unroll
            for (int j = 0; j < 8; j++) {
                int cb = kt * 64 + j * 8 + (lane & 3) * 2;
                if (cb     > qrow0) s[j][0] = -1e30f;
                if (cb + 1 > qrow0) s[j][1] = -1e30f;
                if (cb     > qrow1) s[j][2] = -1e30f;
                if (cb + 1 > qrow1) s[j][3] = -1e30f;
            }
        }

        float rm0 = -1e30f, rm1 = -1e30f;
#pragma unroll
        for (int j = 0; j < 8; j++) {
            rm0 = fmaxf(rm0, fmaxf(s[j][0], s[j][1]));
            rm1 = fmaxf(rm1, fmaxf(s[j][2], s[j][3]));
        }
        rm0 = fmaxf(rm0, __shfl_xor_sync(0xffffffffu, rm0, 1));
        rm0 = fmaxf(rm0, __shfl_xor_sync(0xffffffffu, rm0, 2));
        rm1 = fmaxf(rm1, __shfl_xor_sync(0xffffffffu, rm1, 1));
        rm1 = fmaxf(rm1, __shfl_xor_sync(0xffffffffu, rm1, 2));
        float mn0 = fmaxf(m0, rm0), mn1 = fmaxf(m1, rm1);
        float a0 = __expf(m0 - mn0), a1 = __expf(m1 - mn1);
        l0 *= a0; l1 *= a1;
#pragma unroll
        for (int n = 0; n < 16; n++) {
            o_[n][0] *= a0; o_[n][1] *= a0;
            o_[n][2] *= a1; o_[n][3] *= a1;
        }
        m0 = mn0; m1 = mn1;

        uint32_t ph0[8], ph1[8], pl0[8], pl1[8];
        float sum0 = 0.f, sum1 = 0.f;
#pragma unroll
        for (int j = 0; j < 8; j++) {
            float e0 = __expf(s[j][0] - mn0), e1 = __expf(s[j][1] - mn0);
            float e2 = __expf(s[j][2] - mn1), e3 = __expf(s[j][3] - mn1);
            sum0 += e0 + e1; sum1 += e2 + e3;
            __half2 hh0 = __floats2half2_rn(e0, e1);
            __half2 hh1 = __floats2half2_rn(e2, e3);
            ph0[j] = *(uint32_t*)&hh0;
            ph1[j] = *(uint32_t*)&hh1;
            __half2 dd0 = __floats2half2_rn(e0 - __low2float(hh0), e1 - __high2float(hh0));
            __half2 dd1 = __floats2half2_rn(e2 - __low2float(hh1), e3 - __high2float(hh1));
            pl0[j] = *(uint32_t*)&dd0;
            pl1[j] = *(uint32_t*)&dd1;
        }
        sum0 += __shfl_xor_sync(0xffffffffu, sum0, 1);
        sum0 += __shfl_xor_sync(0xffffffffu, sum0, 2);
        sum1 += __shfl_xor_sync(0xffffffffu, sum1, 1);
        sum1 += __shfl_xor_sync(0xffffffffu, sum1, 2);
        l0 += sum0; l1 += sum1;

#pragma unroll
        for (int tt = 0; tt < 4; tt++) {
            uint32_t pa[4] = { ph0[2*tt], ph1[2*tt], ph0[2*tt+1], ph1[2*tt+1] };
            uint32_t pb[4] = { pl0[2*tt], pl1[2*tt], pl0[2*tt+1], pl1[2*tt+1] };
#pragma unroll
            for (int dg = 0; dg < 8; dg++) {
                uint32_t vh_[4];
                int r = dg * 16 + laneR;
                uint32_t ph = (uint32_t)(((tt * 2 + laneH) ^ (r & 7)) * 16);
                ldm_x4(vh_, s0 + SVH + r * 128 + ph);
#pragma unroll
                for (int sub = 0; sub < 2; sub++) {
                    int n = dg * 2 + sub;
                    uint32_t fh[2] = { vh_[sub], vh_[2 + sub] };
                    mma16816(o_[n], pa, fh);
                    mma16816(o_[n], pb, fh);
                }
            }
        }

        __syncthreads();
        if (kt + 1 <= KTMAX) {
            loadKV(kt + 1);
            cp_commit();
        }
    }

    float il0 = 1.f / l0, il1 = 1.f / l1;
    size_t ob0 = (size_t)(b * SS + qrow0) * (NH * HD) + h * HD + (lane & 3) * 2;
    size_t ob1 = (size_t)(b * SS + qrow1) * (NH * HD) + h * HD + (lane & 3) * 2;
#pragma unroll
    for (int n = 0; n < 16; n++) {
        __half2 w0 = __floats2half2_rn(o_[n][0] * il0, o_[n][1] * il0);
        __half2 w1 = __floats2half2_rn(o_[n][2] * il1, o_[n][3] * il1);
        *(__half2*)(out + ob0 + n * 8) = w0;
        *(__half2*)(out + ob1 + n * 8) = w1;
    }
}

// ---------------------------------------------------------------------------
extern "C" void kernel_launch(void* const* d_in, const int* in_sizes, int n_in,
                              void* d_out, int out_size) {
    const float* hid = (const float*)d_in[0];
    const int*   pos = (const int*)d_in[1];
    const float* Wq  = (const float*)d_in[2];
    const float* Wk  = (const float*)d_in[3];
    const float* Wv  = (const float*)d_in[4];
    const float* Wo  = (const float*)d_in[5];
    float* out = (float*)d_out;

    float *pq, *pk, *pv;
    cudaGetSymbolAddress((void**)&pq, g_q);
    cudaGetSymbolAddress((void**)&pk, g_k);
    cudaGetSymbolAddress((void**)&pv, g_v);
    __half *hf, *af, *qh, *ql, *kh, *kl, *vh, *vl, *oh;
    __half *fqh, *fql, *fkh, *fkl, *fvh;
    cudaGetSymbolAddress((void**)&hf, g_hid_f16);
    cudaGetSymbolAddress((void**)&af, g_at_f16);
    cudaGetSymbolAddress((void**)&qh, g_wq_h);  cudaGetSymbolAddress((void**)&ql, g_wq_l);
    cudaGetSymbolAddress((void**)&kh, g_wk_h);  cudaGetSymbolAddress((void**)&kl, g_wk_l);
    cudaGetSymbolAddress((void**)&vh, g_wv_h);  cudaGetSymbolAddress((void**)&vl, g_wv_l);
    cudaGetSymbolAddress((void**)&oh, g_wo_h);
    cudaGetSymbolAddress((void**)&fqh, g_qh);   cudaGetSymbolAddress((void**)&fql, g_ql);
    cudaGetSymbolAddress((void**)&fkh, g_kh);   cudaGetSymbolAddress((void**)&fkl, g_kl);
    cudaGetSymbolAddress((void**)&fvh, g_vth);

    const int nHid = MROWS * DMODEL;
    const int nPrep = 2 * NW1 + 2 * NW2;
    tofp16<<<(nHid + 255) / 256, 256>>>(hid, hf, nHid);
    prep_weights<<<(nPrep + 255) / 256, 256>>>(Wq, Wk, Wv, Wo);
    rope_table<<<(MROWS*64 + 255)/256, 256>>>(pos);

    cudaFuncSetAttribute(gemm_qkv, cudaFuncAttributeMaxDynamicSharedMemorySize, GK_SMEM);
    cudaFuncSetAttribute(gemm_mma1, cudaFuncAttributeMaxDynamicSharedMemorySize, GK1_SMEM);

    gemm_qkv<<<dim3(48, MROWS/BM), 256, GK_SMEM>>>(hf, qh, ql, kh, kl, vh, vl, pq, pk, pv);

    rope_split_qk<<<(MROWS*(NH+NKV)*64 + 255)/256, 256>>>();
    split_vt<<<BB*NKV*32, 256>>>();

    cudaFuncSetAttribute(flash_mma, cudaFuncAttributeMaxDynamicSharedMemorySize, FL_SMEM);
    flash_mma<<<dim3(SS/128, NH, BB), 256, FL_SMEM>>>(fqh, fql, fkh, fkl, fvh, af);

    gemm_mma1<<<dim3(NH*HD/BN, MROWS/BM), 256, GK1_SMEM>>>(af, oh, out, MROWS, NH*HD, NH*HD);
}

// round 13
// speedup vs baseline: 13.5991x; 1.2659x over previous
#include <cuda_runtime.h>
#include <cuda_fp16.h>
#include <math.h>
#include <stdint.h>

#define BB 2
#define SS 2048
#define DMODEL 4096
#define NH 32
#define NKV 8
#define HD 128
#define MROWS (BB*SS)   // 4096
#define QSCALE 0.08838834764831845f

extern __shared__ char dyn_smem[];

// ---------------- scratch (device globals; no allocation allowed) ----------
__device__ float g_q[(size_t)MROWS * NH * HD];
__device__ float g_k[(size_t)MROWS * NKV * HD];
__device__ float g_v[(size_t)MROWS * NKV * HD];
__device__ float g_cos[MROWS * (HD/2)];
__device__ float g_sin[MROWS * (HD/2)];

// fp16 operands (weights hi only)
__device__ __half g_hid_f16[(size_t)MROWS * DMODEL];
__device__ __half g_at_f16[(size_t)MROWS * NH*HD];
__device__ __half g_wq_h[(size_t)NH*HD * DMODEL];
__device__ __half g_wk_h[(size_t)NKV*HD * DMODEL];
__device__ __half g_wv_h[(size_t)NKV*HD * DMODEL];
__device__ __half g_wo_h[(size_t)NH*HD * NH*HD];

// fp16 attention operands (post-rope, split)
__device__ __half g_qh[(size_t)MROWS * NH * HD];
__device__ __half g_ql[(size_t)MROWS * NH * HD];
__device__ __half g_kh[(size_t)MROWS * NKV * HD];
__device__ __half g_kl[(size_t)MROWS * NKV * HD];
__device__ __half g_vth[(size_t)BB * NKV * HD * SS];  // [b][kvh][d][s]

// ---------------- PTX helpers (sm_80+ base-target safe) ---------------------
__device__ __forceinline__ uint32_t smem_u32(const void* p) {
    uint32_t a;
    asm("{ .reg .u64 t; cvta.to.shared.u64 t, %1; cvt.u32.u64 %0, t; }" : "=r"(a) : "l"(p));
    return a;
}
__device__ __forceinline__ void cp16(uint32_t dst, const void* src) {
    asm volatile("cp.async.cg.shared.global [%0], [%1], 16;\n" :: "r"(dst), "l"(src));
}
__device__ __forceinline__ void cp_commit() { asm volatile("cp.async.commit_group;\n" ::: "memory"); }

__device__ __forceinline__ void ldm_x4(uint32_t* r, uint32_t addr) {
    asm volatile("ldmatrix.sync.aligned.m8n8.x4.shared.b16 {%0,%1,%2,%3}, [%4];"
        : "=r"(r[0]), "=r"(r[1]), "=r"(r[2]), "=r"(r[3]) : "r"(addr));
}
__device__ __forceinline__ void mma16816(float* d, const uint32_t* a, const uint32_t* b) {
    asm volatile("mma.sync.aligned.m16n8k16.row.col.f32.f16.f16.f32 "
        "{%0,%1,%2,%3}, {%4,%5,%6,%7}, {%8,%9}, {%0,%1,%2,%3};"
        : "+f"(d[0]), "+f"(d[1]), "+f"(d[2]), "+f"(d[3])
        : "r"(a[0]), "r"(a[1]), "r"(a[2]), "r"(a[3]), "r"(b[0]), "r"(b[1]));
}

// ---------------- conversion kernels ----------------------------------------
__global__ void tofp16(const float* __restrict__ s, __half* __restrict__ d, int n) {
    int i = blockIdx.x * blockDim.x + threadIdx.x;
    if (i < n) d[i] = __float2half(s[i]);
}

#define NW1 (NH*HD*DMODEL)
#define NW2 (NKV*HD*DMODEL)
__global__ void prep_weights(const float* __restrict__ Wq, const float* __restrict__ Wk,
                             const float* __restrict__ Wv, const float* __restrict__ Wo) {
    int i = blockIdx.x * blockDim.x + threadIdx.x;
    if (i < NW1) {
        g_wq_h[i] = __float2half(Wq[i]);
    } else if (i < NW1 + NW2) {
        int j = i - NW1;
        g_wk_h[j] = __float2half(Wk[j]);
    } else if (i < NW1 + 2*NW2) {
        int j = i - NW1 - NW2;
        g_wv_h[j] = __float2half(Wv[j]);
    } else if (i < 2*NW1 + 2*NW2) {
        int j = i - NW1 - 2*NW2;
        g_wo_h[j] = __float2half(Wo[j]);
    }
}

// ---------------------------------------------------------------------------
// Single-term fp16 GEMM core (NT). CTA 128x128, 8 warps (2x4, warp tile
// 64x32), BK=64, 3-stage cp.async, 2 CTAs/SM. 128B-row XOR swizzle both mats.
// ---------------------------------------------------------------------------
#define BM 128
#define BN 128
#define ST1_BYTES 32768                 // A 16K + B 16K
#define GK1_SMEM (3*ST1_BYTES + 128)    // 98432

__device__ __forceinline__ void gemm1_core(
    const __half* __restrict__ A, const __half* __restrict__ B,
    float* __restrict__ C, int bm, int bn, int N, int K) {
    uint32_t sm0 = (smem_u32(dyn_smem) + 127) & ~127u;

    int t = threadIdx.x;
    int wid = t >> 5, lane = t & 31;
    int wm = (wid >> 2) * 64;
    int wn = (wid & 3) * 32;

    float acc[4][4][4];
#pragma unroll
    for (int a = 0; a < 4; a++)
#pragma unroll
        for (int b = 0; b < 4; b++)
#pragma unroll
            for (int c = 0; c < 4; c++) acc[a][b][c] = 0.f;

    auto load_stage = [&](int s, int ck) {
        int k0 = ck * 64;
        uint32_t sb = sm0 + s * ST1_BYTES;
#pragma unroll
        for (int i = 0; i < 4; i++) {
            int idx = i * 256 + t;
            int r = idx >> 3, c = idx & 7;
            cp16(sb + r * 128 + ((c ^ (r & 7)) * 16),
                 A + (size_t)(bm + r) * K + k0 + c * 8);
        }
        uint32_t sbB = sb + 16384;
#pragma unroll
        for (int i = 0; i < 4; i++) {
            int idx = i * 256 + t;
            int r = idx >> 3, c = idx & 7;
            cp16(sbB + r * 128 + ((c ^ (r & 7)) * 16),
                 B + (size_t)(bn + r) * K + k0 + c * 8);
        }
        cp_commit();
    };

    const int NCH = K >> 6;
    load_stage(0, 0);
    load_stage(1, 1);

    int laneR = lane & 15, laneH = lane >> 4;
    uint32_t aOff[4], bOff[2];
#pragma unroll
    for (int mi = 0; mi < 4; mi++) {
        int r = wm + mi * 16 + laneR;
        aOff[mi] = sm0 + r * 128 + ((laneH ^ (r & 7)) * 16);
    }
#pragma unroll
    for (int nb = 0; nb < 2; nb++) {
        int r = wn + nb * 16 + laneR;
        bOff[nb] = sm0 + 16384 + r * 128 + ((laneH ^ (r & 7)) * 16);
    }

    for (int ch = 0; ch < NCH; ch++) {
        if (ch + 2 < NCH) {
            load_stage((ch + 2) % 3, ch + 2);
            asm volatile("cp.async.wait_group 2;\n" ::: "memory");
        } else if (ch + 1 < NCH) {
            asm volatile("cp.async.wait_group 1;\n" ::: "memory");
        } else {
            asm volatile("cp.async.wait_group 0;\n" ::: "memory");
        }
        __syncthreads();

        uint32_t soff = (uint32_t)(ch % 3) * ST1_BYTES;
#pragma unroll
        for (int kk = 0; kk < 4; kk++) {
            uint32_t kx = kk * 32;
            uint32_t ah[4][4];
#pragma unroll
            for (int mi = 0; mi < 4; mi++)
                ldm_x4(ah[mi], (aOff[mi] + soff) ^ kx);
#pragma unroll
            for (int nb = 0; nb < 2; nb++) {
                uint32_t bh[4];
                ldm_x4(bh, (bOff[nb] + soff) ^ kx);
#pragma unroll
                for (int mi = 0; mi < 4; mi++)
#pragma unroll
                    for (int sub = 0; sub < 2; sub++) {
                        int ni = nb * 2 + sub;
                        uint32_t fh[2] = { bh[sub], bh[2 + sub] };
                        mma16816(acc[mi][ni], ah[mi], fh);
                    }
            }
        }
        __syncthreads();
    }

    int row = lane >> 2;
    int col = (lane & 3) * 2;
#pragma unroll
    for (int mi = 0; mi < 4; mi++)
#pragma unroll
        for (int ni = 0; ni < 4; ni++) {
            float* c0 = C + (size_t)(bm + wm + mi * 16 + row) * N + bn + wn + ni * 8 + col;
            c0[0] = acc[mi][ni][0];
            c0[1] = acc[mi][ni][1];
            float* c1 = c0 + 8 * (size_t)N;
            c1[0] = acc[mi][ni][2];
            c1[1] = acc[mi][ni][3];
        }
}

// fused QKV: 48 N-tiles (32 Q, 8 K, 8 V), one launch, single-term
__global__ __launch_bounds__(256, 2)
void gemm_qkv(const __half* __restrict__ A,
              const __half* __restrict__ Wqh, const __half* __restrict__ Wkh,
              const __half* __restrict__ Wvh,
              float* __restrict__ pq, float* __restrict__ pk, float* __restrict__ pv) {
    int tx = blockIdx.x;
    const __half* Bh; float* C; int N, bn;
    if (tx < 32)      { Bh = Wqh; C = pq; N = NH*HD;  bn = tx * 128; }
    else if (tx < 40) { Bh = Wkh; C = pk; N = NKV*HD; bn = (tx - 32) * 128; }
    else              { Bh = Wvh; C = pv; N = NKV*HD; bn = (tx - 40) * 128; }
    gemm1_core(A, Bh, C, blockIdx.y * BM, bn, N, DMODEL);
}

__global__ __launch_bounds__(256, 2)
void gemm_mma1(const __half* __restrict__ A, const __half* __restrict__ B,
               float* __restrict__ C, int M, int N, int K) {
    gemm1_core(A, B, C, blockIdx.y * BM, blockIdx.x * BN, N, K);
}

// ---------------- RoPE table: fp64 reduce, fp32 sincos -----------------------
__global__ void rope_table(const int* __restrict__ pos) {
    int idx = blockIdx.x * blockDim.x + threadIdx.x;
    if (idx >= MROWS * 64) return;
    int i   = idx & 63;
    int row = idx >> 6;
    double inv = exp(-(double)(2 * i) / 128.0 * log(10000.0));
    double ang = (double)pos[row] * inv;
    float a = (float)fmod(ang, 6.283185307179586476925287);
    g_cos[idx] = __cosf(a);
    g_sin[idx] = __sinf(a);
}

// ---------------- fused RoPE + fp16 hi/lo split (q and k in one pass) --------
__global__ void rope_split_qk() {
    int idx = blockIdx.x * blockDim.x + threadIdx.x;
    const int total = MROWS * (NH + NKV) * 64;
    if (idx >= total) return;
    int i    = idx & 63;
    int head = (idx >> 6) % (NH + NKV);
    int row  = idx / (64 * (NH + NKV));
    float c = g_cos[row * 64 + i];
    float s = g_sin[row * 64 + i];
    if (head < NH) {
        size_t o = (size_t)row * NH * HD + head * HD;
        float x1 = g_q[o + i], x2 = g_q[o + i + 64];
        float y1 = (x1 * c - x2 * s) * QSCALE;
        float y2 = (x2 * c + x1 * s) * QSCALE;
        __half h1 = __float2half(y1), h2 = __float2half(y2);
        g_qh[o + i] = h1;      g_ql[o + i]      = __float2half(y1 - __half2float(h1));
        g_qh[o + i + 64] = h2; g_ql[o + i + 64] = __float2half(y2 - __half2float(h2));
    } else {
        size_t o = (size_t)row * NKV * HD + (head - NH) * HD;
        float x1 = g_k[o + i], x2 = g_k[o + i + 64];
        float y1 = x1 * c - x2 * s;
        float y2 = x2 * c + x1 * s;
        __half h1 = __float2half(y1), h2 = __float2half(y2);
        g_kh[o + i] = h1;      g_kl[o + i]      = __float2half(y1 - __half2float(h1));
        g_kh[o + i + 64] = h2; g_kl[o + i + 64] = __float2half(y2 - __half2float(h2));
    }
}

// ---------------- V transpose: g_v -> Vt[b][kvh][d][s] fp16 (hi only) --------
__global__ __launch_bounds__(256) void split_vt() {
    __shared__ float sv[64][129];
    int blk = blockIdx.x;
    int st  = blk & 31;
    int kvh = (blk >> 5) & 7;
    int b   = blk >> 8;
    int tid = threadIdx.x;
#pragma unroll
    for (int it = 0; it < 32; it++) {
        int idx = it * 256 + tid;
        int r = idx >> 7, c = idx & 127;
        sv[r][c] = g_v[(size_t)(b * SS + st * 64 + r) * (NKV * HD) + kvh * HD + c];
    }
    __syncthreads();
    int d = tid >> 1, j = tid & 1;
    __half hbuf[32];
#pragma unroll
    for (int q = 0; q < 32; q++)
        hbuf[q] = __float2half(sv[j * 32 + q][d]);
    size_t base = ((size_t)(b * NKV + kvh) * HD + d) * SS + st * 64 + j * 32;
    uint4* dh = (uint4*)(g_vth + base);
#pragma unroll
    for (int q = 0; q < 4; q++)
        dh[q] = ((uint4*)hbuf)[q];
}

// ---------------------------------------------------------------------------
// HMMA flash attention: Br=128 (8 warps), Bc=64; QK 3-term, PV 2-term (P split).
// smem: Qh/Ql 32KB each, Kh/Kl 16KB each, Vh 16KB -> 112KB.
// ---------------------------------------------------------------------------
#define SQH 0
#define SQL 32768
#define SKH 65536
#define SKL 81920
#define SVH 98304
#define FL_SMEM 114688

__global__ __launch_bounds__(256) void flash_mma(
    const __half* __restrict__ Qh_g, const __half* __restrict__ Ql_g,
    const __half* __restrict__ Kh_g, const __half* __restrict__ Kl_g,
    const __half* __restrict__ Vth_g,
    __half* __restrict__ out) {
    uint32_t s0 = smem_u32(dyn_smem);

    int qt = blockIdx.x, h = blockIdx.y, b = blockIdx.z;
    int kvh = h >> 2;
    int t = threadIdx.x, wid = t >> 5, lane = t & 31;
    int laneR = lane & 15, laneH = lane >> 4;
    int wm = wid * 16;

#pragma unroll
    for (int i = 0; i < 8; i++) {
        int idx = i * 256 + t;
        int r = idx >> 4, c = idx & 15;
        uint32_t d = r * 256 + ((c ^ (r & 7)) * 16);
        size_t g = ((size_t)(b * SS + qt * 128 + r)) * (NH * HD) + h * HD + c * 8;
        cp16(s0 + SQH + d, Qh_g + g);
        cp16(s0 + SQL + d, Ql_g + g);
    }
    auto loadKV = [&](int kt) {
#pragma unroll
        for (int i = 0; i < 4; i++) {
            int idx = i * 256 + t;
            int r = idx >> 4, c = idx & 15;
            uint32_t d = r * 256 + ((c ^ (r & 7)) * 16);
            size_t g = ((size_t)(b * SS + kt * 64 + r)) * (NKV * HD) + kvh * HD + c * 8;
            cp16(s0 + SKH + d, Kh_g + g);
            cp16(s0 + SKL + d, Kl_g + g);
        }
#pragma unroll
        for (int i = 0; i < 4; i++) {
            int idx = i * 256 + t;
            int r = idx >> 3, c = idx & 7;
            uint32_t d = r * 128 + ((c ^ (r & 7)) * 16);
            size_t g = ((size_t)((b * NKV + kvh) * HD + r)) * SS + kt * 64 + c * 8;
            cp16(s0 + SVH + d, Vth_g + g);
        }
    };
    loadKV(0);
    cp_commit();

    float o_[16][4];
#pragma unroll
    for (int n = 0; n < 16; n++)
#pragma unroll
        for (int c = 0; c < 4; c++) o_[n][c] = 0.f;
    float m0 = -1e30f, m1 = -1e30f, l0 = 0.f, l1 = 0.f;
    int r0 = lane >> 2;
    int qrow0 = qt * 128 + wm + r0;
    int qrow1 = qrow0 + 8;
    const int KTMAX = 2 * qt + 1;

    for (int kt = 0; kt <= KTMAX; kt++) {
        asm volatile("cp.async.wait_group 0;\n" ::: "memory");
        __syncthreads();

        float s[8][4];
#pragma unroll
        for (int j = 0; j < 8; j++)
#pragma unroll
            for (int c = 0; c < 4; c++) s[j][c] = 0.f;

#pragma unroll
        for (int kk = 0; kk < 8; kk++) {
            uint32_t qa[4], qb[4];
            {
                int r = wm + laneR;
                uint32_t ph = (uint32_t)(((kk * 2 + laneH) ^ (r & 7)) * 16);
                ldm_x4(qa, s0 + SQH + r * 256 + ph);
                ldm_x4(qb, s0 + SQL + r * 256 + ph);
            }
#pragma unroll
            for (int jj = 0; jj < 4; jj++) {
                uint32_t kh_[4], kl_[4];
                int r = jj * 16 + laneR;
                uint32_t ph = (uint32_t)(((kk * 2 + laneH) ^ (r & 7)) * 16);
                ldm_x4(kh_, s0 + SKH + r * 256 + ph);
                ldm_x4(kl_, s0 + SKL + r * 256 + ph);
#pragma unroll
                for (int sub = 0; sub < 2; sub++) {
                    int j = jj * 2 + sub;
                    uint32_t fh[2] = { kh_[sub], kh_[2 + sub] };
                    uint32_t fl[2] = { kl_[sub], kl_[2 + sub] };
                    mma16816(s[j], qa, fh);
                    mma16816(s[j], qa, fl);
                    mma16816(s[j], qb, fh);
                }
            }
        }

        if (kt * 64 + 63 > qrow0) {
#pragma unroll
            for (int j = 0; j < 8; j++) {
                int cb = kt * 64 + j * 8 + (lane & 3) * 2;
                if (cb     > qrow0) s[j][0] = -1e30f;
                if (cb + 1 > qrow0) s[j][1] = -1e30f;
                if (cb     > qrow1) s[j][2] = -1e30f;
                if (cb + 1 > qrow1) s[j][3] = -1e30f;
            }
        }

        float rm0 = -1e30f, rm1 = -1e30f;
#pragma unroll
        for (int j = 0; j < 8; j++) {
            rm0 = fmaxf(rm0, fmaxf(s[j][0], s[j][1]));
            rm1 = fmaxf(rm1, fmaxf(s[j][2], s[j][3]));
        }
        rm0 = fmaxf(rm0, __shfl_xor_sync(0xffffffffu, rm0, 1));
        rm0 = fmaxf(rm0, __shfl_xor_sync(0xffffffffu, rm0, 2));
        rm1 = fmaxf(rm1, __shfl_xor_sync(0xffffffffu, rm1, 1));
        rm1 = fmaxf(rm1, __shfl_xor_sync(0xffffffffu, rm1, 2));
        float mn0 = fmaxf(m0, rm0), mn1 = fmaxf(m1, rm1);
        float a0 = __expf(m0 - mn0), a1 = __expf(m1 - mn1);
        l0 *= a0; l1 *= a1;
#pragma unroll
        for (int n = 0; n < 16; n++) {
            o_[n][0] *= a0; o_[n][1] *= a0;
            o_[n][2] *= a1; o_[n][3] *= a1;
        }
        m0 = mn0; m1 = mn1;

        uint32_t ph0[8], ph1[8], pl0[8], pl1[8];
        float sum0 = 0.f, sum1 = 0.f;
#pragma unroll
        for (int j = 0; j < 8; j++) {
            float e0 = __expf(s[j][0] - mn0), e1 = __expf(s[j][1] - mn0);
            float e2 = __expf(s[j][2] - mn1), e3 = __expf(s[j][3] - mn1);
            sum0 += e0 + e1; sum1 += e2 + e3;
            __half2 hh0 = __floats2half2_rn(e0, e1);
            __half2 hh1 = __floats2half2_rn(e2, e3);
            ph0[j] = *(uint32_t*)&hh0;
            ph1[j] = *(uint32_t*)&hh1;
            __half2 dd0 = __floats2half2_rn(e0 - __low2float(hh0), e1 - __high2float(hh0));
            __half2 dd1 = __floats2half2_rn(e2 - __low2float(hh1), e3 - __high2float(hh1));
            pl0[j] = *(uint32_t*)&dd0;
            pl1[j] = *(uint32_t*)&dd1;
        }
        sum0 += __shfl_xor_sync(0xffffffffu, sum0, 1);
        sum0 += __shfl_xor_sync(0xffffffffu, sum0, 2);
        sum1 += __shfl_xor_sync(0xffffffffu, sum1, 1);
        sum1 += __shfl_xor_sync(0xffffffffu, sum1, 2);
        l0 += sum0; l1 += sum1;

#pragma unroll
        for (int tt = 0; tt < 4; tt++) {
            uint32_t pa[4] = { ph0[2*tt], ph1[2*tt], ph0[2*tt+1], ph1[2*tt+1] };
            uint32_t pb[4] = { pl0[2*tt], pl1[2*tt], pl0[2*tt+1], pl1[2*tt+1] };
#pragma unroll
            for (int dg = 0; dg < 8; dg++) {
                uint32_t vh_[4];
                int r = dg * 16 + laneR;
                uint32_t ph = (uint32_t)(((tt * 2 + laneH) ^ (r & 7)) * 16);
                ldm_x4(vh_, s0 + SVH + r * 128 + ph);
#pragma unroll
                for (int sub = 0; sub < 2; sub++) {
                    int n = dg * 2 + sub;
                    uint32_t fh[2] = { vh_[sub], vh_[2 + sub] };
                    mma16816(o_[n], pa, fh);
                    mma16816(o_[n], pb, fh);
                }
            }
        }

        __syncthreads();
        if (kt + 1 <= KTMAX) {
            loadKV(kt + 1);
            cp_commit();
        }
    }

    float il0 = 1.f / l0, il1 = 1.f / l1;
    size_t ob0 = (size_t)(b * SS + qrow0) * (NH * HD) + h * HD + (lane & 3) * 2;
    size_t ob1 = (size_t)(b * SS + qrow1) * (NH * HD) + h * HD + (lane & 3) * 2;
#pragma unroll
    for (int n = 0; n < 16; n++) {
        __half2 w0 = __floats2half2_rn(o_[n][0] * il0, o_[n][1] * il0);
        __half2 w1 = __floats2half2_rn(o_[n][2] * il1, o_[n][3] * il1);
        *(__half2*)(out + ob0 + n * 8) = w0;
        *(__half2*)(out + ob1 + n * 8) = w1;
    }
}

// ---------------------------------------------------------------------------
extern "C" void kernel_launch(void* const* d_in, const int* in_sizes, int n_in,
                              void* d_out, int out_size) {
    const float* hid = (const float*)d_in[0];
    const int*   pos = (const int*)d_in[1];
    const float* Wq  = (const float*)d_in[2];
    const float* Wk  = (const float*)d_in[3];
    const float* Wv  = (const float*)d_in[4];
    const float* Wo  = (const float*)d_in[5];
    float* out = (float*)d_out;

    float *pq, *pk, *pv;
    cudaGetSymbolAddress((void**)&pq, g_q);
    cudaGetSymbolAddress((void**)&pk, g_k);
    cudaGetSymbolAddress((void**)&pv, g_v);
    __half *hf, *af, *qh, *kh, *vh, *oh;
    __half *fqh, *fql, *fkh, *fkl, *fvh;
    cudaGetSymbolAddress((void**)&hf, g_hid_f16);
    cudaGetSymbolAddress((void**)&af, g_at_f16);
    cudaGetSymbolAddress((void**)&qh, g_wq_h);
    cudaGetSymbolAddress((void**)&kh, g_wk_h);
    cudaGetSymbolAddress((void**)&vh, g_wv_h);
    cudaGetSymbolAddress((void**)&oh, g_wo_h);
    cudaGetSymbolAddress((void**)&fqh, g_qh);   cudaGetSymbolAddress((void**)&fql, g_ql);
    cudaGetSymbolAddress((void**)&fkh, g_kh);   cudaGetSymbolAddress((void**)&fkl, g_kl);
    cudaGetSymbolAddress((void**)&fvh, g_vth);

    const int nHid = MROWS * DMODEL;
    const int nPrep = 2 * NW1 + 2 * NW2;
    tofp16<<<(nHid + 255) / 256, 256>>>(hid, hf, nHid);
    prep_weights<<<(nPrep + 255) / 256, 256>>>(Wq, Wk, Wv, Wo);
    rope_table<<<(MROWS*64 + 255)/256, 256>>>(pos);

    cudaFuncSetAttribute(gemm_qkv, cudaFuncAttributeMaxDynamicSharedMemorySize, GK1_SMEM);
    cudaFuncSetAttribute(gemm_mma1, cudaFuncAttributeMaxDynamicSharedMemorySize, GK1_SMEM);

    gemm_qkv<<<dim3(48, MROWS/BM), 256, GK1_SMEM>>>(hf, qh, kh, vh, pq, pk, pv);

    rope_split_qk<<<(MROWS*(NH+NKV)*64 + 255)/256, 256>>>();
    split_vt<<<BB*NKV*32, 256>>>();

    cudaFuncSetAttribute(flash_mma, cudaFuncAttributeMaxDynamicSharedMemorySize, FL_SMEM);
    flash_mma<<<dim3(SS/128, NH, BB), 256, FL_SMEM>>>(fqh, fql, fkh, fkl, fvh, af);

    gemm_mma1<<<dim3(NH*HD/BN, MROWS/BM), 256, GK1_SMEM>>>(af, oh, out, MROWS, NH*HD, NH*HD);
}